// round 10
// baseline (speedup 1.0000x reference)
#include <cuda_runtime.h>
#include <cuda_bf16.h>
#include <cstdint>

#define BSZ     4
#define D_MODEL 1024
#define QLEN    512
#define MLEN    512
#define KLEN    1024
#define NHEAD   16
#define DHEAD   64
#define DINNER  4096

typedef __nv_bfloat16 bf16;

// ---------------- fp32 scratch ----------------------------------------------
__device__ float g_wheads[BSZ * 3 * D_MODEL * KLEN];
__device__ float g_rk[D_MODEL * KLEN];
__device__ float g_tmp1[BSZ * D_MODEL * QLEN];
__device__ float g_x[BSZ * D_MODEL * QLEN];
__device__ float g_tmp2[2 * BSZ * D_MODEL * QLEN];   // two K-split halves for FF2

// ---------------- bf16-split (hi,hi,lo / hi,lo,hi) scratch -------------------
__device__ bf16 g_qkvw3[3 * D_MODEL * 3 * D_MODEL];
__device__ bf16 g_rw3  [D_MODEL * 3 * D_MODEL];
__device__ bf16 g_ow3  [D_MODEL * 3 * D_MODEL];
__device__ bf16 g_ff1w3[DINNER * 3 * D_MODEL];
__device__ bf16 g_ff2w3[D_MODEL * 3 * DINNER];
__device__ bf16 g_pos3 [3 * D_MODEL * KLEN];
__device__ bf16 g_cat3 [BSZ * 3 * D_MODEL * KLEN];
__device__ bf16 g_avec3[BSZ * 3 * D_MODEL * QLEN];
__device__ bf16 g_x3   [BSZ * 3 * D_MODEL * QLEN];
__device__ bf16 g_h3   [BSZ * 3 * DINNER * QLEN];

// ---------------- helpers ----------------------------------------------------
__device__ __forceinline__ void split_bf16(float x, bf16& hi, bf16& lo)
{
    hi = __float2bfloat16(x);
    lo = __float2bfloat16(x - __bfloat162float(hi));
}

__device__ __forceinline__ void cp_async16(uint32_t smem_dst, const void* gmem_src)
{
    asm volatile("cp.async.cg.shared.global [%0], [%1], 16;\n"
                 :: "r"(smem_dst), "l"(gmem_src));
}
__device__ __forceinline__ void cp_commit()
{
    asm volatile("cp.async.commit_group;\n");
}
__device__ __forceinline__ void cp_wait_all()
{
    asm volatile("cp.async.wait_group 0;\n");
}
__device__ __forceinline__ void ldsm_x4(uint32_t& r0, uint32_t& r1, uint32_t& r2, uint32_t& r3, uint32_t addr)
{
    asm volatile("ldmatrix.sync.aligned.m8n8.x4.shared.b16 {%0,%1,%2,%3}, [%4];\n"
                 : "=r"(r0), "=r"(r1), "=r"(r2), "=r"(r3) : "r"(addr));
}
__device__ __forceinline__ void ldsm_x4_t(uint32_t& r0, uint32_t& r1, uint32_t& r2, uint32_t& r3, uint32_t addr)
{
    asm volatile("ldmatrix.sync.aligned.m8n8.x4.trans.shared.b16 {%0,%1,%2,%3}, [%4];\n"
                 : "=r"(r0), "=r"(r1), "=r"(r2), "=r"(r3) : "r"(addr));
}
__device__ __forceinline__ void mma16816(float* c, const uint32_t* a, const uint32_t* b)
{
    asm volatile(
        "mma.sync.aligned.m16n8k16.row.col.f32.bf16.bf16.f32 "
        "{%0,%1,%2,%3}, {%4,%5,%6,%7}, {%8,%9}, {%0,%1,%2,%3};\n"
        : "+f"(c[0]), "+f"(c[1]), "+f"(c[2]), "+f"(c[3])
        : "r"(a[0]), "r"(a[1]), "r"(a[2]), "r"(a[3]), "r"(b[0]), "r"(b[1]));
}

// ---------------- expansion kernels ------------------------------------------
// One merged launch for all 5 weights: each CTA = 128 threads x 8 k = 1024-k chunk.
__global__ void expand_weights_kernel(const float* __restrict__ qkv_w,
                                      const float* __restrict__ r_w,
                                      const float* __restrict__ o_w,
                                      const float* __restrict__ ff1_w,
                                      const float* __restrict__ ff2_w,
                                      bf16* qkvw3, bf16* rw3, bf16* ow3,
                                      bf16* ff1w3, bf16* ff2w3)
{
    int cid = blockIdx.x;
    const float* in; bf16* out; int K; int row; int kc;
    if (cid < 3072)       { in = qkv_w; out = qkvw3; K = 1024; row = cid;        kc = 0; }
    else if (cid < 4096)  { in = r_w;   out = rw3;   K = 1024; row = cid - 3072; kc = 0; }
    else if (cid < 5120)  { in = o_w;   out = ow3;   K = 1024; row = cid - 4096; kc = 0; }
    else if (cid < 9216)  { in = ff1_w; out = ff1w3; K = 1024; row = cid - 5120; kc = 0; }
    else { int c = cid - 9216; in = ff2_w; out = ff2w3; K = 4096; row = c >> 2; kc = c & 3; }

    int k0 = (kc * 128 + threadIdx.x) * 8;
    const float4* ip = (const float4*)(in + (long)row * K + k0);
    float4 f0 = ip[0], f1 = ip[1];
    float v[8] = {f0.x, f0.y, f0.z, f0.w, f1.x, f1.y, f1.z, f1.w};
    unsigned short s[24];
#pragma unroll
    for (int j = 0; j < 8; j++) {
        bf16 hi, lo; split_bf16(v[j], hi, lo);
        unsigned short uh = __bfloat16_as_ushort(hi);
        unsigned short ul = __bfloat16_as_ushort(lo);
        s[3 * j] = uh; s[3 * j + 1] = uh; s[3 * j + 2] = ul;
    }
    uint32_t w[12];
#pragma unroll
    for (int i = 0; i < 12; i++)
        w[i] = (uint32_t)s[2 * i] | ((uint32_t)s[2 * i + 1] << 16);
    uint4* op = (uint4*)(out + (long)row * 3 * K + 3 * k0);
    op[0] = make_uint4(w[0], w[1], w[2], w[3]);
    op[1] = make_uint4(w[4], w[5], w[6], w[7]);
    op[2] = make_uint4(w[8], w[9], w[10], w[11]);
}

// B-pattern with column offset n0 (row stride ldn)
__global__ void expandB_kernel(const float* __restrict__ in, bf16* __restrict__ out,
                               int ldn, int n0, long sIn, long sOut)
{
    int n = n0 + blockIdx.x * 256 + threadIdx.x;
    int k = blockIdx.y;
    float x = in[(long)blockIdx.z * sIn + (long)k * ldn + n];
    bf16 hi, lo; split_bf16(x, hi, lo);
    bf16* o = out + (long)blockIdx.z * sOut + (long)(3 * k) * ldn + n;
    o[0] = hi; o[ldn] = lo; o[2 * ldn] = hi;
}

// cat expansion with time offset t0base (cols < 256 provably unused)
__global__ void expand_cat_kernel(const float* __restrict__ z0, const float* __restrict__ z1ss,
                                  int t0base)
{
    int t = t0base + blockIdx.x * 256 + threadIdx.x;
    int d = blockIdx.y;
    int b = blockIdx.z;
    float x = (t < MLEN) ? z0[((long)b * D_MODEL + d) * MLEN + t]
                         : z1ss[((long)b * D_MODEL + d) * QLEN + (t - MLEN)];
    bf16 hi, lo; split_bf16(x, hi, lo);
    bf16* o = g_cat3 + (long)b * 3 * D_MODEL * KLEN + (long)(3 * d) * KLEN + t;
    o[0] = hi; o[KLEN] = lo; o[2 * KLEN] = hi;
}

// ---------------- tensor-core GEMM (mma.sync), templated tiles ---------------
// GBM = 32*MI, GBN = 32*NJ (NJ = 4 -> 128, NJ = 8 -> 256), GBK = 64.
// K-split: blockIdx.z = (b << zshift) | ks; A offset ks*K (row stride ldk),
// B offset ks*K rows, C offset ks*strideCk; bias/addend applied on ks==0 only.
// mode: 0 = fp32 out, 1 = fp32 relu out, 2 = bf16-split([hi,lo,hi] rows) relu out
#define APADE 72

template<int MI, int NJ>
__global__ __launch_bounds__(256, (NJ == 4 ? 2 : 1))
void gemm_bf16_kernel(const bf16* __restrict__ A,
                      const bf16* __restrict__ B,
                      void*       __restrict__ Cv,
                      const float* __restrict__ bias,
                      const float* __restrict__ addend,
                      int K, int ldk, int ldn,
                      long strideB, long strideC, long strideAdd, long strideCk,
                      int zshift, int mode)
{
    constexpr int GBMt = 32 * MI;
    constexpr int GBN  = 32 * NJ;
    constexpr int BP   = GBN + 8;          // B smem row stride (elements)
    constexpr int BCH  = GBN / 8;          // 16B chunks per B row
    constexpr int BSH  = (NJ == 4 ? 4 : 5);

    extern __shared__ bf16 smem_g[];
    bf16* Asm = smem_g;
    bf16* Bsm = smem_g + 2 * GBMt * APADE;

    const int tid  = threadIdx.x;
    const int lane = tid & 31;
    const int warp = tid >> 5;
    const int wm = warp >> 2;
    const int wn = warp & 3;
    const int bn = blockIdx.x * GBN;
    const int bm = blockIdx.y * GBMt;
    const int b  = blockIdx.z >> zshift;
    const int ks = blockIdx.z & ((1 << zshift) - 1);

    const bf16* Ag = A + (long)bm * ldk + (long)ks * K;
    const bf16* Bg = B + (long)b * strideB + (long)ks * K * ldn;

    uint32_t sA = (uint32_t)__cvta_generic_to_shared(Asm);
    uint32_t sB = (uint32_t)__cvta_generic_to_shared(Bsm);
    const uint32_t sAsz = GBMt * APADE * 2;
    const uint32_t sBsz = 64 * BP * 2;

    float acc[MI][NJ][4];
#pragma unroll
    for (int i = 0; i < MI; i++)
#pragma unroll
        for (int j = 0; j < NJ; j++)
#pragma unroll
            for (int r = 0; r < 4; r++) acc[i][j][r] = 0.f;

    auto load_tiles = [&](int buf, int k0) {
#pragma unroll
        for (int i = 0; i < MI; i++) {               // A: GBMt rows x 8 chunks
            int c   = tid + 256 * i;
            int row = c >> 3, ch = c & 7;
            cp_async16(sA + buf * sAsz + (row * APADE + ch * 8) * 2,
                       Ag + (long)row * ldk + k0 + ch * 8);
        }
#pragma unroll
        for (int i = 0; i < (64 * BCH) / 256; i++) { // B: 64 rows x BCH chunks
            int c   = tid + 256 * i;
            int row = c >> BSH, ch = c & (BCH - 1);
            cp_async16(sB + buf * sBsz + (row * BP + ch * 8) * 2,
                       Bg + (long)(k0 + row) * ldn + bn + ch * 8);
        }
        cp_commit();
    };

    load_tiles(0, 0);

    const int nIter = K >> 6;
    for (int it = 0; it < nIter; it++) {
        int buf = it & 1;
        cp_wait_all();
        __syncthreads();
        if (it + 1 < nIter) load_tiles(buf ^ 1, (it + 1) * 64);

#pragma unroll
        for (int ks4 = 0; ks4 < 4; ks4++) {
            uint32_t afrag[MI][4];
            uint32_t bfrag[NJ][2];
            int lrow = lane & 15, lcol = (lane >> 4) * 8;
#pragma unroll
            for (int mi = 0; mi < MI; mi++) {
                uint32_t addr = sA + buf * sAsz +
                    ((MI * 16 * wm + 16 * mi + lrow) * APADE + ks4 * 16 + lcol) * 2;
                ldsm_x4(afrag[mi][0], afrag[mi][1], afrag[mi][2], afrag[mi][3], addr);
            }
#pragma unroll
            for (int nj2 = 0; nj2 < NJ / 2; nj2++) {
                uint32_t addr = sB + buf * sBsz +
                    ((ks4 * 16 + lrow) * BP + (8 * NJ) * wn + 16 * nj2 + lcol) * 2;
                uint32_t r0, r1, r2, r3;
                ldsm_x4_t(r0, r1, r2, r3, addr);
                bfrag[2 * nj2][0] = r0;     bfrag[2 * nj2][1] = r1;
                bfrag[2 * nj2 + 1][0] = r2; bfrag[2 * nj2 + 1][1] = r3;
            }
#pragma unroll
            for (int mi = 0; mi < MI; mi++)
#pragma unroll
                for (int nj = 0; nj < NJ; nj++)
                    mma16816(acc[mi][nj], afrag[mi], bfrag[nj]);
        }
        __syncthreads();
    }

    const float* Ad = (addend && ks == 0) ? (addend + (long)b * strideAdd) : nullptr;
    const float* bz = (ks == 0) ? bias : nullptr;
    int g = lane >> 2, tg = lane & 3;

    if (mode == 2) {
        bf16* C3 = (bf16*)Cv + (long)b * strideC;
#pragma unroll
        for (int mi = 0; mi < MI; mi++) {
            int row0 = bm + MI * 16 * wm + 16 * mi + g;
            int row1 = row0 + 8;
            float bv0 = bz ? bz[row0] : 0.f;
            float bv1 = bz ? bz[row1] : 0.f;
#pragma unroll
            for (int nj = 0; nj < NJ; nj++) {
                int col = bn + (8 * NJ) * wn + 8 * nj + 2 * tg;
#pragma unroll
                for (int half = 0; half < 2; half++) {
                    int row = half ? row1 : row0;
                    float bv = half ? bv1 : bv0;
                    float v0 = fmaxf(acc[mi][nj][2 * half]     + bv, 0.f);
                    float v1 = fmaxf(acc[mi][nj][2 * half + 1] + bv, 0.f);
                    bf16 h0, l0, h1, l1;
                    split_bf16(v0, h0, l0);
                    split_bf16(v1, h1, l1);
                    long base = (long)(3 * row) * ldn + col;
                    C3[base]               = h0; C3[base + 1]           = h1;
                    C3[base + ldn]         = l0; C3[base + ldn + 1]     = l1;
                    C3[base + 2 * ldn]     = h0; C3[base + 2 * ldn + 1] = h1;
                }
            }
        }
        return;
    }

    float* Cb = (float*)Cv + (long)b * strideC + (long)ks * strideCk;
#pragma unroll
    for (int mi = 0; mi < MI; mi++) {
        int row0 = bm + MI * 16 * wm + 16 * mi + g;
        int row1 = row0 + 8;
        float bv0 = bz ? bz[row0] : 0.f;
        float bv1 = bz ? bz[row1] : 0.f;
#pragma unroll
        for (int nj = 0; nj < NJ; nj++) {
            int col = bn + (8 * NJ) * wn + 8 * nj + 2 * tg;
            float v00 = acc[mi][nj][0] + bv0;
            float v01 = acc[mi][nj][1] + bv0;
            float v10 = acc[mi][nj][2] + bv1;
            float v11 = acc[mi][nj][3] + bv1;
            if (Ad) {
                v00 += Ad[(long)row0 * ldn + col];
                v01 += Ad[(long)row0 * ldn + col + 1];
                v10 += Ad[(long)row1 * ldn + col];
                v11 += Ad[(long)row1 * ldn + col + 1];
            }
            if (mode == 1) {
                v00 = fmaxf(v00, 0.f); v01 = fmaxf(v01, 0.f);
                v10 = fmaxf(v10, 0.f); v11 = fmaxf(v11, 0.f);
            }
            Cb[(long)row0 * ldn + col]     = v00;
            Cb[(long)row0 * ldn + col + 1] = v01;
            Cb[(long)row1 * ldn + col]     = v10;
            Cb[(long)row1 * ldn + col + 1] = v11;
        }
    }
}

// ---------------- tiled banded attention (float4 LDS, writes avec3) ----------
#define AT_SMEM ((64*68*2 + 64*258 + 64*260 + 4*64 + 64) * 4)

__global__ __launch_bounds__(256)
void attn_tiled_kernel(const float* __restrict__ wheads,
                       const float* __restrict__ rk,
                       const float* __restrict__ rwb,
                       const float* __restrict__ rrb,
                       bf16*        __restrict__ avec3)
{
    extern __shared__ float sm[];
    float* qw   = sm;                       // [qi][d]  stride 68
    float* qr   = qw  + 64 * 68;            // [qi][d]  stride 68
    float* BDs  = qr  + 64 * 68;            // [qi][t]  stride 258
    float* U    = BDs + 64 * 258;           // union region (64*260 floats)
    float* red  = U   + 64 * 260;
    float* sinv = red + 4 * 64;
    float* Rs = U;                          // [d][t]   stride 260 (phase 1)
    float* Ks = U;                          // [jj][d]  stride 68  (phase 2)
    float* Vs = U + 64 * 68;                // [jj][d]  stride 68
    float* Ps = U + 2 * 64 * 68;            // [qi][jj] stride 65

    const int i0 = blockIdx.x * 64;
    const int h  = blockIdx.y;
    const int b  = blockIdx.z;
    const int tid = threadIdx.x;

    const float* W  = wheads + (long)b * (3 * D_MODEL) * KLEN;
    const float* Qg = W + (long)(h * DHEAD) * KLEN;
    const float* Kg = W + (long)(D_MODEL + h * DHEAD) * KLEN;
    const float* Vg = W + (long)(2 * D_MODEL + h * DHEAD) * KLEN;

    for (int idx = tid; idx < 64 * 64; idx += 256) {
        int d = idx >> 6, q = idx & 63;
        float qv = Qg[(long)d * KLEN + MLEN + i0 + q];
        qw[q * 68 + d] = qv + rwb[h * DHEAD + d];
        qr[q * 68 + d] = qv + rrb[h * DHEAD + d];
    }
    for (int idx = tid; idx < 64 * 256; idx += 256) {
        int d = idx >> 8, t = idx & 255;
        Rs[d * 260 + t] = rk[(long)(h * DHEAD + d) * KLEN + 768 + t];
    }
    __syncthreads();

    // phase 1: BD table (thread (q, tg); 16-t register blocks, float4 Rs reads)
    {
        int q = tid & 63, tg = tid >> 6;
#pragma unroll
        for (int g4 = 0; g4 < 4; g4++) {
            int t0 = tg * 64 + g4 * 16;
            float acc[16];
#pragma unroll
            for (int u = 0; u < 16; u++) acc[u] = 0.f;
            for (int d = 0; d < 64; d++) {
                float qv = qr[q * 68 + d];
                const float4* rp = (const float4*)(Rs + d * 260 + t0);
#pragma unroll
                for (int u4 = 0; u4 < 4; u4++) {
                    float4 r4 = rp[u4];
                    acc[u4 * 4 + 0] = fmaf(qv, r4.x, acc[u4 * 4 + 0]);
                    acc[u4 * 4 + 1] = fmaf(qv, r4.y, acc[u4 * 4 + 1]);
                    acc[u4 * 4 + 2] = fmaf(qv, r4.z, acc[u4 * 4 + 2]);
                    acc[u4 * 4 + 3] = fmaf(qv, r4.w, acc[u4 * 4 + 3]);
                }
            }
#pragma unroll
            for (int u = 0; u < 16; u++)
                BDs[q * 258 + t0 + u] = acc[u];
        }
    }

    const int qi = tid & 63;
    const int jg = tid >> 6;
    float O[16];
#pragma unroll
    for (int u = 0; u < 16; u++) O[u] = 0.f;
    float sume = 0.f;

    for (int c = 0; c < 5; c++) {
        int jb = c * 64;
        __syncthreads();
        for (int idx = tid; idx < 64 * 64; idx += 256) {
            int d = idx >> 6, jj = idx & 63;
            int jglob = i0 + 257 + jb + jj;
            float kv = 0.f, vv = 0.f;
            if (jglob < KLEN) {
                kv = Kg[(long)d * KLEN + jglob];
                vv = Vg[(long)d * KLEN + jglob];
            }
            Ks[jj * 68 + d] = kv;
            Vs[jj * 68 + d] = vv;
        }
        __syncthreads();

        // QK scores: float4 over d; Ks reads are warp-uniform broadcasts
        {
            float acc[16];
#pragma unroll
            for (int u = 0; u < 16; u++) acc[u] = 0.f;
            for (int d4 = 0; d4 < 16; d4++) {
                float4 qv4 = *(const float4*)(qw + qi * 68 + d4 * 4);
#pragma unroll
                for (int u = 0; u < 16; u++) {
                    float4 k4 = *(const float4*)(Ks + (jg * 16 + u) * 68 + d4 * 4);
                    acc[u] = fmaf(qv4.x, k4.x, acc[u]);
                    acc[u] = fmaf(qv4.y, k4.y, acc[u]);
                    acc[u] = fmaf(qv4.z, k4.z, acc[u]);
                    acc[u] = fmaf(qv4.w, k4.w, acc[u]);
                }
            }
#pragma unroll
            for (int u = 0; u < 16; u++) {
                int jp = jb + jg * 16 + u;
                int t  = jp - qi;
                float pv = 0.f;
                if (t >= 0 && t < 256)
                    pv = __expf((acc[u] + BDs[qi * 258 + t]) * 0.125f);
                sume += pv;
                Ps[qi * 65 + jg * 16 + u] = pv;
            }
        }
        __syncthreads();

        // AV: float4 Vs reads (warp-uniform broadcasts)
#pragma unroll 4
        for (int jj = 0; jj < 64; jj++) {
            float pv = Ps[qi * 65 + jj];
            const float4* vp = (const float4*)(Vs + jj * 68 + jg * 16);
#pragma unroll
            for (int u4 = 0; u4 < 4; u4++) {
                float4 v4 = vp[u4];
                O[u4 * 4 + 0] = fmaf(pv, v4.x, O[u4 * 4 + 0]);
                O[u4 * 4 + 1] = fmaf(pv, v4.y, O[u4 * 4 + 1]);
                O[u4 * 4 + 2] = fmaf(pv, v4.z, O[u4 * 4 + 2]);
                O[u4 * 4 + 3] = fmaf(pv, v4.w, O[u4 * 4 + 3]);
            }
        }
    }

    red[jg * 64 + qi] = sume;
    __syncthreads();
    if (tid < 64)
        sinv[tid] = 1.f / (red[tid] + red[64 + tid] + red[128 + tid] + red[192 + tid]);
    __syncthreads();
    float inv = sinv[qi];
    bf16* outp = avec3 + (long)b * 3 * D_MODEL * QLEN;
#pragma unroll
    for (int u = 0; u < 16; u++) {
        int dp = h * DHEAD + jg * 16 + u;
        float v = O[u] * inv;
        bf16 hi, lo; split_bf16(v, hi, lo);
        long base = (long)(3 * dp) * QLEN + i0 + qi;
        outp[base]            = hi;
        outp[base + QLEN]     = lo;
        outp[base + 2 * QLEN] = hi;
    }
}

// ---------------- channel LayerNorm (optional 2nd input sum, fused split) ----
__global__ __launch_bounds__(256)
void ln_kernel(const float* __restrict__ ya, const float* __restrict__ yb,
               float* __restrict__ out, bf16* __restrict__ out3)
{
    int b  = blockIdx.y;
    int t0 = blockIdx.x * 32;
    int tid = threadIdx.x;
    int tt = tid & 31, cg = tid >> 5;
    const float* Ya = ya + (long)b * D_MODEL * QLEN;
    const float* Yb = yb ? (yb + (long)b * D_MODEL * QLEN) : nullptr;

    float s = 0.f, s2 = 0.f;
    for (int c = cg * 128; c < cg * 128 + 128; c++) {
        long idx = (long)c * QLEN + t0 + tt;
        float v = Ya[idx] + (Yb ? Yb[idx] : 0.f);
        s += v; s2 += v * v;
    }
    __shared__ float ssum[8][32], ssq[8][32];
    __shared__ float smean[32], srstd[32];
    ssum[cg][tt] = s; ssq[cg][tt] = s2;
    __syncthreads();
    if (tid < 32) {
        float ts = 0.f, ts2 = 0.f;
#pragma unroll
        for (int g = 0; g < 8; g++) { ts += ssum[g][tid]; ts2 += ssq[g][tid]; }
        float mean = ts * (1.0f / D_MODEL);
        float var  = ts2 * (1.0f / D_MODEL) - mean * mean;
        smean[tid] = mean;
        srstd[tid] = rsqrtf(var + 1e-5f);
    }
    __syncthreads();
    float mean = smean[tt], rstd = srstd[tt];
    float* O = out + (long)b * D_MODEL * QLEN;
    bf16* O3 = out3 ? (out3 + (long)b * 3 * D_MODEL * QLEN) : nullptr;
    for (int c = cg * 128; c < cg * 128 + 128; c++) {
        long idx = (long)c * QLEN + t0 + tt;
        float v = Ya[idx] + (Yb ? Yb[idx] : 0.f);
        float r = (v - mean) * rstd;
        O[idx] = r;
        if (O3) {
            bf16 hi, lo; split_bf16(r, hi, lo);
            long base = (long)(3 * c) * QLEN + t0 + tt;
            O3[base]            = hi;
            O3[base + QLEN]     = lo;
            O3[base + 2 * QLEN] = hi;
        }
    }
}

// ---------------- launcher ---------------------------------------------------
#define GSMEM48 ((2 * 128 * APADE + 2 * 64 * 264) * 2)    // 104448 (MI=4, NJ=8)
#define GSMEM24 ((2 * 64  * APADE + 2 * 64 * 136) * 2)    // 53248  (MI=2, NJ=4)

extern "C" void kernel_launch(void* const* d_in, const int* in_sizes, int n_in,
                              void* d_out, int out_size)
{
    const float* z1ss    = (const float*)d_in[0];
    const float* uss     = (const float*)d_in[1];
    const float* z0      = (const float*)d_in[2];
    const float* pos_emb = (const float*)d_in[3];
    const float* qkv_w   = (const float*)d_in[4];
    const float* r_w     = (const float*)d_in[5];
    const float* r_w_bias= (const float*)d_in[6];
    const float* r_r_bias= (const float*)d_in[7];
    const float* o_w     = (const float*)d_in[8];
    const float* o_b     = (const float*)d_in[9];
    const float* ff1_w   = (const float*)d_in[10];
    const float* ff1_b   = (const float*)d_in[11];
    const float* ff2_w   = (const float*)d_in[12];
    const float* ff2_b   = (const float*)d_in[13];
    float* out = (float*)d_out;

    float *wheads, *rk, *tmp1, *x, *tmp2;
    bf16 *qkvw3, *rw3, *ow3, *ff1w3, *ff2w3, *pos3, *cat3, *avec3, *x3, *h3;
    cudaGetSymbolAddress((void**)&wheads, g_wheads);
    cudaGetSymbolAddress((void**)&rk,     g_rk);
    cudaGetSymbolAddress((void**)&tmp1,   g_tmp1);
    cudaGetSymbolAddress((void**)&x,      g_x);
    cudaGetSymbolAddress((void**)&tmp2,   g_tmp2);
    cudaGetSymbolAddress((void**)&qkvw3,  g_qkvw3);
    cudaGetSymbolAddress((void**)&rw3,    g_rw3);
    cudaGetSymbolAddress((void**)&ow3,    g_ow3);
    cudaGetSymbolAddress((void**)&ff1w3,  g_ff1w3);
    cudaGetSymbolAddress((void**)&ff2w3,  g_ff2w3);
    cudaGetSymbolAddress((void**)&pos3,   g_pos3);
    cudaGetSymbolAddress((void**)&cat3,   g_cat3);
    cudaGetSymbolAddress((void**)&avec3,  g_avec3);
    cudaGetSymbolAddress((void**)&x3,     g_x3);
    cudaGetSymbolAddress((void**)&h3,     g_h3);

    cudaFuncSetAttribute(attn_tiled_kernel,
                         cudaFuncAttributeMaxDynamicSharedMemorySize, AT_SMEM);
    cudaFuncSetAttribute(gemm_bf16_kernel<4, 8>,
                         cudaFuncAttributeMaxDynamicSharedMemorySize, GSMEM48);
    cudaFuncSetAttribute(gemm_bf16_kernel<2, 4>,
                         cudaFuncAttributeMaxDynamicSharedMemorySize, GSMEM24);

    const long s3dk = (long)3 * D_MODEL * KLEN;
    const long s3dq = (long)3 * D_MODEL * QLEN;
    const long s3iq = (long)3 * DINNER * QLEN;
    const long sdq  = (long)D_MODEL * QLEN;

    // [0] all weight expansions in one launch
    expand_weights_kernel<<<13312, 128>>>(qkv_w, r_w, o_w, ff1_w, ff2_w,
                                          qkvw3, rw3, ow3, ff1w3, ff2w3);
    // [1] cat expansion (cols [256,1024) only)
    expand_cat_kernel<<<dim3(3, D_MODEL, BSZ), 256>>>(z0, z1ss, 256);
    // [2] pos expansion (cols [768,1024) only)
    expandB_kernel<<<dim3(1, D_MODEL, 1), 256>>>(pos_emb, pos3, KLEN, 768, 0, 0);

    // [3] r_head_k: cols [768,1024) only
    gemm_bf16_kernel<2, 4><<<dim3(2, 16, 1), 256, GSMEM24>>>(
        rw3, pos3 + 768, rk + 768, nullptr, nullptr,
        3 * D_MODEL, 3 * D_MODEL, KLEN, 0, 0, 0, 0, 0, 0);

    // [4] QKV over N-window [256,1024): 256-wide tiles -> 288 CTAs
    gemm_bf16_kernel<4, 8><<<dim3(3, 24, BSZ), 256, GSMEM48>>>(
        qkvw3, cat3 + 256, wheads + 256, nullptr, uss + 256,
        3 * D_MODEL, 3 * D_MODEL, KLEN, s3dk, s3dk, s3dk, 0, 0, 0);

    // [5] banded attention -> avec3 (bf16 split, fused)  [ncu capture target]
    attn_tiled_kernel<<<dim3(QLEN / 64, NHEAD, BSZ), 256, AT_SMEM>>>(
        wheads, rk, r_w_bias, r_r_bias, avec3);

    // [6] O-proj: 64x128 tiles -> 256 CTAs
    gemm_bf16_kernel<2, 4><<<dim3(4, 16, BSZ), 256, GSMEM24>>>(
        ow3, avec3, tmp1, o_b, z1ss,
        3 * D_MODEL, 3 * D_MODEL, QLEN, s3dq, sdq, sdq, 0, 0, 0);

    // [7] x = LN(tmp1), fused x3
    ln_kernel<<<dim3(QLEN / 32, BSZ), 256>>>(tmp1, nullptr, x, x3);

    // [8] FF1: 128x256 tiles -> 256 CTAs, fused bf16-split relu epilogue
    gemm_bf16_kernel<4, 8><<<dim3(2, 32, BSZ), 256, GSMEM48>>>(
        ff1w3, x3, h3, ff1_b, nullptr,
        3 * D_MODEL, 3 * D_MODEL, QLEN, s3dq, s3iq, 0, 0, 0, 2);

    // [9] FF2: K-split x2 in one launch (z = b*2 + ks), 128x256 tiles -> 128 CTAs
    gemm_bf16_kernel<4, 8><<<dim3(2, 8, 2 * BSZ), 256, GSMEM48>>>(
        ff2w3, h3, tmp2, ff2_b, x,
        3 * DINNER / 2, 3 * DINNER, QLEN, s3iq, sdq, sdq, (long)BSZ * sdq, 1, 0);

    // [10] out = LN(tmp2_half0 + tmp2_half1)
    ln_kernel<<<dim3(QLEN / 32, BSZ), 256>>>(tmp2, tmp2 + (long)BSZ * sdq, out, nullptr);
}

// round 11
// speedup vs baseline: 1.0297x; 1.0297x over previous
#include <cuda_runtime.h>
#include <cuda_bf16.h>
#include <cstdint>

#define BSZ     4
#define D_MODEL 1024
#define QLEN    512
#define MLEN    512
#define KLEN    1024
#define NHEAD   16
#define DHEAD   64
#define DINNER  4096

typedef __nv_bfloat16 bf16;

// ---------------- fp32 scratch ----------------------------------------------
__device__ float g_wheads[BSZ * 3 * D_MODEL * KLEN];
__device__ float g_rkp[4 * D_MODEL * KLEN];          // 4 K-split partial planes
__device__ float g_tmp1[BSZ * D_MODEL * QLEN];
__device__ float g_x[BSZ * D_MODEL * QLEN];
__device__ float g_tmp2[BSZ * D_MODEL * QLEN];

// ---------------- bf16-split (hi,hi,lo / hi,lo,hi) scratch -------------------
__device__ bf16 g_qkvw3[3 * D_MODEL * 3 * D_MODEL];
__device__ bf16 g_rw3  [D_MODEL * 3 * D_MODEL];
__device__ bf16 g_ow3  [D_MODEL * 3 * D_MODEL];
__device__ bf16 g_ff1w3[DINNER * 3 * D_MODEL];
__device__ bf16 g_ff2w3[D_MODEL * 3 * DINNER];
__device__ bf16 g_pos3 [3 * D_MODEL * KLEN];
__device__ bf16 g_cat3 [BSZ * 3 * D_MODEL * KLEN];
__device__ bf16 g_avec3[BSZ * 3 * D_MODEL * QLEN];
__device__ bf16 g_x3   [BSZ * 3 * D_MODEL * QLEN];
__device__ bf16 g_h3   [BSZ * 3 * DINNER * QLEN];

// ---------------- helpers ----------------------------------------------------
__device__ __forceinline__ void split_bf16(float x, bf16& hi, bf16& lo)
{
    hi = __float2bfloat16(x);
    lo = __float2bfloat16(x - __bfloat162float(hi));
}

__device__ __forceinline__ void cp_async16(uint32_t smem_dst, const void* gmem_src)
{
    asm volatile("cp.async.cg.shared.global [%0], [%1], 16;\n"
                 :: "r"(smem_dst), "l"(gmem_src));
}
__device__ __forceinline__ void cp_commit()
{
    asm volatile("cp.async.commit_group;\n");
}
__device__ __forceinline__ void cp_wait_all()
{
    asm volatile("cp.async.wait_group 0;\n");
}
__device__ __forceinline__ void ldsm_x4(uint32_t& r0, uint32_t& r1, uint32_t& r2, uint32_t& r3, uint32_t addr)
{
    asm volatile("ldmatrix.sync.aligned.m8n8.x4.shared.b16 {%0,%1,%2,%3}, [%4];\n"
                 : "=r"(r0), "=r"(r1), "=r"(r2), "=r"(r3) : "r"(addr));
}
__device__ __forceinline__ void ldsm_x4_t(uint32_t& r0, uint32_t& r1, uint32_t& r2, uint32_t& r3, uint32_t addr)
{
    asm volatile("ldmatrix.sync.aligned.m8n8.x4.trans.shared.b16 {%0,%1,%2,%3}, [%4];\n"
                 : "=r"(r0), "=r"(r1), "=r"(r2), "=r"(r3) : "r"(addr));
}
__device__ __forceinline__ void mma16816(float* c, const uint32_t* a, const uint32_t* b)
{
    asm volatile(
        "mma.sync.aligned.m16n8k16.row.col.f32.bf16.bf16.f32 "
        "{%0,%1,%2,%3}, {%4,%5,%6,%7}, {%8,%9}, {%0,%1,%2,%3};\n"
        : "+f"(c[0]), "+f"(c[1]), "+f"(c[2]), "+f"(c[3])
        : "r"(a[0]), "r"(a[1]), "r"(a[2]), "r"(a[3]), "r"(b[0]), "r"(b[1]));
}

// ---------------- expansion kernels ------------------------------------------
// One merged launch for all 5 weights: each CTA = 128 threads x 8 k = 1024-k chunk.
__global__ void expand_weights_kernel(const float* __restrict__ qkv_w,
                                      const float* __restrict__ r_w,
                                      const float* __restrict__ o_w,
                                      const float* __restrict__ ff1_w,
                                      const float* __restrict__ ff2_w,
                                      bf16* qkvw3, bf16* rw3, bf16* ow3,
                                      bf16* ff1w3, bf16* ff2w3)
{
    int cid = blockIdx.x;
    const float* in; bf16* out; int K; int row; int kc;
    if (cid < 3072)       { in = qkv_w; out = qkvw3; K = 1024; row = cid;        kc = 0; }
    else if (cid < 4096)  { in = r_w;   out = rw3;   K = 1024; row = cid - 3072; kc = 0; }
    else if (cid < 5120)  { in = o_w;   out = ow3;   K = 1024; row = cid - 4096; kc = 0; }
    else if (cid < 9216)  { in = ff1_w; out = ff1w3; K = 1024; row = cid - 5120; kc = 0; }
    else { int c = cid - 9216; in = ff2_w; out = ff2w3; K = 4096; row = c >> 2; kc = c & 3; }

    int k0 = (kc * 128 + threadIdx.x) * 8;
    const float4* ip = (const float4*)(in + (long)row * K + k0);
    float4 f0 = ip[0], f1 = ip[1];
    float v[8] = {f0.x, f0.y, f0.z, f0.w, f1.x, f1.y, f1.z, f1.w};
    unsigned short s[24];
#pragma unroll
    for (int j = 0; j < 8; j++) {
        bf16 hi, lo; split_bf16(v[j], hi, lo);
        unsigned short uh = __bfloat16_as_ushort(hi);
        unsigned short ul = __bfloat16_as_ushort(lo);
        s[3 * j] = uh; s[3 * j + 1] = uh; s[3 * j + 2] = ul;
    }
    uint32_t w[12];
#pragma unroll
    for (int i = 0; i < 12; i++)
        w[i] = (uint32_t)s[2 * i] | ((uint32_t)s[2 * i + 1] << 16);
    uint4* op = (uint4*)(out + (long)row * 3 * K + 3 * k0);
    op[0] = make_uint4(w[0], w[1], w[2], w[3]);
    op[1] = make_uint4(w[4], w[5], w[6], w[7]);
    op[2] = make_uint4(w[8], w[9], w[10], w[11]);
}

// B-pattern with column offset n0 (row stride ldn)
__global__ void expandB_kernel(const float* __restrict__ in, bf16* __restrict__ out,
                               int ldn, int n0, long sIn, long sOut)
{
    int n = n0 + blockIdx.x * 256 + threadIdx.x;
    int k = blockIdx.y;
    float x = in[(long)blockIdx.z * sIn + (long)k * ldn + n];
    bf16 hi, lo; split_bf16(x, hi, lo);
    bf16* o = out + (long)blockIdx.z * sOut + (long)(3 * k) * ldn + n;
    o[0] = hi; o[ldn] = lo; o[2 * ldn] = hi;
}

// cat expansion with time offset t0base (cols < 256 provably unused)
__global__ void expand_cat_kernel(const float* __restrict__ z0, const float* __restrict__ z1ss,
                                  int t0base)
{
    int t = t0base + blockIdx.x * 256 + threadIdx.x;
    int d = blockIdx.y;
    int b = blockIdx.z;
    float x = (t < MLEN) ? z0[((long)b * D_MODEL + d) * MLEN + t]
                         : z1ss[((long)b * D_MODEL + d) * QLEN + (t - MLEN)];
    bf16 hi, lo; split_bf16(x, hi, lo);
    bf16* o = g_cat3 + (long)b * 3 * D_MODEL * KLEN + (long)(3 * d) * KLEN + t;
    o[0] = hi; o[KLEN] = lo; o[2 * KLEN] = hi;
}

// ---------------- tensor-core GEMM (mma.sync), templated tiles ---------------
// GBM = 32*MI, GBN = 32*NJ. GBK = 64.
// K-split: blockIdx.z = (b << zshift) | ks; A offset ks*K (row stride ldk),
// B offset ks*K rows, C offset ks*strideCk; bias/addend applied on ks==0 only.
// mode: 0 = fp32 out, 1 = fp32 relu out, 2 = bf16-split([hi,lo,hi] rows) relu out
#define APADE 72

template<int MI, int NJ>
__global__ __launch_bounds__(256, 2)
void gemm_bf16_kernel(const bf16* __restrict__ A,
                      const bf16* __restrict__ B,
                      void*       __restrict__ Cv,
                      const float* __restrict__ bias,
                      const float* __restrict__ addend,
                      int K, int ldk, int ldn,
                      long strideB, long strideC, long strideAdd, long strideCk,
                      int zshift, int mode)
{
    constexpr int GBMt = 32 * MI;
    constexpr int GBN  = 32 * NJ;
    constexpr int BP   = GBN + 8;
    constexpr int BCH  = GBN / 8;
    constexpr int BSH  = (NJ == 4 ? 4 : 5);

    extern __shared__ bf16 smem_g[];
    bf16* Asm = smem_g;
    bf16* Bsm = smem_g + 2 * GBMt * APADE;

    const int tid  = threadIdx.x;
    const int lane = tid & 31;
    const int warp = tid >> 5;
    const int wm = warp >> 2;
    const int wn = warp & 3;
    const int bn = blockIdx.x * GBN;
    const int bm = blockIdx.y * GBMt;
    const int b  = blockIdx.z >> zshift;
    const int ks = blockIdx.z & ((1 << zshift) - 1);

    const bf16* Ag = A + (long)bm * ldk + (long)ks * K;
    const bf16* Bg = B + (long)b * strideB + (long)ks * K * ldn;

    uint32_t sA = (uint32_t)__cvta_generic_to_shared(Asm);
    uint32_t sB = (uint32_t)__cvta_generic_to_shared(Bsm);
    const uint32_t sAsz = GBMt * APADE * 2;
    const uint32_t sBsz = 64 * BP * 2;

    float acc[MI][NJ][4];
#pragma unroll
    for (int i = 0; i < MI; i++)
#pragma unroll
        for (int j = 0; j < NJ; j++)
#pragma unroll
            for (int r = 0; r < 4; r++) acc[i][j][r] = 0.f;

    auto load_tiles = [&](int buf, int k0) {
#pragma unroll
        for (int i = 0; i < MI; i++) {
            int c   = tid + 256 * i;
            int row = c >> 3, ch = c & 7;
            cp_async16(sA + buf * sAsz + (row * APADE + ch * 8) * 2,
                       Ag + (long)row * ldk + k0 + ch * 8);
        }
#pragma unroll
        for (int i = 0; i < (64 * BCH) / 256; i++) {
            int c   = tid + 256 * i;
            int row = c >> BSH, ch = c & (BCH - 1);
            cp_async16(sB + buf * sBsz + (row * BP + ch * 8) * 2,
                       Bg + (long)(k0 + row) * ldn + bn + ch * 8);
        }
        cp_commit();
    };

    load_tiles(0, 0);

    const int nIter = K >> 6;
    for (int it = 0; it < nIter; it++) {
        int buf = it & 1;
        cp_wait_all();
        __syncthreads();
        if (it + 1 < nIter) load_tiles(buf ^ 1, (it + 1) * 64);

#pragma unroll
        for (int ks4 = 0; ks4 < 4; ks4++) {
            uint32_t afrag[MI][4];
            uint32_t bfrag[NJ][2];
            int lrow = lane & 15, lcol = (lane >> 4) * 8;
#pragma unroll
            for (int mi = 0; mi < MI; mi++) {
                uint32_t addr = sA + buf * sAsz +
                    ((MI * 16 * wm + 16 * mi + lrow) * APADE + ks4 * 16 + lcol) * 2;
                ldsm_x4(afrag[mi][0], afrag[mi][1], afrag[mi][2], afrag[mi][3], addr);
            }
#pragma unroll
            for (int nj2 = 0; nj2 < NJ / 2; nj2++) {
                uint32_t addr = sB + buf * sBsz +
                    ((ks4 * 16 + lrow) * BP + (8 * NJ) * wn + 16 * nj2 + lcol) * 2;
                uint32_t r0, r1, r2, r3;
                ldsm_x4_t(r0, r1, r2, r3, addr);
                bfrag[2 * nj2][0] = r0;     bfrag[2 * nj2][1] = r1;
                bfrag[2 * nj2 + 1][0] = r2; bfrag[2 * nj2 + 1][1] = r3;
            }
#pragma unroll
            for (int mi = 0; mi < MI; mi++)
#pragma unroll
                for (int nj = 0; nj < NJ; nj++)
                    mma16816(acc[mi][nj], afrag[mi], bfrag[nj]);
        }
        __syncthreads();
    }

    const float* Ad = (addend && ks == 0) ? (addend + (long)b * strideAdd) : nullptr;
    const float* bz = (ks == 0) ? bias : nullptr;
    int g = lane >> 2, tg = lane & 3;

    if (mode == 2) {
        bf16* C3 = (bf16*)Cv + (long)b * strideC;
#pragma unroll
        for (int mi = 0; mi < MI; mi++) {
            int row0 = bm + MI * 16 * wm + 16 * mi + g;
            int row1 = row0 + 8;
            float bv0 = bz ? bz[row0] : 0.f;
            float bv1 = bz ? bz[row1] : 0.f;
#pragma unroll
            for (int nj = 0; nj < NJ; nj++) {
                int col = bn + (8 * NJ) * wn + 8 * nj + 2 * tg;
#pragma unroll
                for (int half = 0; half < 2; half++) {
                    int row = half ? row1 : row0;
                    float bv = half ? bv1 : bv0;
                    float v0 = fmaxf(acc[mi][nj][2 * half]     + bv, 0.f);
                    float v1 = fmaxf(acc[mi][nj][2 * half + 1] + bv, 0.f);
                    bf16 h0, l0, h1, l1;
                    split_bf16(v0, h0, l0);
                    split_bf16(v1, h1, l1);
                    long base = (long)(3 * row) * ldn + col;
                    C3[base]               = h0; C3[base + 1]           = h1;
                    C3[base + ldn]         = l0; C3[base + ldn + 1]     = l1;
                    C3[base + 2 * ldn]     = h0; C3[base + 2 * ldn + 1] = h1;
                }
            }
        }
        return;
    }

    float* Cb = (float*)Cv + (long)b * strideC + (long)ks * strideCk;
#pragma unroll
    for (int mi = 0; mi < MI; mi++) {
        int row0 = bm + MI * 16 * wm + 16 * mi + g;
        int row1 = row0 + 8;
        float bv0 = bz ? bz[row0] : 0.f;
        float bv1 = bz ? bz[row1] : 0.f;
#pragma unroll
        for (int nj = 0; nj < NJ; nj++) {
            int col = bn + (8 * NJ) * wn + 8 * nj + 2 * tg;
            float v00 = acc[mi][nj][0] + bv0;
            float v01 = acc[mi][nj][1] + bv0;
            float v10 = acc[mi][nj][2] + bv1;
            float v11 = acc[mi][nj][3] + bv1;
            if (Ad) {
                v00 += Ad[(long)row0 * ldn + col];
                v01 += Ad[(long)row0 * ldn + col + 1];
                v10 += Ad[(long)row1 * ldn + col];
                v11 += Ad[(long)row1 * ldn + col + 1];
            }
            if (mode == 1) {
                v00 = fmaxf(v00, 0.f); v01 = fmaxf(v01, 0.f);
                v10 = fmaxf(v10, 0.f); v11 = fmaxf(v11, 0.f);
            }
            Cb[(long)row0 * ldn + col]     = v00;
            Cb[(long)row0 * ldn + col + 1] = v01;
            Cb[(long)row1 * ldn + col]     = v10;
            Cb[(long)row1 * ldn + col + 1] = v11;
        }
    }
}

// ---------------- tiled banded attention (float4 LDS, writes avec3) ----------
#define AT_SMEM ((64*68*2 + 64*258 + 64*260 + 4*64 + 64) * 4)

__global__ __launch_bounds__(256)
void attn_tiled_kernel(const float* __restrict__ wheads,
                       const float* __restrict__ rkp,
                       const float* __restrict__ rwb,
                       const float* __restrict__ rrb,
                       bf16*        __restrict__ avec3)
{
    extern __shared__ float sm[];
    float* qw   = sm;                       // [qi][d]  stride 68
    float* qr   = qw  + 64 * 68;            // [qi][d]  stride 68
    float* BDs  = qr  + 64 * 68;            // [qi][t]  stride 258
    float* U    = BDs + 64 * 258;           // union region (64*260 floats)
    float* red  = U   + 64 * 260;
    float* sinv = red + 4 * 64;
    float* Rs = U;                          // [d][t]   stride 260 (phase 1)
    float* Ks = U;                          // [jj][d]  stride 68  (phase 2)
    float* Vs = U + 64 * 68;                // [jj][d]  stride 68
    float* Ps = U + 2 * 64 * 68;            // [qi][jj] stride 65

    const int i0 = blockIdx.x * 64;
    const int h  = blockIdx.y;
    const int b  = blockIdx.z;
    const int tid = threadIdx.x;

    const float* W  = wheads + (long)b * (3 * D_MODEL) * KLEN;
    const float* Qg = W + (long)(h * DHEAD) * KLEN;
    const float* Kg = W + (long)(D_MODEL + h * DHEAD) * KLEN;
    const float* Vg = W + (long)(2 * D_MODEL + h * DHEAD) * KLEN;

    for (int idx = tid; idx < 64 * 64; idx += 256) {
        int d = idx >> 6, q = idx & 63;
        float qv = Qg[(long)d * KLEN + MLEN + i0 + q];
        qw[q * 68 + d] = qv + rwb[h * DHEAD + d];
        qr[q * 68 + d] = qv + rrb[h * DHEAD + d];
    }
    // Rs = sum of 4 K-split partial planes of r_head_k (cols 768..1023)
    {
        const long DK = (long)D_MODEL * KLEN;
        for (int idx = tid; idx < 64 * 256; idx += 256) {
            int d = idx >> 8, t = idx & 255;
            long base = (long)(h * DHEAD + d) * KLEN + 768 + t;
            Rs[d * 260 + t] = rkp[base] + rkp[DK + base]
                            + rkp[2 * DK + base] + rkp[3 * DK + base];
        }
    }
    __syncthreads();

    // phase 1: BD table (thread (q, tg); 16-t register blocks, float4 Rs reads)
    {
        int q = tid & 63, tg = tid >> 6;
#pragma unroll
        for (int g4 = 0; g4 < 4; g4++) {
            int t0 = tg * 64 + g4 * 16;
            float acc[16];
#pragma unroll
            for (int u = 0; u < 16; u++) acc[u] = 0.f;
            for (int d = 0; d < 64; d++) {
                float qv = qr[q * 68 + d];
                const float4* rp = (const float4*)(Rs + d * 260 + t0);
#pragma unroll
                for (int u4 = 0; u4 < 4; u4++) {
                    float4 r4 = rp[u4];
                    acc[u4 * 4 + 0] = fmaf(qv, r4.x, acc[u4 * 4 + 0]);
                    acc[u4 * 4 + 1] = fmaf(qv, r4.y, acc[u4 * 4 + 1]);
                    acc[u4 * 4 + 2] = fmaf(qv, r4.z, acc[u4 * 4 + 2]);
                    acc[u4 * 4 + 3] = fmaf(qv, r4.w, acc[u4 * 4 + 3]);
                }
            }
#pragma unroll
            for (int u = 0; u < 16; u++)
                BDs[q * 258 + t0 + u] = acc[u];
        }
    }

    const int qi = tid & 63;
    const int jg = tid >> 6;
    float O[16];
#pragma unroll
    for (int u = 0; u < 16; u++) O[u] = 0.f;
    float sume = 0.f;

    for (int c = 0; c < 5; c++) {
        int jb = c * 64;
        __syncthreads();
        for (int idx = tid; idx < 64 * 64; idx += 256) {
            int d = idx >> 6, jj = idx & 63;
            int jglob = i0 + 257 + jb + jj;
            float kv = 0.f, vv = 0.f;
            if (jglob < KLEN) {
                kv = Kg[(long)d * KLEN + jglob];
                vv = Vg[(long)d * KLEN + jglob];
            }
            Ks[jj * 68 + d] = kv;
            Vs[jj * 68 + d] = vv;
        }
        __syncthreads();

        // QK scores: float4 over d; Ks reads are warp-uniform broadcasts
        {
            float acc[16];
#pragma unroll
            for (int u = 0; u < 16; u++) acc[u] = 0.f;
            for (int d4 = 0; d4 < 16; d4++) {
                float4 qv4 = *(const float4*)(qw + qi * 68 + d4 * 4);
#pragma unroll
                for (int u = 0; u < 16; u++) {
                    float4 k4 = *(const float4*)(Ks + (jg * 16 + u) * 68 + d4 * 4);
                    acc[u] = fmaf(qv4.x, k4.x, acc[u]);
                    acc[u] = fmaf(qv4.y, k4.y, acc[u]);
                    acc[u] = fmaf(qv4.z, k4.z, acc[u]);
                    acc[u] = fmaf(qv4.w, k4.w, acc[u]);
                }
            }
#pragma unroll
            for (int u = 0; u < 16; u++) {
                int jp = jb + jg * 16 + u;
                int t  = jp - qi;
                float pv = 0.f;
                if (t >= 0 && t < 256)
                    pv = __expf((acc[u] + BDs[qi * 258 + t]) * 0.125f);
                sume += pv;
                Ps[qi * 65 + jg * 16 + u] = pv;
            }
        }
        __syncthreads();

        // AV: float4 Vs reads (warp-uniform broadcasts)
#pragma unroll 4
        for (int jj = 0; jj < 64; jj++) {
            float pv = Ps[qi * 65 + jj];
            const float4* vp = (const float4*)(Vs + jj * 68 + jg * 16);
#pragma unroll
            for (int u4 = 0; u4 < 4; u4++) {
                float4 v4 = vp[u4];
                O[u4 * 4 + 0] = fmaf(pv, v4.x, O[u4 * 4 + 0]);
                O[u4 * 4 + 1] = fmaf(pv, v4.y, O[u4 * 4 + 1]);
                O[u4 * 4 + 2] = fmaf(pv, v4.z, O[u4 * 4 + 2]);
                O[u4 * 4 + 3] = fmaf(pv, v4.w, O[u4 * 4 + 3]);
            }
        }
    }

    red[jg * 64 + qi] = sume;
    __syncthreads();
    if (tid < 64)
        sinv[tid] = 1.f / (red[tid] + red[64 + tid] + red[128 + tid] + red[192 + tid]);
    __syncthreads();
    float inv = sinv[qi];
    bf16* outp = avec3 + (long)b * 3 * D_MODEL * QLEN;
#pragma unroll
    for (int u = 0; u < 16; u++) {
        int dp = h * DHEAD + jg * 16 + u;
        float v = O[u] * inv;
        bf16 hi, lo; split_bf16(v, hi, lo);
        long base = (long)(3 * dp) * QLEN + i0 + qi;
        outp[base]            = hi;
        outp[base + QLEN]     = lo;
        outp[base + 2 * QLEN] = hi;
    }
}

// ---------------- channel LayerNorm (optional 2nd input sum, fused split) ----
__global__ __launch_bounds__(256)
void ln_kernel(const float* __restrict__ ya, const float* __restrict__ yb,
               float* __restrict__ out, bf16* __restrict__ out3)
{
    int b  = blockIdx.y;
    int t0 = blockIdx.x * 32;
    int tid = threadIdx.x;
    int tt = tid & 31, cg = tid >> 5;
    const float* Ya = ya + (long)b * D_MODEL * QLEN;
    const float* Yb = yb ? (yb + (long)b * D_MODEL * QLEN) : nullptr;

    float s = 0.f, s2 = 0.f;
    for (int c = cg * 128; c < cg * 128 + 128; c++) {
        long idx = (long)c * QLEN + t0 + tt;
        float v = Ya[idx] + (Yb ? Yb[idx] : 0.f);
        s += v; s2 += v * v;
    }
    __shared__ float ssum[8][32], ssq[8][32];
    __shared__ float smean[32], srstd[32];
    ssum[cg][tt] = s; ssq[cg][tt] = s2;
    __syncthreads();
    if (tid < 32) {
        float ts = 0.f, ts2 = 0.f;
#pragma unroll
        for (int g = 0; g < 8; g++) { ts += ssum[g][tid]; ts2 += ssq[g][tid]; }
        float mean = ts * (1.0f / D_MODEL);
        float var  = ts2 * (1.0f / D_MODEL) - mean * mean;
        smean[tid] = mean;
        srstd[tid] = rsqrtf(var + 1e-5f);
    }
    __syncthreads();
    float mean = smean[tt], rstd = srstd[tt];
    float* O = out + (long)b * D_MODEL * QLEN;
    bf16* O3 = out3 ? (out3 + (long)b * 3 * D_MODEL * QLEN) : nullptr;
    for (int c = cg * 128; c < cg * 128 + 128; c++) {
        long idx = (long)c * QLEN + t0 + tt;
        float v = Ya[idx] + (Yb ? Yb[idx] : 0.f);
        float r = (v - mean) * rstd;
        O[idx] = r;
        if (O3) {
            bf16 hi, lo; split_bf16(r, hi, lo);
            long base = (long)(3 * c) * QLEN + t0 + tt;
            O3[base]            = hi;
            O3[base + QLEN]     = lo;
            O3[base + 2 * QLEN] = hi;
        }
    }
}

// ---------------- launcher ---------------------------------------------------
#define GSMEM44 ((2 * 128 * APADE + 2 * 64 * 136) * 2)    // 71680 (MI=4, NJ=4)
#define GSMEM24 ((2 * 64  * APADE + 2 * 64 * 136) * 2)    // 53248 (MI=2, NJ=4)

extern "C" void kernel_launch(void* const* d_in, const int* in_sizes, int n_in,
                              void* d_out, int out_size)
{
    const float* z1ss    = (const float*)d_in[0];
    const float* uss     = (const float*)d_in[1];
    const float* z0      = (const float*)d_in[2];
    const float* pos_emb = (const float*)d_in[3];
    const float* qkv_w   = (const float*)d_in[4];
    const float* r_w     = (const float*)d_in[5];
    const float* r_w_bias= (const float*)d_in[6];
    const float* r_r_bias= (const float*)d_in[7];
    const float* o_w     = (const float*)d_in[8];
    const float* o_b     = (const float*)d_in[9];
    const float* ff1_w   = (const float*)d_in[10];
    const float* ff1_b   = (const float*)d_in[11];
    const float* ff2_w   = (const float*)d_in[12];
    const float* ff2_b   = (const float*)d_in[13];
    float* out = (float*)d_out;

    float *wheads, *rkp, *tmp1, *x, *tmp2;
    bf16 *qkvw3, *rw3, *ow3, *ff1w3, *ff2w3, *pos3, *cat3, *avec3, *x3, *h3;
    cudaGetSymbolAddress((void**)&wheads, g_wheads);
    cudaGetSymbolAddress((void**)&rkp,    g_rkp);
    cudaGetSymbolAddress((void**)&tmp1,   g_tmp1);
    cudaGetSymbolAddress((void**)&x,      g_x);
    cudaGetSymbolAddress((void**)&tmp2,   g_tmp2);
    cudaGetSymbolAddress((void**)&qkvw3,  g_qkvw3);
    cudaGetSymbolAddress((void**)&rw3,    g_rw3);
    cudaGetSymbolAddress((void**)&ow3,    g_ow3);
    cudaGetSymbolAddress((void**)&ff1w3,  g_ff1w3);
    cudaGetSymbolAddress((void**)&ff2w3,  g_ff2w3);
    cudaGetSymbolAddress((void**)&pos3,   g_pos3);
    cudaGetSymbolAddress((void**)&cat3,   g_cat3);
    cudaGetSymbolAddress((void**)&avec3,  g_avec3);
    cudaGetSymbolAddress((void**)&x3,     g_x3);
    cudaGetSymbolAddress((void**)&h3,     g_h3);

    cudaFuncSetAttribute(attn_tiled_kernel,
                         cudaFuncAttributeMaxDynamicSharedMemorySize, AT_SMEM);
    cudaFuncSetAttribute(gemm_bf16_kernel<4, 4>,
                         cudaFuncAttributeMaxDynamicSharedMemorySize, GSMEM44);
    cudaFuncSetAttribute(gemm_bf16_kernel<2, 4>,
                         cudaFuncAttributeMaxDynamicSharedMemorySize, GSMEM24);

    const long s3dk = (long)3 * D_MODEL * KLEN;
    const long s3dq = (long)3 * D_MODEL * QLEN;
    const long s3iq = (long)3 * DINNER * QLEN;
    const long sdq  = (long)D_MODEL * QLEN;
    const long sDK  = (long)D_MODEL * KLEN;

    // [1] all weight expansions in one launch
    expand_weights_kernel<<<13312, 128>>>(qkv_w, r_w, o_w, ff1_w, ff2_w,
                                          qkvw3, rw3, ow3, ff1w3, ff2w3);
    // [2] cat expansion (cols [256,1024) only)
    expand_cat_kernel<<<dim3(3, D_MODEL, BSZ), 256>>>(z0, z1ss, 256);
    // [3] pos expansion (cols [768,1024) only)
    expandB_kernel<<<dim3(1, D_MODEL, 1), 256>>>(pos_emb, pos3, KLEN, 768, 0, 0);

    // [4] QKV over N-window [256,1024): 128x128 tiles -> 576 CTAs  [ncu target]
    gemm_bf16_kernel<4, 4><<<dim3(6, 24, BSZ), 256, GSMEM44>>>(
        qkvw3, cat3 + 256, wheads + 256, nullptr, uss + 256,
        3 * D_MODEL, 3 * D_MODEL, KLEN, s3dk, s3dk, s3dk, 0, 0, 0);

    // [5] r_head_k (cols [768,1024)): K-split x4 -> 128 CTAs, 4 partial planes
    gemm_bf16_kernel<2, 4><<<dim3(2, 16, 4), 256, GSMEM24>>>(
        rw3, pos3 + 768, rkp + 768, nullptr, nullptr,
        3 * D_MODEL / 4, 3 * D_MODEL, KLEN, 0, 0, 0, sDK, 2, 0);

    // [6] banded attention (sums rk partials inline) -> avec3
    attn_tiled_kernel<<<dim3(QLEN / 64, NHEAD, BSZ), 256, AT_SMEM>>>(
        wheads, rkp, r_w_bias, r_r_bias, avec3);

    // [7] O-proj: 64x128 tiles -> 256 CTAs
    gemm_bf16_kernel<2, 4><<<dim3(4, 16, BSZ), 256, GSMEM24>>>(
        ow3, avec3, tmp1, o_b, z1ss,
        3 * D_MODEL, 3 * D_MODEL, QLEN, s3dq, sdq, sdq, 0, 0, 0);

    // [8] x = LN(tmp1), fused x3
    ln_kernel<<<dim3(QLEN / 32, BSZ), 256>>>(tmp1, nullptr, x, x3);

    // [9] FF1: 128x128 tiles -> 512 CTAs, fused bf16-split relu epilogue
    gemm_bf16_kernel<4, 4><<<dim3(4, 32, BSZ), 256, GSMEM44>>>(
        ff1w3, x3, h3, ff1_b, nullptr,
        3 * D_MODEL, 3 * D_MODEL, QLEN, s3dq, s3iq, 0, 0, 0, 2);

    // [10] FF2: 64x128 tiles -> 256 CTAs
    gemm_bf16_kernel<2, 4><<<dim3(4, 16, BSZ), 256, GSMEM24>>>(
        ff2w3, h3, tmp2, ff2_b, x,
        3 * DINNER, 3 * DINNER, QLEN, s3iq, sdq, sdq, 0, 0, 0);

    // [11] out = LN(tmp2)
    ln_kernel<<<dim3(QLEN / 32, BSZ), 256>>>(tmp2, nullptr, out, nullptr);
}

// round 12
// speedup vs baseline: 1.1073x; 1.0754x over previous
#include <cuda_runtime.h>
#include <cuda_bf16.h>
#include <cstdint>

#define BSZ     4
#define D_MODEL 1024
#define QLEN    512
#define MLEN    512
#define KLEN    1024
#define NHEAD   16
#define DHEAD   64
#define DINNER  4096

typedef __nv_bfloat16 bf16;

// ---------------- fp32 scratch ----------------------------------------------
__device__ float g_wheads[BSZ * 3 * D_MODEL * KLEN];
__device__ float g_rkp[4 * D_MODEL * KLEN];          // 4 K-split partial planes
__device__ float g_tmp1[BSZ * D_MODEL * QLEN];
__device__ float g_x[BSZ * D_MODEL * QLEN];
__device__ float g_tmp2[2 * BSZ * D_MODEL * QLEN];   // two K-split halves for FF2

// ---------------- bf16-split (hi,hi,lo / hi,lo,hi) scratch -------------------
__device__ bf16 g_qkvw3[3 * D_MODEL * 3 * D_MODEL];
__device__ bf16 g_rw3  [D_MODEL * 3 * D_MODEL];
__device__ bf16 g_ow3  [D_MODEL * 3 * D_MODEL];
__device__ bf16 g_ff1w3[DINNER * 3 * D_MODEL];
__device__ bf16 g_ff2w3[D_MODEL * 3 * DINNER];
__device__ bf16 g_pos3 [3 * D_MODEL * KLEN];
__device__ bf16 g_cat3 [BSZ * 3 * D_MODEL * KLEN];
__device__ bf16 g_avec3[BSZ * 3 * D_MODEL * QLEN];
__device__ bf16 g_x3   [BSZ * 3 * D_MODEL * QLEN];
__device__ bf16 g_h3   [BSZ * 3 * DINNER * QLEN];

// ---------------- helpers ----------------------------------------------------
__device__ __forceinline__ void split_bf16(float x, bf16& hi, bf16& lo)
{
    hi = __float2bfloat16(x);
    lo = __float2bfloat16(x - __bfloat162float(hi));
}

__device__ __forceinline__ void cp_async16(uint32_t smem_dst, const void* gmem_src)
{
    asm volatile("cp.async.cg.shared.global [%0], [%1], 16;\n"
                 :: "r"(smem_dst), "l"(gmem_src));
}
__device__ __forceinline__ void cp_commit()
{
    asm volatile("cp.async.commit_group;\n");
}
__device__ __forceinline__ void cp_wait_all()
{
    asm volatile("cp.async.wait_group 0;\n");
}
__device__ __forceinline__ void ldsm_x4(uint32_t& r0, uint32_t& r1, uint32_t& r2, uint32_t& r3, uint32_t addr)
{
    asm volatile("ldmatrix.sync.aligned.m8n8.x4.shared.b16 {%0,%1,%2,%3}, [%4];\n"
                 : "=r"(r0), "=r"(r1), "=r"(r2), "=r"(r3) : "r"(addr));
}
__device__ __forceinline__ void ldsm_x4_t(uint32_t& r0, uint32_t& r1, uint32_t& r2, uint32_t& r3, uint32_t addr)
{
    asm volatile("ldmatrix.sync.aligned.m8n8.x4.trans.shared.b16 {%0,%1,%2,%3}, [%4];\n"
                 : "=r"(r0), "=r"(r1), "=r"(r2), "=r"(r3) : "r"(addr));
}
__device__ __forceinline__ void mma16816(float* c, const uint32_t* a, const uint32_t* b)
{
    asm volatile(
        "mma.sync.aligned.m16n8k16.row.col.f32.bf16.bf16.f32 "
        "{%0,%1,%2,%3}, {%4,%5,%6,%7}, {%8,%9}, {%0,%1,%2,%3};\n"
        : "+f"(c[0]), "+f"(c[1]), "+f"(c[2]), "+f"(c[3])
        : "r"(a[0]), "r"(a[1]), "r"(a[2]), "r"(a[3]), "r"(b[0]), "r"(b[1]));
}

// ---------------- expansion kernels ------------------------------------------
__global__ void expand_weights_kernel(const float* __restrict__ qkv_w,
                                      const float* __restrict__ r_w,
                                      const float* __restrict__ o_w,
                                      const float* __restrict__ ff1_w,
                                      const float* __restrict__ ff2_w,
                                      bf16* qkvw3, bf16* rw3, bf16* ow3,
                                      bf16* ff1w3, bf16* ff2w3)
{
    int cid = blockIdx.x;
    const float* in; bf16* out; int K; int row; int kc;
    if (cid < 3072)       { in = qkv_w; out = qkvw3; K = 1024; row = cid;        kc = 0; }
    else if (cid < 4096)  { in = r_w;   out = rw3;   K = 1024; row = cid - 3072; kc = 0; }
    else if (cid < 5120)  { in = o_w;   out = ow3;   K = 1024; row = cid - 4096; kc = 0; }
    else if (cid < 9216)  { in = ff1_w; out = ff1w3; K = 1024; row = cid - 5120; kc = 0; }
    else { int c = cid - 9216; in = ff2_w; out = ff2w3; K = 4096; row = c >> 2; kc = c & 3; }

    int k0 = (kc * 128 + threadIdx.x) * 8;
    const float4* ip = (const float4*)(in + (long)row * K + k0);
    float4 f0 = ip[0], f1 = ip[1];
    float v[8] = {f0.x, f0.y, f0.z, f0.w, f1.x, f1.y, f1.z, f1.w};
    unsigned short s[24];
#pragma unroll
    for (int j = 0; j < 8; j++) {
        bf16 hi, lo; split_bf16(v[j], hi, lo);
        unsigned short uh = __bfloat16_as_ushort(hi);
        unsigned short ul = __bfloat16_as_ushort(lo);
        s[3 * j] = uh; s[3 * j + 1] = uh; s[3 * j + 2] = ul;
    }
    uint32_t w[12];
#pragma unroll
    for (int i = 0; i < 12; i++)
        w[i] = (uint32_t)s[2 * i] | ((uint32_t)s[2 * i + 1] << 16);
    uint4* op = (uint4*)(out + (long)row * 3 * K + 3 * k0);
    op[0] = make_uint4(w[0], w[1], w[2], w[3]);
    op[1] = make_uint4(w[4], w[5], w[6], w[7]);
    op[2] = make_uint4(w[8], w[9], w[10], w[11]);
}

__global__ void expandB_kernel(const float* __restrict__ in, bf16* __restrict__ out,
                               int ldn, int n0, long sIn, long sOut)
{
    int n = n0 + blockIdx.x * 256 + threadIdx.x;
    int k = blockIdx.y;
    float x = in[(long)blockIdx.z * sIn + (long)k * ldn + n];
    bf16 hi, lo; split_bf16(x, hi, lo);
    bf16* o = out + (long)blockIdx.z * sOut + (long)(3 * k) * ldn + n;
    o[0] = hi; o[ldn] = lo; o[2 * ldn] = hi;
}

__global__ void expand_cat_kernel(const float* __restrict__ z0, const float* __restrict__ z1ss,
                                  int t0base)
{
    int t = t0base + blockIdx.x * 256 + threadIdx.x;
    int d = blockIdx.y;
    int b = blockIdx.z;
    float x = (t < MLEN) ? z0[((long)b * D_MODEL + d) * MLEN + t]
                         : z1ss[((long)b * D_MODEL + d) * QLEN + (t - MLEN)];
    bf16 hi, lo; split_bf16(x, hi, lo);
    bf16* o = g_cat3 + (long)b * 3 * D_MODEL * KLEN + (long)(3 * d) * KLEN + t;
    o[0] = hi; o[KLEN] = lo; o[2 * KLEN] = hi;
}

// reduce 4 rkp partial planes into plane 0 (cols [768,1024) of each row only)
__global__ void reduce_rk_kernel(float* __restrict__ rkp)
{
    const long DK = (long)D_MODEL * KLEN;
    int idx = blockIdx.x * 256 + threadIdx.x;     // 65536 threads
    int row = idx >> 6;
    int t4  = (idx & 63) * 4;
    long base = (long)row * KLEN + 768 + t4;
    float4 a = *(const float4*)(rkp + base);
    float4 b = *(const float4*)(rkp + DK + base);
    float4 c = *(const float4*)(rkp + 2 * DK + base);
    float4 d = *(const float4*)(rkp + 3 * DK + base);
    a.x += b.x + c.x + d.x;
    a.y += b.y + c.y + d.y;
    a.z += b.z + c.z + d.z;
    a.w += b.w + c.w + d.w;
    *(float4*)(rkp + base) = a;
}

// ---------------- tensor-core GEMM (mma.sync), templated tiles ---------------
#define APADE 72

template<int MI, int NJ>
__global__ __launch_bounds__(256, 2)
void gemm_bf16_kernel(const bf16* __restrict__ A,
                      const bf16* __restrict__ B,
                      void*       __restrict__ Cv,
                      const float* __restrict__ bias,
                      const float* __restrict__ addend,
                      int K, int ldk, int ldn,
                      long strideB, long strideC, long strideAdd, long strideCk,
                      int zshift, int mode)
{
    constexpr int GBMt = 32 * MI;
    constexpr int GBN  = 32 * NJ;
    constexpr int BP   = GBN + 8;
    constexpr int BCH  = GBN / 8;
    constexpr int BSH  = (NJ == 4 ? 4 : 5);

    extern __shared__ bf16 smem_g[];
    bf16* Asm = smem_g;
    bf16* Bsm = smem_g + 2 * GBMt * APADE;

    const int tid  = threadIdx.x;
    const int lane = tid & 31;
    const int warp = tid >> 5;
    const int wm = warp >> 2;
    const int wn = warp & 3;
    const int bn = blockIdx.x * GBN;
    const int bm = blockIdx.y * GBMt;
    const int b  = blockIdx.z >> zshift;
    const int ks = blockIdx.z & ((1 << zshift) - 1);

    const bf16* Ag = A + (long)bm * ldk + (long)ks * K;
    const bf16* Bg = B + (long)b * strideB + (long)ks * K * ldn;

    uint32_t sA = (uint32_t)__cvta_generic_to_shared(Asm);
    uint32_t sB = (uint32_t)__cvta_generic_to_shared(Bsm);
    const uint32_t sAsz = GBMt * APADE * 2;
    const uint32_t sBsz = 64 * BP * 2;

    float acc[MI][NJ][4];
#pragma unroll
    for (int i = 0; i < MI; i++)
#pragma unroll
        for (int j = 0; j < NJ; j++)
#pragma unroll
            for (int r = 0; r < 4; r++) acc[i][j][r] = 0.f;

    auto load_tiles = [&](int buf, int k0) {
#pragma unroll
        for (int i = 0; i < MI; i++) {
            int c   = tid + 256 * i;
            int row = c >> 3, ch = c & 7;
            cp_async16(sA + buf * sAsz + (row * APADE + ch * 8) * 2,
                       Ag + (long)row * ldk + k0 + ch * 8);
        }
#pragma unroll
        for (int i = 0; i < (64 * BCH) / 256; i++) {
            int c   = tid + 256 * i;
            int row = c >> BSH, ch = c & (BCH - 1);
            cp_async16(sB + buf * sBsz + (row * BP + ch * 8) * 2,
                       Bg + (long)(k0 + row) * ldn + bn + ch * 8);
        }
        cp_commit();
    };

    load_tiles(0, 0);

    const int nIter = K >> 6;
    for (int it = 0; it < nIter; it++) {
        int buf = it & 1;
        cp_wait_all();
        __syncthreads();
        if (it + 1 < nIter) load_tiles(buf ^ 1, (it + 1) * 64);

#pragma unroll
        for (int ks4 = 0; ks4 < 4; ks4++) {
            uint32_t afrag[MI][4];
            uint32_t bfrag[NJ][2];
            int lrow = lane & 15, lcol = (lane >> 4) * 8;
#pragma unroll
            for (int mi = 0; mi < MI; mi++) {
                uint32_t addr = sA + buf * sAsz +
                    ((MI * 16 * wm + 16 * mi + lrow) * APADE + ks4 * 16 + lcol) * 2;
                ldsm_x4(afrag[mi][0], afrag[mi][1], afrag[mi][2], afrag[mi][3], addr);
            }
#pragma unroll
            for (int nj2 = 0; nj2 < NJ / 2; nj2++) {
                uint32_t addr = sB + buf * sBsz +
                    ((ks4 * 16 + lrow) * BP + (8 * NJ) * wn + 16 * nj2 + lcol) * 2;
                uint32_t r0, r1, r2, r3;
                ldsm_x4_t(r0, r1, r2, r3, addr);
                bfrag[2 * nj2][0] = r0;     bfrag[2 * nj2][1] = r1;
                bfrag[2 * nj2 + 1][0] = r2; bfrag[2 * nj2 + 1][1] = r3;
            }
#pragma unroll
            for (int mi = 0; mi < MI; mi++)
#pragma unroll
                for (int nj = 0; nj < NJ; nj++)
                    mma16816(acc[mi][nj], afrag[mi], bfrag[nj]);
        }
        __syncthreads();
    }

    const float* Ad = (addend && ks == 0) ? (addend + (long)b * strideAdd) : nullptr;
    const float* bz = (ks == 0) ? bias : nullptr;
    int g = lane >> 2, tg = lane & 3;

    if (mode == 2) {
        bf16* C3 = (bf16*)Cv + (long)b * strideC;
#pragma unroll
        for (int mi = 0; mi < MI; mi++) {
            int row0 = bm + MI * 16 * wm + 16 * mi + g;
            int row1 = row0 + 8;
            float bv0 = bz ? bz[row0] : 0.f;
            float bv1 = bz ? bz[row1] : 0.f;
#pragma unroll
            for (int nj = 0; nj < NJ; nj++) {
                int col = bn + (8 * NJ) * wn + 8 * nj + 2 * tg;
#pragma unroll
                for (int half = 0; half < 2; half++) {
                    int row = half ? row1 : row0;
                    float bv = half ? bv1 : bv0;
                    float v0 = fmaxf(acc[mi][nj][2 * half]     + bv, 0.f);
                    float v1 = fmaxf(acc[mi][nj][2 * half + 1] + bv, 0.f);
                    bf16 h0, l0, h1, l1;
                    split_bf16(v0, h0, l0);
                    split_bf16(v1, h1, l1);
                    long base = (long)(3 * row) * ldn + col;
                    C3[base]               = h0; C3[base + 1]           = h1;
                    C3[base + ldn]         = l0; C3[base + ldn + 1]     = l1;
                    C3[base + 2 * ldn]     = h0; C3[base + 2 * ldn + 1] = h1;
                }
            }
        }
        return;
    }

    float* Cb = (float*)Cv + (long)b * strideC + (long)ks * strideCk;
#pragma unroll
    for (int mi = 0; mi < MI; mi++) {
        int row0 = bm + MI * 16 * wm + 16 * mi + g;
        int row1 = row0 + 8;
        float bv0 = bz ? bz[row0] : 0.f;
        float bv1 = bz ? bz[row1] : 0.f;
#pragma unroll
        for (int nj = 0; nj < NJ; nj++) {
            int col = bn + (8 * NJ) * wn + 8 * nj + 2 * tg;
            float v00 = acc[mi][nj][0] + bv0;
            float v01 = acc[mi][nj][1] + bv0;
            float v10 = acc[mi][nj][2] + bv1;
            float v11 = acc[mi][nj][3] + bv1;
            if (Ad) {
                v00 += Ad[(long)row0 * ldn + col];
                v01 += Ad[(long)row0 * ldn + col + 1];
                v10 += Ad[(long)row1 * ldn + col];
                v11 += Ad[(long)row1 * ldn + col + 1];
            }
            if (mode == 1) {
                v00 = fmaxf(v00, 0.f); v01 = fmaxf(v01, 0.f);
                v10 = fmaxf(v10, 0.f); v11 = fmaxf(v11, 0.f);
            }
            Cb[(long)row0 * ldn + col]     = v00;
            Cb[(long)row0 * ldn + col + 1] = v01;
            Cb[(long)row1 * ldn + col]     = v10;
            Cb[(long)row1 * ldn + col + 1] = v11;
        }
    }
}

// ---------------- tiled banded attention: 32-query blocks, 2 CTAs/SM ---------
// smem (floats): qw 32*68 + delta 64 + BDs 32*258 + U 64*260 + red 256 + sinv 32
#define AT_SMEM ((32*68 + 64 + 32*258 + 64*260 + 256 + 32) * 4)

__global__ __launch_bounds__(256)
void attn_tiled_kernel(const float* __restrict__ wheads,
                       const float* __restrict__ rk,
                       const float* __restrict__ rwb,
                       const float* __restrict__ rrb,
                       bf16*        __restrict__ avec3)
{
    extern __shared__ float sm[];
    float* qw    = sm;                      // [q][d]  stride 68 (q + rwb)
    float* delta = qw + 32 * 68;            // [64]    rrb - rwb
    float* BDs   = delta + 64;              // [q][t]  stride 258
    float* U     = BDs + 32 * 258;          // union (64*260 floats)
    float* red   = U + 64 * 260;            // [8][32]
    float* sinv  = red + 256;               // [32]
    float* Rs = U;                          // [d][t]  stride 260 (BD phase)
    float* Ks = U;                          // [jj][d] stride 68  (chunk phase)
    float* Vs = U + 64 * 68;                // [jj][d] stride 68
    float* Ps = U + 2 * 64 * 68;            // [q][jj] stride 65

    const int i0 = blockIdx.x * 32;
    const int h  = blockIdx.y;
    const int b  = blockIdx.z;
    const int tid = threadIdx.x;

    const float* W  = wheads + (long)b * (3 * D_MODEL) * KLEN;
    const float* Qg = W + (long)(h * DHEAD) * KLEN;
    const float* Kg = W + (long)(D_MODEL + h * DHEAD) * KLEN;
    const float* Vg = W + (long)(2 * D_MODEL + h * DHEAD) * KLEN;

    if (tid < 64)
        delta[tid] = rrb[h * DHEAD + tid] - rwb[h * DHEAD + tid];
    for (int idx = tid; idx < 32 * 64; idx += 256) {
        int d = idx >> 5, q = idx & 31;
        qw[q * 68 + d] = Qg[(long)d * KLEN + MLEN + i0 + q] + rwb[h * DHEAD + d];
    }
    for (int idx = tid; idx < 64 * 256; idx += 256) {
        int d = idx >> 8, t = idx & 255;
        Rs[d * 260 + t] = rk[(long)(h * DHEAD + d) * KLEN + 768 + t];
    }
    __syncthreads();

    // BD phase: thread (q = tid&31, tg = tid>>5) covers t in [tg*32, tg*32+32)
    {
        int q = tid & 31, tg = tid >> 5;
#pragma unroll
        for (int g2 = 0; g2 < 2; g2++) {
            int t0 = tg * 32 + g2 * 16;
            float acc[16];
#pragma unroll
            for (int u = 0; u < 16; u++) acc[u] = 0.f;
            for (int d = 0; d < 64; d++) {
                float qv = qw[q * 68 + d] + delta[d];
                const float4* rp = (const float4*)(Rs + d * 260 + t0);
#pragma unroll
                for (int u4 = 0; u4 < 4; u4++) {
                    float4 r4 = rp[u4];
                    acc[u4 * 4 + 0] = fmaf(qv, r4.x, acc[u4 * 4 + 0]);
                    acc[u4 * 4 + 1] = fmaf(qv, r4.y, acc[u4 * 4 + 1]);
                    acc[u4 * 4 + 2] = fmaf(qv, r4.z, acc[u4 * 4 + 2]);
                    acc[u4 * 4 + 3] = fmaf(qv, r4.w, acc[u4 * 4 + 3]);
                }
            }
#pragma unroll
            for (int u = 0; u < 16; u++)
                BDs[q * 258 + t0 + u] = acc[u];
        }
    }

    const int qi = tid & 31;
    const int jg = tid >> 5;       // 8 j-groups of 8 (QK) / 8 d-groups of 8 (AV)
    float O[8];
#pragma unroll
    for (int u = 0; u < 8; u++) O[u] = 0.f;
    float sume = 0.f;

    for (int c = 0; c < 5; c++) {
        int jb = c * 64;
        __syncthreads();
        for (int idx = tid; idx < 64 * 64; idx += 256) {
            int d = idx >> 6, jj = idx & 63;
            int jglob = i0 + 257 + jb + jj;
            float kv = 0.f, vv = 0.f;
            if (jglob < KLEN) {
                kv = Kg[(long)d * KLEN + jglob];
                vv = Vg[(long)d * KLEN + jglob];
            }
            Ks[jj * 68 + d] = kv;
            Vs[jj * 68 + d] = vv;
        }
        __syncthreads();

        // QK scores: 8 j's per thread, float4 over d (Ks reads broadcast)
        {
            float acc[8];
#pragma unroll
            for (int u = 0; u < 8; u++) acc[u] = 0.f;
            for (int d4 = 0; d4 < 16; d4++) {
                float4 qv4 = *(const float4*)(qw + qi * 68 + d4 * 4);
#pragma unroll
                for (int u = 0; u < 8; u++) {
                    float4 k4 = *(const float4*)(Ks + (jg * 8 + u) * 68 + d4 * 4);
                    acc[u] = fmaf(qv4.x, k4.x, acc[u]);
                    acc[u] = fmaf(qv4.y, k4.y, acc[u]);
                    acc[u] = fmaf(qv4.z, k4.z, acc[u]);
                    acc[u] = fmaf(qv4.w, k4.w, acc[u]);
                }
            }
#pragma unroll
            for (int u = 0; u < 8; u++) {
                int jp = jb + jg * 8 + u;
                int t  = jp - qi;
                float pv = 0.f;
                if (t >= 0 && t < 256)
                    pv = __expf((acc[u] + BDs[qi * 258 + t]) * 0.125f);
                sume += pv;
                Ps[qi * 65 + jg * 8 + u] = pv;
            }
        }
        __syncthreads();

        // AV: 8 d's per thread (Vs reads broadcast)
#pragma unroll 4
        for (int jj = 0; jj < 64; jj++) {
            float pv = Ps[qi * 65 + jj];
            float4 v4a = *(const float4*)(Vs + jj * 68 + jg * 8);
            float4 v4b = *(const float4*)(Vs + jj * 68 + jg * 8 + 4);
            O[0] = fmaf(pv, v4a.x, O[0]);
            O[1] = fmaf(pv, v4a.y, O[1]);
            O[2] = fmaf(pv, v4a.z, O[2]);
            O[3] = fmaf(pv, v4a.w, O[3]);
            O[4] = fmaf(pv, v4b.x, O[4]);
            O[5] = fmaf(pv, v4b.y, O[5]);
            O[6] = fmaf(pv, v4b.z, O[6]);
            O[7] = fmaf(pv, v4b.w, O[7]);
        }
    }

    red[jg * 32 + qi] = sume;
    __syncthreads();
    if (tid < 32) {
        float s = 0.f;
#pragma unroll
        for (int g8 = 0; g8 < 8; g8++) s += red[g8 * 32 + tid];
        sinv[tid] = 1.f / s;
    }
    __syncthreads();
    float inv = sinv[qi];
    bf16* outp = avec3 + (long)b * 3 * D_MODEL * QLEN;
#pragma unroll
    for (int u = 0; u < 8; u++) {
        int dp = h * DHEAD + jg * 8 + u;
        float v = O[u] * inv;
        bf16 hi, lo; split_bf16(v, hi, lo);
        long base = (long)(3 * dp) * QLEN + i0 + qi;
        outp[base]            = hi;
        outp[base + QLEN]     = lo;
        outp[base + 2 * QLEN] = hi;
    }
}

// ---------------- channel LayerNorm (optional 2nd input sum, fused split) ----
__global__ __launch_bounds__(256)
void ln_kernel(const float* __restrict__ ya, const float* __restrict__ yb,
               float* __restrict__ out, bf16* __restrict__ out3)
{
    int b  = blockIdx.y;
    int t0 = blockIdx.x * 32;
    int tid = threadIdx.x;
    int tt = tid & 31, cg = tid >> 5;
    const float* Ya = ya + (long)b * D_MODEL * QLEN;
    const float* Yb = yb ? (yb + (long)b * D_MODEL * QLEN) : nullptr;

    float s = 0.f, s2 = 0.f;
    for (int c = cg * 128; c < cg * 128 + 128; c++) {
        long idx = (long)c * QLEN + t0 + tt;
        float v = Ya[idx] + (Yb ? Yb[idx] : 0.f);
        s += v; s2 += v * v;
    }
    __shared__ float ssum[8][32], ssq[8][32];
    __shared__ float smean[32], srstd[32];
    ssum[cg][tt] = s; ssq[cg][tt] = s2;
    __syncthreads();
    if (tid < 32) {
        float ts = 0.f, ts2 = 0.f;
#pragma unroll
        for (int g = 0; g < 8; g++) { ts += ssum[g][tid]; ts2 += ssq[g][tid]; }
        float mean = ts * (1.0f / D_MODEL);
        float var  = ts2 * (1.0f / D_MODEL) - mean * mean;
        smean[tid] = mean;
        srstd[tid] = rsqrtf(var + 1e-5f);
    }
    __syncthreads();
    float mean = smean[tt], rstd = srstd[tt];
    float* O = out + (long)b * D_MODEL * QLEN;
    bf16* O3 = out3 ? (out3 + (long)b * 3 * D_MODEL * QLEN) : nullptr;
    for (int c = cg * 128; c < cg * 128 + 128; c++) {
        long idx = (long)c * QLEN + t0 + tt;
        float v = Ya[idx] + (Yb ? Yb[idx] : 0.f);
        float r = (v - mean) * rstd;
        O[idx] = r;
        if (O3) {
            bf16 hi, lo; split_bf16(r, hi, lo);
            long base = (long)(3 * c) * QLEN + t0 + tt;
            O3[base]            = hi;
            O3[base + QLEN]     = lo;
            O3[base + 2 * QLEN] = hi;
        }
    }
}

// ---------------- launcher ---------------------------------------------------
#define GSMEM44 ((2 * 128 * APADE + 2 * 64 * 136) * 2)    // 71680 (MI=4, NJ=4)
#define GSMEM24 ((2 * 64  * APADE + 2 * 64 * 136) * 2)    // 53248 (MI=2, NJ=4)

extern "C" void kernel_launch(void* const* d_in, const int* in_sizes, int n_in,
                              void* d_out, int out_size)
{
    const float* z1ss    = (const float*)d_in[0];
    const float* uss     = (const float*)d_in[1];
    const float* z0      = (const float*)d_in[2];
    const float* pos_emb = (const float*)d_in[3];
    const float* qkv_w   = (const float*)d_in[4];
    const float* r_w     = (const float*)d_in[5];
    const float* r_w_bias= (const float*)d_in[6];
    const float* r_r_bias= (const float*)d_in[7];
    const float* o_w     = (const float*)d_in[8];
    const float* o_b     = (const float*)d_in[9];
    const float* ff1_w   = (const float*)d_in[10];
    const float* ff1_b   = (const float*)d_in[11];
    const float* ff2_w   = (const float*)d_in[12];
    const float* ff2_b   = (const float*)d_in[13];
    float* out = (float*)d_out;

    float *wheads, *rkp, *tmp1, *x, *tmp2;
    bf16 *qkvw3, *rw3, *ow3, *ff1w3, *ff2w3, *pos3, *cat3, *avec3, *x3, *h3;
    cudaGetSymbolAddress((void**)&wheads, g_wheads);
    cudaGetSymbolAddress((void**)&rkp,    g_rkp);
    cudaGetSymbolAddress((void**)&tmp1,   g_tmp1);
    cudaGetSymbolAddress((void**)&x,      g_x);
    cudaGetSymbolAddress((void**)&tmp2,   g_tmp2);
    cudaGetSymbolAddress((void**)&qkvw3,  g_qkvw3);
    cudaGetSymbolAddress((void**)&rw3,    g_rw3);
    cudaGetSymbolAddress((void**)&ow3,    g_ow3);
    cudaGetSymbolAddress((void**)&ff1w3,  g_ff1w3);
    cudaGetSymbolAddress((void**)&ff2w3,  g_ff2w3);
    cudaGetSymbolAddress((void**)&pos3,   g_pos3);
    cudaGetSymbolAddress((void**)&cat3,   g_cat3);
    cudaGetSymbolAddress((void**)&avec3,  g_avec3);
    cudaGetSymbolAddress((void**)&x3,     g_x3);
    cudaGetSymbolAddress((void**)&h3,     g_h3);

    cudaFuncSetAttribute(attn_tiled_kernel,
                         cudaFuncAttributeMaxDynamicSharedMemorySize, AT_SMEM);
    cudaFuncSetAttribute(gemm_bf16_kernel<4, 4>,
                         cudaFuncAttributeMaxDynamicSharedMemorySize, GSMEM44);
    cudaFuncSetAttribute(gemm_bf16_kernel<2, 4>,
                         cudaFuncAttributeMaxDynamicSharedMemorySize, GSMEM24);

    const long s3dk = (long)3 * D_MODEL * KLEN;
    const long s3dq = (long)3 * D_MODEL * QLEN;
    const long s3iq = (long)3 * DINNER * QLEN;
    const long sdq  = (long)D_MODEL * QLEN;
    const long sDK  = (long)D_MODEL * KLEN;

    // [1] all weight expansions in one launch
    expand_weights_kernel<<<13312, 128>>>(qkv_w, r_w, o_w, ff1_w, ff2_w,
                                          qkvw3, rw3, ow3, ff1w3, ff2w3);
    // [2] cat expansion (cols [256,1024) only)
    expand_cat_kernel<<<dim3(3, D_MODEL, BSZ), 256>>>(z0, z1ss, 256);
    // [3] pos expansion (cols [768,1024) only)
    expandB_kernel<<<dim3(1, D_MODEL, 1), 256>>>(pos_emb, pos3, KLEN, 768, 0, 0);

    // [4] QKV over N-window [256,1024): 128x128 tiles -> 576 CTAs
    gemm_bf16_kernel<4, 4><<<dim3(6, 24, BSZ), 256, GSMEM44>>>(
        qkvw3, cat3 + 256, wheads + 256, nullptr, uss + 256,
        3 * D_MODEL, 3 * D_MODEL, KLEN, s3dk, s3dk, s3dk, 0, 0, 0);

    // [5] r_head_k (cols [768,1024)): K-split x4 -> 128 CTAs, 4 partial planes
    gemm_bf16_kernel<2, 4><<<dim3(2, 16, 4), 256, GSMEM24>>>(
        rw3, pos3 + 768, rkp + 768, nullptr, nullptr,
        3 * D_MODEL / 4, 3 * D_MODEL, KLEN, 0, 0, 0, sDK, 2, 0);

    // [5b] reduce 4 rk partial planes -> plane 0
    reduce_rk_kernel<<<256, 256>>>(rkp);

    // [6] banded attention (32-query blocks, 2 CTAs/SM) -> avec3
    attn_tiled_kernel<<<dim3(QLEN / 32, NHEAD, BSZ), 256, AT_SMEM>>>(
        wheads, rkp, r_w_bias, r_r_bias, avec3);

    // [7] O-proj: 64x128 tiles -> 256 CTAs
    gemm_bf16_kernel<2, 4><<<dim3(4, 16, BSZ), 256, GSMEM24>>>(
        ow3, avec3, tmp1, o_b, z1ss,
        3 * D_MODEL, 3 * D_MODEL, QLEN, s3dq, sdq, sdq, 0, 0, 0);

    // [8] x = LN(tmp1), fused x3
    ln_kernel<<<dim3(QLEN / 32, BSZ), 256>>>(tmp1, nullptr, x, x3);

    // [9] FF1: 128x128 tiles -> 512 CTAs, fused bf16-split relu epilogue
    gemm_bf16_kernel<4, 4><<<dim3(4, 32, BSZ), 256, GSMEM44>>>(
        ff1w3, x3, h3, ff1_b, nullptr,
        3 * D_MODEL, 3 * D_MODEL, QLEN, s3dq, s3iq, 0, 0, 0, 2);

    // [10] FF2: K-split x2, 128x128 tiles -> 256 CTAs (z = b*2 + ks)
    gemm_bf16_kernel<4, 4><<<dim3(4, 8, 2 * BSZ), 256, GSMEM44>>>(
        ff2w3, h3, tmp2, ff2_b, x,
        3 * DINNER / 2, 3 * DINNER, QLEN, s3iq, sdq, sdq, (long)BSZ * sdq, 1, 0);

    // [11] out = LN(tmp2_half0 + tmp2_half1)
    ln_kernel<<<dim3(QLEN / 32, BSZ), 256>>>(tmp2, tmp2 + (long)BSZ * sdq, out, nullptr);
}

// round 13
// speedup vs baseline: 1.1244x; 1.0154x over previous
#include <cuda_runtime.h>
#include <cuda_bf16.h>
#include <cstdint>

#define BSZ     4
#define D_MODEL 1024
#define QLEN    512
#define MLEN    512
#define KLEN    1024
#define NHEAD   16
#define DHEAD   64
#define DINNER  4096

typedef __nv_bfloat16 bf16;

// ---------------- fp32 scratch ----------------------------------------------
__device__ float g_wheads[BSZ * 3 * D_MODEL * KLEN];
__device__ float g_rkp[8 * D_MODEL * KLEN];          // 8 K-split partial planes
__device__ float g_x[BSZ * D_MODEL * QLEN];
__device__ float g_tmp2[2 * BSZ * D_MODEL * QLEN];   // K-split halves (O-proj / FF2)
__device__ float g_BD[NHEAD * 256 * (BSZ * QLEN)];   // BD[h][t][b*512+i], 33.5 MB

// ---------------- bf16-split (hi,hi,lo / hi,lo,hi) scratch -------------------
__device__ bf16 g_qkvw3[3 * D_MODEL * 3 * D_MODEL];
__device__ bf16 g_rw3  [D_MODEL * 3 * D_MODEL];
__device__ bf16 g_ow3  [D_MODEL * 3 * D_MODEL];
__device__ bf16 g_ff1w3[DINNER * 3 * D_MODEL];
__device__ bf16 g_ff2w3[D_MODEL * 3 * DINNER];
__device__ bf16 g_pos3 [3 * D_MODEL * KLEN];
__device__ bf16 g_cat3 [BSZ * 3 * D_MODEL * KLEN];
__device__ bf16 g_avec3[BSZ * 3 * D_MODEL * QLEN];
__device__ bf16 g_x3   [BSZ * 3 * D_MODEL * QLEN];
__device__ bf16 g_h3   [BSZ * 3 * DINNER * QLEN];
__device__ bf16 g_rA3  [NHEAD * 256 * 192];                 // BD GEMM A operand
__device__ bf16 g_qr3  [NHEAD * 192 * (BSZ * QLEN)];        // BD GEMM B operand

// ---------------- helpers ----------------------------------------------------
__device__ __forceinline__ void split_bf16(float x, bf16& hi, bf16& lo)
{
    hi = __float2bfloat16(x);
    lo = __float2bfloat16(x - __bfloat162float(hi));
}

__device__ __forceinline__ void cp_async16(uint32_t smem_dst, const void* gmem_src)
{
    asm volatile("cp.async.cg.shared.global [%0], [%1], 16;\n"
                 :: "r"(smem_dst), "l"(gmem_src));
}
__device__ __forceinline__ void cp_commit()
{
    asm volatile("cp.async.commit_group;\n");
}
__device__ __forceinline__ void cp_wait_all()
{
    asm volatile("cp.async.wait_group 0;\n");
}
__device__ __forceinline__ void ldsm_x4(uint32_t& r0, uint32_t& r1, uint32_t& r2, uint32_t& r3, uint32_t addr)
{
    asm volatile("ldmatrix.sync.aligned.m8n8.x4.shared.b16 {%0,%1,%2,%3}, [%4];\n"
                 : "=r"(r0), "=r"(r1), "=r"(r2), "=r"(r3) : "r"(addr));
}
__device__ __forceinline__ void ldsm_x4_t(uint32_t& r0, uint32_t& r1, uint32_t& r2, uint32_t& r3, uint32_t addr)
{
    asm volatile("ldmatrix.sync.aligned.m8n8.x4.trans.shared.b16 {%0,%1,%2,%3}, [%4];\n"
                 : "=r"(r0), "=r"(r1), "=r"(r2), "=r"(r3) : "r"(addr));
}
__device__ __forceinline__ void mma16816(float* c, const uint32_t* a, const uint32_t* b)
{
    asm volatile(
        "mma.sync.aligned.m16n8k16.row.col.f32.bf16.bf16.f32 "
        "{%0,%1,%2,%3}, {%4,%5,%6,%7}, {%8,%9}, {%0,%1,%2,%3};\n"
        : "+f"(c[0]), "+f"(c[1]), "+f"(c[2]), "+f"(c[3])
        : "r"(a[0]), "r"(a[1]), "r"(a[2]), "r"(a[3]), "r"(b[0]), "r"(b[1]));
}

// ---------------- expansion kernels ------------------------------------------
__global__ void expand_weights_kernel(const float* __restrict__ qkv_w,
                                      const float* __restrict__ r_w,
                                      const float* __restrict__ o_w,
                                      const float* __restrict__ ff1_w,
                                      const float* __restrict__ ff2_w,
                                      bf16* qkvw3, bf16* rw3, bf16* ow3,
                                      bf16* ff1w3, bf16* ff2w3)
{
    int cid = blockIdx.x;
    const float* in; bf16* out; int K; int row; int kc;
    if (cid < 3072)       { in = qkv_w; out = qkvw3; K = 1024; row = cid;        kc = 0; }
    else if (cid < 4096)  { in = r_w;   out = rw3;   K = 1024; row = cid - 3072; kc = 0; }
    else if (cid < 5120)  { in = o_w;   out = ow3;   K = 1024; row = cid - 4096; kc = 0; }
    else if (cid < 9216)  { in = ff1_w; out = ff1w3; K = 1024; row = cid - 5120; kc = 0; }
    else { int c = cid - 9216; in = ff2_w; out = ff2w3; K = 4096; row = c >> 2; kc = c & 3; }

    int k0 = (kc * 128 + threadIdx.x) * 8;
    const float4* ip = (const float4*)(in + (long)row * K + k0);
    float4 f0 = ip[0], f1 = ip[1];
    float v[8] = {f0.x, f0.y, f0.z, f0.w, f1.x, f1.y, f1.z, f1.w};
    unsigned short s[24];
#pragma unroll
    for (int j = 0; j < 8; j++) {
        bf16 hi, lo; split_bf16(v[j], hi, lo);
        unsigned short uh = __bfloat16_as_ushort(hi);
        unsigned short ul = __bfloat16_as_ushort(lo);
        s[3 * j] = uh; s[3 * j + 1] = uh; s[3 * j + 2] = ul;
    }
    uint32_t w[12];
#pragma unroll
    for (int i = 0; i < 12; i++)
        w[i] = (uint32_t)s[2 * i] | ((uint32_t)s[2 * i + 1] << 16);
    uint4* op = (uint4*)(out + (long)row * 3 * K + 3 * k0);
    op[0] = make_uint4(w[0], w[1], w[2], w[3]);
    op[1] = make_uint4(w[4], w[5], w[6], w[7]);
    op[2] = make_uint4(w[8], w[9], w[10], w[11]);
}

__global__ void expandB_kernel(const float* __restrict__ in, bf16* __restrict__ out,
                               int ldn, int n0, long sIn, long sOut)
{
    int n = n0 + blockIdx.x * 256 + threadIdx.x;
    int k = blockIdx.y;
    float x = in[(long)blockIdx.z * sIn + (long)k * ldn + n];
    bf16 hi, lo; split_bf16(x, hi, lo);
    bf16* o = out + (long)blockIdx.z * sOut + (long)(3 * k) * ldn + n;
    o[0] = hi; o[ldn] = lo; o[2 * ldn] = hi;
}

__global__ void expand_cat_kernel(const float* __restrict__ z0, const float* __restrict__ z1ss,
                                  int t0base)
{
    int t = t0base + blockIdx.x * 256 + threadIdx.x;
    int d = blockIdx.y;
    int b = blockIdx.z;
    float x = (t < MLEN) ? z0[((long)b * D_MODEL + d) * MLEN + t]
                         : z1ss[((long)b * D_MODEL + d) * QLEN + (t - MLEN)];
    bf16 hi, lo; split_bf16(x, hi, lo);
    bf16* o = g_cat3 + (long)b * 3 * D_MODEL * KLEN + (long)(3 * d) * KLEN + t;
    o[0] = hi; o[KLEN] = lo; o[2 * KLEN] = hi;
}

// reduce 8 rkp partial planes into plane 0 (cols [768,1024) only)
__global__ void reduce_rk_kernel(float* __restrict__ rkp)
{
    const long DK = (long)D_MODEL * KLEN;
    int idx = blockIdx.x * 256 + threadIdx.x;     // 65536 threads
    int row = idx >> 6;
    int t4  = (idx & 63) * 4;
    long base = (long)row * KLEN + 768 + t4;
    float4 a = *(const float4*)(rkp + base);
#pragma unroll
    for (int p = 1; p < 8; p++) {
        float4 q = *(const float4*)(rkp + p * DK + base);
        a.x += q.x; a.y += q.y; a.z += q.z; a.w += q.w;
    }
    *(float4*)(rkp + base) = a;
}

// rA3[h][t][3d] = A-pattern split of rk[h*64+d][768+t]
__global__ void expand_rA_kernel(const float* __restrict__ rkp, bf16* __restrict__ rA3)
{
    int h = blockIdx.y;
    int t = blockIdx.x * 16 + (threadIdx.x >> 4);
    int d0 = (threadIdx.x & 15) * 4;
    bf16* op = rA3 + ((long)h * 256 + t) * 192 + 3 * d0;
#pragma unroll
    for (int dd = 0; dd < 4; dd++) {
        int d = d0 + dd;
        float v = rkp[(long)(h * DHEAD + d) * KLEN + 768 + t];
        bf16 hi, lo; split_bf16(v, hi, lo);
        op[3 * dd] = hi; op[3 * dd + 1] = hi; op[3 * dd + 2] = lo;
    }
}

// qr3[h][3d+r][b*512+i] = B-pattern split of (Q[b,h,d,i] + rrb[h,d])
__global__ void expand_qr_kernel(const float* __restrict__ wheads,
                                 const float* __restrict__ rrb,
                                 bf16* __restrict__ qr3)
{
    int i = blockIdx.x * 256 + threadIdx.x;
    int d = blockIdx.y;
    int b = blockIdx.z & 3, h = blockIdx.z >> 2;
    float v = wheads[(long)b * 3 * D_MODEL * KLEN + (long)(h * DHEAD + d) * KLEN
                     + MLEN + i] + rrb[h * DHEAD + d];
    bf16 hi, lo; split_bf16(v, hi, lo);
    const int NB = BSZ * QLEN;  // 2048
    bf16* o = qr3 + (long)h * 192 * NB + (long)(3 * d) * NB + b * QLEN + i;
    o[0] = hi; o[NB] = lo; o[2 * NB] = hi;
}

// ---------------- tensor-core GEMM (mma.sync), templated tiles ---------------
#define APADE 72

template<int MI, int NJ>
__global__ __launch_bounds__(256, 2)
void gemm_bf16_kernel(const bf16* __restrict__ A,
                      const bf16* __restrict__ B,
                      void*       __restrict__ Cv,
                      const float* __restrict__ bias,
                      const float* __restrict__ addend,
                      int K, int ldk, int ldn,
                      long strideA, long strideB, long strideC,
                      long strideAdd, long strideCk,
                      int zshift, int mode, int tilemap)
{
    constexpr int GBMt = 32 * MI;
    constexpr int GBN  = 32 * NJ;
    constexpr int BP   = GBN + 8;
    constexpr int BCH  = GBN / 8;
    constexpr int BSH  = (NJ == 4 ? 4 : 5);

    extern __shared__ bf16 smem_g[];
    bf16* Asm = smem_g;
    bf16* Bsm = smem_g + 2 * GBMt * APADE;

    const int tid  = threadIdx.x;
    const int lane = tid & 31;
    const int warp = tid >> 5;
    const int wm = warp >> 2;
    const int wn = warp & 3;

    int bxi = blockIdx.x, byi = blockIdx.y;
    if (tilemap) {
        // QKV map: 96 K/V tiles (rows 1024..3071 x cols 256..1024) +
        //          32 Q tiles  (rows    0..1023 x cols 512..1024)
        int f = blockIdx.x;
        if (f < 96) { byi = 8 + f / 6; bxi = f % 6; }
        else        { int gq = f - 96; byi = gq >> 2; bxi = 2 + (gq & 3); }
    }
    const int bn = bxi * GBN;
    const int bm = byi * GBMt;
    const int b  = blockIdx.z >> zshift;
    const int ks = blockIdx.z & ((1 << zshift) - 1);

    const bf16* Ag = A + (long)b * strideA + (long)bm * ldk + (long)ks * K;
    const bf16* Bg = B + (long)b * strideB + (long)ks * K * ldn;

    uint32_t sA = (uint32_t)__cvta_generic_to_shared(Asm);
    uint32_t sB = (uint32_t)__cvta_generic_to_shared(Bsm);
    const uint32_t sAsz = GBMt * APADE * 2;
    const uint32_t sBsz = 64 * BP * 2;

    float acc[MI][NJ][4];
#pragma unroll
    for (int i = 0; i < MI; i++)
#pragma unroll
        for (int j = 0; j < NJ; j++)
#pragma unroll
            for (int r = 0; r < 4; r++) acc[i][j][r] = 0.f;

    auto load_tiles = [&](int buf, int k0) {
#pragma unroll
        for (int i = 0; i < MI; i++) {
            int c   = tid + 256 * i;
            int row = c >> 3, ch = c & 7;
            cp_async16(sA + buf * sAsz + (row * APADE + ch * 8) * 2,
                       Ag + (long)row * ldk + k0 + ch * 8);
        }
#pragma unroll
        for (int i = 0; i < (64 * BCH) / 256; i++) {
            int c   = tid + 256 * i;
            int row = c >> BSH, ch = c & (BCH - 1);
            cp_async16(sB + buf * sBsz + (row * BP + ch * 8) * 2,
                       Bg + (long)(k0 + row) * ldn + bn + ch * 8);
        }
        cp_commit();
    };

    load_tiles(0, 0);

    const int nIter = K >> 6;
    for (int it = 0; it < nIter; it++) {
        int buf = it & 1;
        cp_wait_all();
        __syncthreads();
        if (it + 1 < nIter) load_tiles(buf ^ 1, (it + 1) * 64);

#pragma unroll
        for (int ks4 = 0; ks4 < 4; ks4++) {
            uint32_t afrag[MI][4];
            uint32_t bfrag[NJ][2];
            int lrow = lane & 15, lcol = (lane >> 4) * 8;
#pragma unroll
            for (int mi = 0; mi < MI; mi++) {
                uint32_t addr = sA + buf * sAsz +
                    ((MI * 16 * wm + 16 * mi + lrow) * APADE + ks4 * 16 + lcol) * 2;
                ldsm_x4(afrag[mi][0], afrag[mi][1], afrag[mi][2], afrag[mi][3], addr);
            }
#pragma unroll
            for (int nj2 = 0; nj2 < NJ / 2; nj2++) {
                uint32_t addr = sB + buf * sBsz +
                    ((ks4 * 16 + lrow) * BP + (8 * NJ) * wn + 16 * nj2 + lcol) * 2;
                uint32_t r0, r1, r2, r3;
                ldsm_x4_t(r0, r1, r2, r3, addr);
                bfrag[2 * nj2][0] = r0;     bfrag[2 * nj2][1] = r1;
                bfrag[2 * nj2 + 1][0] = r2; bfrag[2 * nj2 + 1][1] = r3;
            }
#pragma unroll
            for (int mi = 0; mi < MI; mi++)
#pragma unroll
                for (int nj = 0; nj < NJ; nj++)
                    mma16816(acc[mi][nj], afrag[mi], bfrag[nj]);
        }
        __syncthreads();
    }

    const float* Ad = (addend && ks == 0) ? (addend + (long)b * strideAdd) : nullptr;
    const float* bz = (ks == 0) ? bias : nullptr;
    int g = lane >> 2, tg = lane & 3;

    if (mode == 2) {
        bf16* C3 = (bf16*)Cv + (long)b * strideC;
#pragma unroll
        for (int mi = 0; mi < MI; mi++) {
            int row0 = bm + MI * 16 * wm + 16 * mi + g;
            int row1 = row0 + 8;
            float bv0 = bz ? bz[row0] : 0.f;
            float bv1 = bz ? bz[row1] : 0.f;
#pragma unroll
            for (int nj = 0; nj < NJ; nj++) {
                int col = bn + (8 * NJ) * wn + 8 * nj + 2 * tg;
#pragma unroll
                for (int half = 0; half < 2; half++) {
                    int row = half ? row1 : row0;
                    float bv = half ? bv1 : bv0;
                    float v0 = fmaxf(acc[mi][nj][2 * half]     + bv, 0.f);
                    float v1 = fmaxf(acc[mi][nj][2 * half + 1] + bv, 0.f);
                    bf16 h0, l0, h1, l1;
                    split_bf16(v0, h0, l0);
                    split_bf16(v1, h1, l1);
                    long base = (long)(3 * row) * ldn + col;
                    C3[base]               = h0; C3[base + 1]           = h1;
                    C3[base + ldn]         = l0; C3[base + ldn + 1]     = l1;
                    C3[base + 2 * ldn]     = h0; C3[base + 2 * ldn + 1] = h1;
                }
            }
        }
        return;
    }

    float* Cb = (float*)Cv + (long)b * strideC + (long)ks * strideCk;
#pragma unroll
    for (int mi = 0; mi < MI; mi++) {
        int row0 = bm + MI * 16 * wm + 16 * mi + g;
        int row1 = row0 + 8;
        float bv0 = bz ? bz[row0] : 0.f;
        float bv1 = bz ? bz[row1] : 0.f;
#pragma unroll
        for (int nj = 0; nj < NJ; nj++) {
            int col = bn + (8 * NJ) * wn + 8 * nj + 2 * tg;
            float v00 = acc[mi][nj][0] + bv0;
            float v01 = acc[mi][nj][1] + bv0;
            float v10 = acc[mi][nj][2] + bv1;
            float v11 = acc[mi][nj][3] + bv1;
            if (Ad) {
                v00 += Ad[(long)row0 * ldn + col];
                v01 += Ad[(long)row0 * ldn + col + 1];
                v10 += Ad[(long)row1 * ldn + col];
                v11 += Ad[(long)row1 * ldn + col + 1];
            }
            if (mode == 1) {
                v00 = fmaxf(v00, 0.f); v01 = fmaxf(v01, 0.f);
                v10 = fmaxf(v10, 0.f); v11 = fmaxf(v11, 0.f);
            }
            Cb[(long)row0 * ldn + col]     = v00;
            Cb[(long)row0 * ldn + col + 1] = v01;
            Cb[(long)row1 * ldn + col]     = v10;
            Cb[(long)row1 * ldn + col + 1] = v11;
        }
    }
}

// ---------------- tiled banded attention: 32-query blocks --------------------
// BD table precomputed by GEMM; loaded from gmem. smem = 86 KB -> 2 CTAs/SM.
#define AT_SMEM ((32*68 + 32*258 + 64*68*2 + 32*65 + 256 + 32) * 4)

__global__ __launch_bounds__(256)
void attn_tiled_kernel(const float* __restrict__ wheads,
                       const float* __restrict__ BDg,
                       const float* __restrict__ rwb,
                       bf16*        __restrict__ avec3)
{
    extern __shared__ float sm[];
    float* qw   = sm;                       // [q][d]  stride 68 (q + rwb)
    float* BDs  = qw + 32 * 68;             // [q][t]  stride 258
    float* U    = BDs + 32 * 258;
    float* Ks   = U;                        // [jj][d] stride 68
    float* Vs   = U + 64 * 68;              // [jj][d] stride 68
    float* Ps   = U + 2 * 64 * 68;          // [q][jj] stride 65
    float* red  = U + 2 * 64 * 68 + 32 * 65;  // [8][32]
    float* sinv = red + 256;                // [32]

    const int i0 = blockIdx.x * 32;
    const int h  = blockIdx.y;
    const int b  = blockIdx.z;
    const int tid = threadIdx.x;

    const float* W  = wheads + (long)b * (3 * D_MODEL) * KLEN;
    const float* Qg = W + (long)(h * DHEAD) * KLEN;
    const float* Kg = W + (long)(D_MODEL + h * DHEAD) * KLEN;
    const float* Vg = W + (long)(2 * D_MODEL + h * DHEAD) * KLEN;

    for (int idx = tid; idx < 32 * 64; idx += 256) {
        int d = idx >> 5, q = idx & 31;
        qw[q * 68 + d] = Qg[(long)d * KLEN + MLEN + i0 + q] + rwb[h * DHEAD + d];
    }
    // load BD tile: BDg[h][t][b*512 + i0 + q]
    {
        const float* BDh = BDg + (long)h * 256 * (BSZ * QLEN) + b * QLEN + i0;
        for (int idx = tid; idx < 32 * 256; idx += 256) {
            int q = idx & 31, t = idx >> 5;
            BDs[q * 258 + t] = BDh[(long)t * (BSZ * QLEN) + q];
        }
    }
    __syncthreads();

    const int qi = tid & 31;
    const int jg = tid >> 5;
    float O[8];
#pragma unroll
    for (int u = 0; u < 8; u++) O[u] = 0.f;
    float sume = 0.f;

    for (int c = 0; c < 5; c++) {
        int jb = c * 64;
        if (c > 0) __syncthreads();
        for (int idx = tid; idx < 64 * 64; idx += 256) {
            int d = idx >> 6, jj = idx & 63;
            int jglob = i0 + 257 + jb + jj;
            float kv = 0.f, vv = 0.f;
            if (jglob < KLEN) {
                kv = Kg[(long)d * KLEN + jglob];
                vv = Vg[(long)d * KLEN + jglob];
            }
            Ks[jj * 68 + d] = kv;
            Vs[jj * 68 + d] = vv;
        }
        __syncthreads();

        // QK scores: 8 j's per thread, float4 over d
        {
            float acc[8];
#pragma unroll
            for (int u = 0; u < 8; u++) acc[u] = 0.f;
            for (int d4 = 0; d4 < 16; d4++) {
                float4 qv4 = *(const float4*)(qw + qi * 68 + d4 * 4);
#pragma unroll
                for (int u = 0; u < 8; u++) {
                    float4 k4 = *(const float4*)(Ks + (jg * 8 + u) * 68 + d4 * 4);
                    acc[u] = fmaf(qv4.x, k4.x, acc[u]);
                    acc[u] = fmaf(qv4.y, k4.y, acc[u]);
                    acc[u] = fmaf(qv4.z, k4.z, acc[u]);
                    acc[u] = fmaf(qv4.w, k4.w, acc[u]);
                }
            }
#pragma unroll
            for (int u = 0; u < 8; u++) {
                int jp = jb + jg * 8 + u;
                int t  = jp - qi;
                float pv = 0.f;
                if (t >= 0 && t < 256)
                    pv = __expf((acc[u] + BDs[qi * 258 + t]) * 0.125f);
                sume += pv;
                Ps[qi * 65 + jg * 8 + u] = pv;
            }
        }
        __syncthreads();

        // AV: 8 d's per thread
#pragma unroll 4
        for (int jj = 0; jj < 64; jj++) {
            float pv = Ps[qi * 65 + jj];
            float4 v4a = *(const float4*)(Vs + jj * 68 + jg * 8);
            float4 v4b = *(const float4*)(Vs + jj * 68 + jg * 8 + 4);
            O[0] = fmaf(pv, v4a.x, O[0]);
            O[1] = fmaf(pv, v4a.y, O[1]);
            O[2] = fmaf(pv, v4a.z, O[2]);
            O[3] = fmaf(pv, v4a.w, O[3]);
            O[4] = fmaf(pv, v4b.x, O[4]);
            O[5] = fmaf(pv, v4b.y, O[5]);
            O[6] = fmaf(pv, v4b.z, O[6]);
            O[7] = fmaf(pv, v4b.w, O[7]);
        }
    }

    red[jg * 32 + qi] = sume;
    __syncthreads();
    if (tid < 32) {
        float s = 0.f;
#pragma unroll
        for (int g8 = 0; g8 < 8; g8++) s += red[g8 * 32 + tid];
        sinv[tid] = 1.f / s;
    }
    __syncthreads();
    float inv = sinv[qi];
    bf16* outp = avec3 + (long)b * 3 * D_MODEL * QLEN;
#pragma unroll
    for (int u = 0; u < 8; u++) {
        int dp = h * DHEAD + jg * 8 + u;
        float v = O[u] * inv;
        bf16 hi, lo; split_bf16(v, hi, lo);
        long base = (long)(3 * dp) * QLEN + i0 + qi;
        outp[base]            = hi;
        outp[base + QLEN]     = lo;
        outp[base + 2 * QLEN] = hi;
    }
}

// ---------------- channel LayerNorm (optional 2nd input sum, fused split) ----
__global__ __launch_bounds__(256)
void ln_kernel(const float* __restrict__ ya, const float* __restrict__ yb,
               float* __restrict__ out, bf16* __restrict__ out3)
{
    int b  = blockIdx.y;
    int t0 = blockIdx.x * 32;
    int tid = threadIdx.x;
    int tt = tid & 31, cg = tid >> 5;
    const float* Ya = ya + (long)b * D_MODEL * QLEN;
    const float* Yb = yb ? (yb + (long)b * D_MODEL * QLEN) : nullptr;

    float s = 0.f, s2 = 0.f;
    for (int c = cg * 128; c < cg * 128 + 128; c++) {
        long idx = (long)c * QLEN + t0 + tt;
        float v = Ya[idx] + (Yb ? Yb[idx] : 0.f);
        s += v; s2 += v * v;
    }
    __shared__ float ssum[8][32], ssq[8][32];
    __shared__ float smean[32], srstd[32];
    ssum[cg][tt] = s; ssq[cg][tt] = s2;
    __syncthreads();
    if (tid < 32) {
        float ts = 0.f, ts2 = 0.f;
#pragma unroll
        for (int g = 0; g < 8; g++) { ts += ssum[g][tid]; ts2 += ssq[g][tid]; }
        float mean = ts * (1.0f / D_MODEL);
        float var  = ts2 * (1.0f / D_MODEL) - mean * mean;
        smean[tid] = mean;
        srstd[tid] = rsqrtf(var + 1e-5f);
    }
    __syncthreads();
    float mean = smean[tt], rstd = srstd[tt];
    float* O = out + (long)b * D_MODEL * QLEN;
    bf16* O3 = out3 ? (out3 + (long)b * 3 * D_MODEL * QLEN) : nullptr;
    for (int c = cg * 128; c < cg * 128 + 128; c++) {
        long idx = (long)c * QLEN + t0 + tt;
        float v = Ya[idx] + (Yb ? Yb[idx] : 0.f);
        float r = (v - mean) * rstd;
        O[idx] = r;
        if (O3) {
            bf16 hi, lo; split_bf16(r, hi, lo);
            long base = (long)(3 * c) * QLEN + t0 + tt;
            O3[base]            = hi;
            O3[base + QLEN]     = lo;
            O3[base + 2 * QLEN] = hi;
        }
    }
}

// ---------------- launcher ---------------------------------------------------
#define GSMEM44 ((2 * 128 * APADE + 2 * 64 * 136) * 2)    // 71680 (MI=4, NJ=4)

extern "C" void kernel_launch(void* const* d_in, const int* in_sizes, int n_in,
                              void* d_out, int out_size)
{
    const float* z1ss    = (const float*)d_in[0];
    const float* uss     = (const float*)d_in[1];
    const float* z0      = (const float*)d_in[2];
    const float* pos_emb = (const float*)d_in[3];
    const float* qkv_w   = (const float*)d_in[4];
    const float* r_w     = (const float*)d_in[5];
    const float* r_w_bias= (const float*)d_in[6];
    const float* r_r_bias= (const float*)d_in[7];
    const float* o_w     = (const float*)d_in[8];
    const float* o_b     = (const float*)d_in[9];
    const float* ff1_w   = (const float*)d_in[10];
    const float* ff1_b   = (const float*)d_in[11];
    const float* ff2_w   = (const float*)d_in[12];
    const float* ff2_b   = (const float*)d_in[13];
    float* out = (float*)d_out;

    float *wheads, *rkp, *x, *tmp2, *BDg;
    bf16 *qkvw3, *rw3, *ow3, *ff1w3, *ff2w3, *pos3, *cat3, *avec3, *x3, *h3, *rA3, *qr3;
    cudaGetSymbolAddress((void**)&wheads, g_wheads);
    cudaGetSymbolAddress((void**)&rkp,    g_rkp);
    cudaGetSymbolAddress((void**)&x,      g_x);
    cudaGetSymbolAddress((void**)&tmp2,   g_tmp2);
    cudaGetSymbolAddress((void**)&BDg,    g_BD);
    cudaGetSymbolAddress((void**)&qkvw3,  g_qkvw3);
    cudaGetSymbolAddress((void**)&rw3,    g_rw3);
    cudaGetSymbolAddress((void**)&ow3,    g_ow3);
    cudaGetSymbolAddress((void**)&ff1w3,  g_ff1w3);
    cudaGetSymbolAddress((void**)&ff2w3,  g_ff2w3);
    cudaGetSymbolAddress((void**)&pos3,   g_pos3);
    cudaGetSymbolAddress((void**)&cat3,   g_cat3);
    cudaGetSymbolAddress((void**)&avec3,  g_avec3);
    cudaGetSymbolAddress((void**)&x3,     g_x3);
    cudaGetSymbolAddress((void**)&h3,     g_h3);
    cudaGetSymbolAddress((void**)&rA3,    g_rA3);
    cudaGetSymbolAddress((void**)&qr3,    g_qr3);

    cudaFuncSetAttribute(attn_tiled_kernel,
                         cudaFuncAttributeMaxDynamicSharedMemorySize, AT_SMEM);
    cudaFuncSetAttribute(gemm_bf16_kernel<4, 4>,
                         cudaFuncAttributeMaxDynamicSharedMemorySize, GSMEM44);

    const long s3dk = (long)3 * D_MODEL * KLEN;
    const long s3dq = (long)3 * D_MODEL * QLEN;
    const long s3iq = (long)3 * DINNER * QLEN;
    const long sdq  = (long)D_MODEL * QLEN;
    const long sDK  = (long)D_MODEL * KLEN;
    const int  NB   = BSZ * QLEN;   // 2048

    // [1] all weight expansions
    expand_weights_kernel<<<13312, 128>>>(qkv_w, r_w, o_w, ff1_w, ff2_w,
                                          qkvw3, rw3, ow3, ff1w3, ff2w3);
    // [2] cat expansion (cols [256,1024))
    expand_cat_kernel<<<dim3(3, D_MODEL, BSZ), 256>>>(z0, z1ss, 256);
    // [3] pos expansion (cols [768,1024))
    expandB_kernel<<<dim3(1, D_MODEL, 1), 256>>>(pos_emb, pos3, KLEN, 768, 0, 0);

    // [4] QKV with custom tile list: 128 tiles x 4 batches = 512 CTAs
    gemm_bf16_kernel<4, 4><<<dim3(128, 1, BSZ), 256, GSMEM44>>>(
        qkvw3, cat3 + 256, wheads + 256, nullptr, uss + 256,
        3 * D_MODEL, 3 * D_MODEL, KLEN, 0, s3dk, s3dk, s3dk, 0, 0, 0, 1);

    // [5] r_head_k (cols [768,1024)): MI=4, K-split x8 -> 128 CTAs
    gemm_bf16_kernel<4, 4><<<dim3(2, 8, 8), 256, GSMEM44>>>(
        rw3, pos3 + 768, rkp + 768, nullptr, nullptr,
        3 * D_MODEL / 8, 3 * D_MODEL, KLEN, 0, 0, 0, 0, sDK, 3, 0, 0);

    // [6] reduce 8 rk partial planes -> plane 0
    reduce_rk_kernel<<<256, 256>>>(rkp);

    // [7] expand rA3 (BD GEMM A operand)
    expand_rA_kernel<<<dim3(16, NHEAD), 256>>>(rkp, rA3);
    // [8] expand qr3 (BD GEMM B operand)
    expand_qr_kernel<<<dim3(QLEN / 256, DHEAD, BSZ * NHEAD), 256>>>(
        wheads, r_r_bias, qr3);

    // [9] BD GEMM: per head, M=256(t) x N=2048(b*512+i) x K=192 -> 512 CTAs
    gemm_bf16_kernel<4, 4><<<dim3(16, 2, NHEAD), 256, GSMEM44>>>(
        rA3, qr3, BDg, nullptr, nullptr,
        192, 192, NB, (long)256 * 192, (long)192 * NB, (long)256 * NB,
        0, 0, 0, 0, 0);

    // [10] banded attention (BD from gmem) -> avec3
    attn_tiled_kernel<<<dim3(QLEN / 32, NHEAD, BSZ), 256, AT_SMEM>>>(
        wheads, BDg, r_w_bias, avec3);

    // [11] O-proj: MI=4, K-split x2 -> 256 CTAs, partials into tmp2 planes
    gemm_bf16_kernel<4, 4><<<dim3(4, 8, 2 * BSZ), 256, GSMEM44>>>(
        ow3, avec3, tmp2, o_b, z1ss,
        3 * D_MODEL / 2, 3 * D_MODEL, QLEN, 0, s3dq, sdq, sdq, (long)BSZ * sdq, 1, 0, 0);

    // [12] x = LN(tmp2_half0 + tmp2_half1), fused x3
    ln_kernel<<<dim3(QLEN / 32, BSZ), 256>>>(tmp2, tmp2 + (long)BSZ * sdq, x, x3);

    // [13] FF1: 512 CTAs, fused bf16-split relu epilogue
    gemm_bf16_kernel<4, 4><<<dim3(4, 32, BSZ), 256, GSMEM44>>>(
        ff1w3, x3, h3, ff1_b, nullptr,
        3 * D_MODEL, 3 * D_MODEL, QLEN, 0, s3dq, s3iq, 0, 0, 0, 2, 0);

    // [14] FF2: K-split x2 -> 256 CTAs, partials into tmp2 planes
    gemm_bf16_kernel<4, 4><<<dim3(4, 8, 2 * BSZ), 256, GSMEM44>>>(
        ff2w3, h3, tmp2, ff2_b, x,
        3 * DINNER / 2, 3 * DINNER, QLEN, 0, s3iq, sdq, sdq, (long)BSZ * sdq, 1, 0, 0);

    // [15] out = LN(tmp2_half0 + tmp2_half1)
    ln_kernel<<<dim3(QLEN / 32, BSZ), 256>>>(tmp2, tmp2 + (long)BSZ * sdq, out, nullptr);
}

// round 14
// speedup vs baseline: 1.1532x; 1.0256x over previous
#include <cuda_runtime.h>
#include <cuda_bf16.h>
#include <cstdint>

#define BSZ     4
#define D_MODEL 1024
#define QLEN    512
#define MLEN    512
#define KLEN    1024
#define NHEAD   16
#define DHEAD   64
#define DINNER  4096

typedef __nv_bfloat16 bf16;

// ---------------- fp32 scratch ----------------------------------------------
__device__ float g_wheads[BSZ * 3 * D_MODEL * KLEN];
__device__ float g_rkp[8 * D_MODEL * KLEN];          // 8 K-split partial planes
__device__ float g_x[BSZ * D_MODEL * QLEN];
__device__ float g_tmp2[2 * BSZ * D_MODEL * QLEN];   // K-split halves
__device__ float g_BD[NHEAD * 256 * (BSZ * QLEN)];   // BD[h][t][b*512+i]

// ---------------- two-plane bf16 split scratch ([hi | lo]) -------------------
__device__ bf16 g_qkvw2[3 * D_MODEL * 2 * D_MODEL];
__device__ bf16 g_rw2  [D_MODEL * 2 * D_MODEL];
__device__ bf16 g_ow2  [D_MODEL * 2 * D_MODEL];
__device__ bf16 g_ff1w2[DINNER * 2 * D_MODEL];
__device__ bf16 g_ff2w2[D_MODEL * 2 * DINNER];
__device__ bf16 g_pos2 [2 * D_MODEL * KLEN];
__device__ bf16 g_cat2 [BSZ * 2 * D_MODEL * KLEN];
__device__ bf16 g_avec2[BSZ * 2 * D_MODEL * QLEN];
__device__ bf16 g_x2   [BSZ * 2 * D_MODEL * QLEN];
__device__ bf16 g_h2   [BSZ * 2 * DINNER * QLEN];
__device__ bf16 g_rA2  [NHEAD * 256 * 128];
__device__ bf16 g_qr2  [NHEAD * 128 * (BSZ * QLEN)];

// ---------------- helpers ----------------------------------------------------
__device__ __forceinline__ void split_bf16(float x, bf16& hi, bf16& lo)
{
    hi = __float2bfloat16(x);
    lo = __float2bfloat16(x - __bfloat162float(hi));
}

__device__ __forceinline__ void cp_async16(uint32_t smem_dst, const void* gmem_src)
{
    asm volatile("cp.async.cg.shared.global [%0], [%1], 16;\n"
                 :: "r"(smem_dst), "l"(gmem_src));
}
__device__ __forceinline__ void cp_commit()
{
    asm volatile("cp.async.commit_group;\n");
}
__device__ __forceinline__ void cp_wait_all()
{
    asm volatile("cp.async.wait_group 0;\n");
}
__device__ __forceinline__ void ldsm_x4(uint32_t& r0, uint32_t& r1, uint32_t& r2, uint32_t& r3, uint32_t addr)
{
    asm volatile("ldmatrix.sync.aligned.m8n8.x4.shared.b16 {%0,%1,%2,%3}, [%4];\n"
                 : "=r"(r0), "=r"(r1), "=r"(r2), "=r"(r3) : "r"(addr));
}
__device__ __forceinline__ void ldsm_x4_t(uint32_t& r0, uint32_t& r1, uint32_t& r2, uint32_t& r3, uint32_t addr)
{
    asm volatile("ldmatrix.sync.aligned.m8n8.x4.trans.shared.b16 {%0,%1,%2,%3}, [%4];\n"
                 : "=r"(r0), "=r"(r1), "=r"(r2), "=r"(r3) : "r"(addr));
}
__device__ __forceinline__ void mma16816(float* c, const uint32_t* a, const uint32_t* b)
{
    asm volatile(
        "mma.sync.aligned.m16n8k16.row.col.f32.bf16.bf16.f32 "
        "{%0,%1,%2,%3}, {%4,%5,%6,%7}, {%8,%9}, {%0,%1,%2,%3};\n"
        : "+f"(c[0]), "+f"(c[1]), "+f"(c[2]), "+f"(c[3])
        : "r"(a[0]), "r"(a[1]), "r"(a[2]), "r"(a[3]), "r"(b[0]), "r"(b[1]));
}

// ---------------- expansion kernels (two-plane) -------------------------------
__global__ void expand_weights_kernel(const float* __restrict__ qkv_w,
                                      const float* __restrict__ r_w,
                                      const float* __restrict__ o_w,
                                      const float* __restrict__ ff1_w,
                                      const float* __restrict__ ff2_w,
                                      bf16* qkvw2, bf16* rw2, bf16* ow2,
                                      bf16* ff1w2, bf16* ff2w2)
{
    int cid = blockIdx.x;
    const float* in; bf16* out; int K; int row; int kc;
    if (cid < 3072)       { in = qkv_w; out = qkvw2; K = 1024; row = cid;        kc = 0; }
    else if (cid < 4096)  { in = r_w;   out = rw2;   K = 1024; row = cid - 3072; kc = 0; }
    else if (cid < 5120)  { in = o_w;   out = ow2;   K = 1024; row = cid - 4096; kc = 0; }
    else if (cid < 9216)  { in = ff1_w; out = ff1w2; K = 1024; row = cid - 5120; kc = 0; }
    else { int c = cid - 9216; in = ff2_w; out = ff2w2; K = 4096; row = c >> 2; kc = c & 3; }

    int k0 = (kc * 128 + threadIdx.x) * 8;
    const float4* ip = (const float4*)(in + (long)row * K + k0);
    float4 f0 = ip[0], f1 = ip[1];
    float v[8] = {f0.x, f0.y, f0.z, f0.w, f1.x, f1.y, f1.z, f1.w};
    unsigned short sh[8], sl[8];
#pragma unroll
    for (int j = 0; j < 8; j++) {
        bf16 hi, lo; split_bf16(v[j], hi, lo);
        sh[j] = __bfloat16_as_ushort(hi);
        sl[j] = __bfloat16_as_ushort(lo);
    }
    uint32_t wh[4], wl[4];
#pragma unroll
    for (int i = 0; i < 4; i++) {
        wh[i] = (uint32_t)sh[2 * i] | ((uint32_t)sh[2 * i + 1] << 16);
        wl[i] = (uint32_t)sl[2 * i] | ((uint32_t)sl[2 * i + 1] << 16);
    }
    bf16* orow = out + (long)row * 2 * K;
    *(uint4*)(orow + k0)     = make_uint4(wh[0], wh[1], wh[2], wh[3]);
    *(uint4*)(orow + K + k0) = make_uint4(wl[0], wl[1], wl[2], wl[3]);
}

// B-operand two-plane: hi row k, lo row Kp+k
__global__ void expandB_kernel(const float* __restrict__ in, bf16* __restrict__ out,
                               int ldn, int n0, int Kp, long sIn, long sOut)
{
    int n = n0 + blockIdx.x * 256 + threadIdx.x;
    int k = blockIdx.y;
    float x = in[(long)blockIdx.z * sIn + (long)k * ldn + n];
    bf16 hi, lo; split_bf16(x, hi, lo);
    bf16* o = out + (long)blockIdx.z * sOut + (long)k * ldn + n;
    o[0] = hi;
    o[(long)Kp * ldn] = lo;
}

__global__ void expand_cat_kernel(const float* __restrict__ z0, const float* __restrict__ z1ss,
                                  int t0base)
{
    int t = t0base + blockIdx.x * 256 + threadIdx.x;
    int d = blockIdx.y;
    int b = blockIdx.z;
    float x = (t < MLEN) ? z0[((long)b * D_MODEL + d) * MLEN + t]
                         : z1ss[((long)b * D_MODEL + d) * QLEN + (t - MLEN)];
    bf16 hi, lo; split_bf16(x, hi, lo);
    bf16* o = g_cat2 + (long)b * 2 * D_MODEL * KLEN + (long)d * KLEN + t;
    o[0] = hi;
    o[(long)D_MODEL * KLEN] = lo;
}

__global__ void reduce_rk_kernel(float* __restrict__ rkp)
{
    const long DK = (long)D_MODEL * KLEN;
    int idx = blockIdx.x * 256 + threadIdx.x;
    int row = idx >> 6;
    int t4  = (idx & 63) * 4;
    long base = (long)row * KLEN + 768 + t4;
    float4 a = *(const float4*)(rkp + base);
#pragma unroll
    for (int p = 1; p < 8; p++) {
        float4 q = *(const float4*)(rkp + p * DK + base);
        a.x += q.x; a.y += q.y; a.z += q.z; a.w += q.w;
    }
    *(float4*)(rkp + base) = a;
}

// rA2[h][t][0..64)=hi, [64..128)=lo of rk[h*64+d][768+t]
__global__ void expand_rA_kernel(const float* __restrict__ rkp, bf16* __restrict__ rA2)
{
    int h = blockIdx.y;
    int t = blockIdx.x * 16 + (threadIdx.x >> 4);
    int d0 = (threadIdx.x & 15) * 4;
    bf16* op = rA2 + ((long)h * 256 + t) * 128 + d0;
#pragma unroll
    for (int dd = 0; dd < 4; dd++) {
        int d = d0 + dd;
        float v = rkp[(long)(h * DHEAD + d) * KLEN + 768 + t];
        bf16 hi, lo; split_bf16(v, hi, lo);
        op[dd] = hi; op[64 + dd] = lo;
    }
}

// qr2[h][d][b*512+i]=hi, [64+d]=lo of (Q + rrb)
__global__ void expand_qr_kernel(const float* __restrict__ wheads,
                                 const float* __restrict__ rrb,
                                 bf16* __restrict__ qr2)
{
    int i = blockIdx.x * 256 + threadIdx.x;
    int d = blockIdx.y;
    int b = blockIdx.z & 3, h = blockIdx.z >> 2;
    float v = wheads[(long)b * 3 * D_MODEL * KLEN + (long)(h * DHEAD + d) * KLEN
                     + MLEN + i] + rrb[h * DHEAD + d];
    bf16 hi, lo; split_bf16(v, hi, lo);
    const int NB = BSZ * QLEN;
    bf16* o = qr2 + (long)h * 128 * NB + (long)d * NB + b * QLEN + i;
    o[0] = hi;
    o[64 * NB] = lo;
}

// ---------------- tensor-core GEMM, two-plane 3-term mapping ------------------
// Iteration space: 3 parts x Kps. part0: hiA*hiB, part1: hiA*loB, part2: loA*hiB.
// A: [M][2*Kp] (hi cols [0,Kp), lo [Kp,2Kp)), ldk = 2*Kp.
// B: [2*Kp][ldn] rows (hi [0,Kp), lo [Kp,2Kp)).
#define APADE 72

template<int MI, int NJ>
__global__ __launch_bounds__(256, 2)
void gemm_bf16_kernel(const bf16* __restrict__ A,
                      const bf16* __restrict__ B,
                      void*       __restrict__ Cv,
                      const float* __restrict__ bias,
                      const float* __restrict__ addend,
                      int Kps, int Kp, int ldn,
                      long strideA, long strideB, long strideC,
                      long strideAdd, long strideCk, long planeC,
                      int zshift, int mode, int tilemap)
{
    constexpr int GBMt = 32 * MI;
    constexpr int GBN  = 32 * NJ;
    constexpr int BP   = GBN + 8;
    constexpr int BCH  = GBN / 8;
    constexpr int BSH  = (NJ == 4 ? 4 : 5);

    extern __shared__ bf16 smem_g[];
    bf16* Asm = smem_g;
    bf16* Bsm = smem_g + 2 * GBMt * APADE;

    const int tid  = threadIdx.x;
    const int lane = tid & 31;
    const int warp = tid >> 5;
    const int wm = warp >> 2;
    const int wn = warp & 3;

    int bxi = blockIdx.x, byi = blockIdx.y;
    if (tilemap) {
        int f = blockIdx.x;
        if (f < 96) { byi = 8 + f / 6; bxi = f % 6; }
        else        { int gq = f - 96; byi = gq >> 2; bxi = 2 + (gq & 3); }
    }
    const int bn = bxi * GBN;
    const int bm = byi * GBMt;
    const int b  = blockIdx.z >> zshift;
    const int ks = blockIdx.z & ((1 << zshift) - 1);
    const int ldk = 2 * Kp;

    const bf16* Ag = A + (long)b * strideA + (long)bm * ldk;
    const bf16* Bg = B + (long)b * strideB;

    uint32_t sA = (uint32_t)__cvta_generic_to_shared(Asm);
    uint32_t sB = (uint32_t)__cvta_generic_to_shared(Bsm);
    const uint32_t sAsz = GBMt * APADE * 2;
    const uint32_t sBsz = 64 * BP * 2;

    float acc[MI][NJ][4];
#pragma unroll
    for (int i = 0; i < MI; i++)
#pragma unroll
        for (int j = 0; j < NJ; j++)
#pragma unroll
            for (int r = 0; r < 4; r++) acc[i][j][r] = 0.f;

    auto load_tiles = [&](int buf, int k0) {
        int part = k0 / Kps;
        int kk   = k0 - part * Kps;
        long aoff = (part < 2 ? 0L : (long)Kp) + (long)ks * Kps + kk;
        long boff = (part == 1 ? (long)Kp : 0L) + (long)ks * Kps + kk;
#pragma unroll
        for (int i = 0; i < MI; i++) {
            int c   = tid + 256 * i;
            int row = c >> 3, ch = c & 7;
            cp_async16(sA + buf * sAsz + (row * APADE + ch * 8) * 2,
                       Ag + (long)row * ldk + aoff + ch * 8);
        }
#pragma unroll
        for (int i = 0; i < (64 * BCH) / 256; i++) {
            int c   = tid + 256 * i;
            int row = c >> BSH, ch = c & (BCH - 1);
            cp_async16(sB + buf * sBsz + (row * BP + ch * 8) * 2,
                       Bg + (boff + row) * ldn + bn + ch * 8);
        }
        cp_commit();
    };

    load_tiles(0, 0);

    const int nIter = (3 * Kps) >> 6;
    for (int it = 0; it < nIter; it++) {
        int buf = it & 1;
        cp_wait_all();
        __syncthreads();
        if (it + 1 < nIter) load_tiles(buf ^ 1, (it + 1) * 64);

#pragma unroll
        for (int ks4 = 0; ks4 < 4; ks4++) {
            uint32_t afrag[MI][4];
            uint32_t bfrag[NJ][2];
            int lrow = lane & 15, lcol = (lane >> 4) * 8;
#pragma unroll
            for (int mi = 0; mi < MI; mi++) {
                uint32_t addr = sA + buf * sAsz +
                    ((MI * 16 * wm + 16 * mi + lrow) * APADE + ks4 * 16 + lcol) * 2;
                ldsm_x4(afrag[mi][0], afrag[mi][1], afrag[mi][2], afrag[mi][3], addr);
            }
#pragma unroll
            for (int nj2 = 0; nj2 < NJ / 2; nj2++) {
                uint32_t addr = sB + buf * sBsz +
                    ((ks4 * 16 + lrow) * BP + (8 * NJ) * wn + 16 * nj2 + lcol) * 2;
                uint32_t r0, r1, r2, r3;
                ldsm_x4_t(r0, r1, r2, r3, addr);
                bfrag[2 * nj2][0] = r0;     bfrag[2 * nj2][1] = r1;
                bfrag[2 * nj2 + 1][0] = r2; bfrag[2 * nj2 + 1][1] = r3;
            }
#pragma unroll
            for (int mi = 0; mi < MI; mi++)
#pragma unroll
                for (int nj = 0; nj < NJ; nj++)
                    mma16816(acc[mi][nj], afrag[mi], bfrag[nj]);
        }
        __syncthreads();
    }

    const float* Ad = (addend && ks == 0) ? (addend + (long)b * strideAdd) : nullptr;
    const float* bz = (ks == 0) ? bias : nullptr;
    int g = lane >> 2, tg = lane & 3;

    if (mode == 2) {
        // two-plane bf16 output + relu (hi at row, lo at planeC offset)
        bf16* C2 = (bf16*)Cv + (long)b * strideC;
#pragma unroll
        for (int mi = 0; mi < MI; mi++) {
            int row0 = bm + MI * 16 * wm + 16 * mi + g;
            int row1 = row0 + 8;
            float bv0 = bz ? bz[row0] : 0.f;
            float bv1 = bz ? bz[row1] : 0.f;
#pragma unroll
            for (int nj = 0; nj < NJ; nj++) {
                int col = bn + (8 * NJ) * wn + 8 * nj + 2 * tg;
#pragma unroll
                for (int half = 0; half < 2; half++) {
                    int row = half ? row1 : row0;
                    float bv = half ? bv1 : bv0;
                    float v0 = fmaxf(acc[mi][nj][2 * half]     + bv, 0.f);
                    float v1 = fmaxf(acc[mi][nj][2 * half + 1] + bv, 0.f);
                    bf16 h0, l0, h1, l1;
                    split_bf16(v0, h0, l0);
                    split_bf16(v1, h1, l1);
                    long base = (long)row * ldn + col;
                    C2[base]              = h0; C2[base + 1]              = h1;
                    C2[planeC + base]     = l0; C2[planeC + base + 1]     = l1;
                }
            }
        }
        return;
    }

    float* Cb = (float*)Cv + (long)b * strideC + (long)ks * strideCk;
#pragma unroll
    for (int mi = 0; mi < MI; mi++) {
        int row0 = bm + MI * 16 * wm + 16 * mi + g;
        int row1 = row0 + 8;
        float bv0 = bz ? bz[row0] : 0.f;
        float bv1 = bz ? bz[row1] : 0.f;
#pragma unroll
        for (int nj = 0; nj < NJ; nj++) {
            int col = bn + (8 * NJ) * wn + 8 * nj + 2 * tg;
            float v00 = acc[mi][nj][0] + bv0;
            float v01 = acc[mi][nj][1] + bv0;
            float v10 = acc[mi][nj][2] + bv1;
            float v11 = acc[mi][nj][3] + bv1;
            if (Ad) {
                v00 += Ad[(long)row0 * ldn + col];
                v01 += Ad[(long)row0 * ldn + col + 1];
                v10 += Ad[(long)row1 * ldn + col];
                v11 += Ad[(long)row1 * ldn + col + 1];
            }
            if (mode == 1) {
                v00 = fmaxf(v00, 0.f); v01 = fmaxf(v01, 0.f);
                v10 = fmaxf(v10, 0.f); v11 = fmaxf(v11, 0.f);
            }
            Cb[(long)row0 * ldn + col]     = v00;
            Cb[(long)row0 * ldn + col + 1] = v01;
            Cb[(long)row1 * ldn + col]     = v10;
            Cb[(long)row1 * ldn + col + 1] = v11;
        }
    }
}

// ---------------- tiled banded attention: 32-query blocks --------------------
// K stays [jj][d]; V staged [d][jj] via cp.async16; Ps stride 68, float4 AV.
// Chunk base jb = i0 + 256 + 64c (16B aligned); t = 64c + jj - qi - 1.
#define AT_SMEM ((32*68 + 32*258 + 64*68*2 + 32*68 + 256 + 32) * 4)

__global__ __launch_bounds__(256)
void attn_tiled_kernel(const float* __restrict__ wheads,
                       const float* __restrict__ BDg,
                       const float* __restrict__ rwb,
                       bf16*        __restrict__ avec2)
{
    extern __shared__ float sm[];
    float* qw   = sm;                        // [q][d]   stride 68
    float* BDs  = qw + 32 * 68;              // [q][t]   stride 258
    float* Ks   = BDs + 32 * 258;            // [jj][d]  stride 68
    float* Vs   = Ks + 64 * 68;              // [d][jj]  stride 68
    float* Ps   = Vs + 64 * 68;              // [q][jj]  stride 68
    float* red  = Ps + 32 * 68;              // [8][32]
    float* sinv = red + 256;                 // [32]

    const int i0 = blockIdx.x * 32;
    const int h  = blockIdx.y;
    const int b  = blockIdx.z;
    const int tid = threadIdx.x;

    const float* W  = wheads + (long)b * (3 * D_MODEL) * KLEN;
    const float* Qg = W + (long)(h * DHEAD) * KLEN;
    const float* Kg = W + (long)(D_MODEL + h * DHEAD) * KLEN;
    const float* Vg = W + (long)(2 * D_MODEL + h * DHEAD) * KLEN;

    for (int idx = tid; idx < 32 * 64; idx += 256) {
        int d = idx >> 5, q = idx & 31;
        qw[q * 68 + d] = Qg[(long)d * KLEN + MLEN + i0 + q] + rwb[h * DHEAD + d];
    }
    {
        const float* BDh = BDg + (long)h * 256 * (BSZ * QLEN) + b * QLEN + i0;
        for (int idx = tid; idx < 32 * 256; idx += 256) {
            int q = idx & 31, t = idx >> 5;
            BDs[q * 258 + t] = BDh[(long)t * (BSZ * QLEN) + q];
        }
    }
    __syncthreads();

    const int qi = tid & 31;
    const int jg = tid >> 5;
    uint32_t VsAddr = (uint32_t)__cvta_generic_to_shared(Vs);
    float O[8];
#pragma unroll
    for (int u = 0; u < 8; u++) O[u] = 0.f;
    float sume = 0.f;

    for (int c = 0; c < 5; c++) {
        int jbase = i0 + 256 + 64 * c;       // 16B-aligned global j base
        if (c > 0) __syncthreads();
        // V: [d][jj] via cp.async16 (4 j's per chunk)
        for (int idx = tid; idx < 64 * 16; idx += 256) {
            int d = idx >> 4, jj0 = (idx & 15) * 4;
            int jg0 = jbase + jj0;
            uint32_t dst = VsAddr + (d * 68 + jj0) * 4;
            if (jg0 + 3 < KLEN) {
                cp_async16(dst, Vg + (long)d * KLEN + jg0);
            } else {
                float4 z = make_float4(0.f, 0.f, 0.f, 0.f);
                if (jg0 + 0 < KLEN) z.x = Vg[(long)d * KLEN + jg0];
                if (jg0 + 1 < KLEN) z.y = Vg[(long)d * KLEN + jg0 + 1];
                if (jg0 + 2 < KLEN) z.z = Vg[(long)d * KLEN + jg0 + 2];
                if (jg0 + 3 < KLEN) z.w = Vg[(long)d * KLEN + jg0 + 3];
                *(float4*)(Vs + d * 68 + jj0) = z;
            }
        }
        cp_commit();
        // K: [jj][d] per-element
        for (int idx = tid; idx < 64 * 64; idx += 256) {
            int d = idx >> 6, jj = idx & 63;
            int jglob = jbase + jj;
            Ks[jj * 68 + d] = (jglob < KLEN) ? Kg[(long)d * KLEN + jglob] : 0.f;
        }
        cp_wait_all();
        __syncthreads();

        // QK scores: 8 j's per thread, float4 over d
        {
            float acc[8];
#pragma unroll
            for (int u = 0; u < 8; u++) acc[u] = 0.f;
            for (int d4 = 0; d4 < 16; d4++) {
                float4 qv4 = *(const float4*)(qw + qi * 68 + d4 * 4);
#pragma unroll
                for (int u = 0; u < 8; u++) {
                    float4 k4 = *(const float4*)(Ks + (jg * 8 + u) * 68 + d4 * 4);
                    acc[u] = fmaf(qv4.x, k4.x, acc[u]);
                    acc[u] = fmaf(qv4.y, k4.y, acc[u]);
                    acc[u] = fmaf(qv4.z, k4.z, acc[u]);
                    acc[u] = fmaf(qv4.w, k4.w, acc[u]);
                }
            }
#pragma unroll
            for (int u = 0; u < 8; u++) {
                int jj = jg * 8 + u;
                int t  = 64 * c + jj - qi - 1;
                float pv = 0.f;
                if (t >= 0 && t < 256)
                    pv = __expf((acc[u] + BDs[qi * 258 + t]) * 0.125f);
                sume += pv;
                Ps[qi * 68 + jj] = pv;
            }
        }
        __syncthreads();

        // AV: float4 Ps x uniform float4 Vs
        for (int js = 0; js < 16; js++) {
            int jj0 = js * 4;
            float4 p4 = *(const float4*)(Ps + qi * 68 + jj0);
#pragma unroll
            for (int u = 0; u < 8; u++) {
                float4 v4 = *(const float4*)(Vs + (jg * 8 + u) * 68 + jj0);
                O[u] = fmaf(p4.x, v4.x, O[u]);
                O[u] = fmaf(p4.y, v4.y, O[u]);
                O[u] = fmaf(p4.z, v4.z, O[u]);
                O[u] = fmaf(p4.w, v4.w, O[u]);
            }
        }
    }

    red[jg * 32 + qi] = sume;
    __syncthreads();
    if (tid < 32) {
        float s = 0.f;
#pragma unroll
        for (int g8 = 0; g8 < 8; g8++) s += red[g8 * 32 + tid];
        sinv[tid] = 1.f / s;
    }
    __syncthreads();
    float inv = sinv[qi];
    bf16* outp = avec2 + (long)b * 2 * D_MODEL * QLEN;
#pragma unroll
    for (int u = 0; u < 8; u++) {
        int dp = h * DHEAD + jg * 8 + u;
        float v = O[u] * inv;
        bf16 hi, lo; split_bf16(v, hi, lo);
        long base = (long)dp * QLEN + i0 + qi;
        outp[base]                          = hi;
        outp[(long)D_MODEL * QLEN + base]   = lo;
    }
}

// ---------------- channel LayerNorm (optional 2nd input, 2-plane split) ------
__global__ __launch_bounds__(256)
void ln_kernel(const float* __restrict__ ya, const float* __restrict__ yb,
               float* __restrict__ out, bf16* __restrict__ out2)
{
    int b  = blockIdx.y;
    int t0 = blockIdx.x * 32;
    int tid = threadIdx.x;
    int tt = tid & 31, cg = tid >> 5;
    const float* Ya = ya + (long)b * D_MODEL * QLEN;
    const float* Yb = yb ? (yb + (long)b * D_MODEL * QLEN) : nullptr;

    float s = 0.f, s2 = 0.f;
    for (int c = cg * 128; c < cg * 128 + 128; c++) {
        long idx = (long)c * QLEN + t0 + tt;
        float v = Ya[idx] + (Yb ? Yb[idx] : 0.f);
        s += v; s2 += v * v;
    }
    __shared__ float ssum[8][32], ssq[8][32];
    __shared__ float smean[32], srstd[32];
    ssum[cg][tt] = s; ssq[cg][tt] = s2;
    __syncthreads();
    if (tid < 32) {
        float ts = 0.f, ts2 = 0.f;
#pragma unroll
        for (int g = 0; g < 8; g++) { ts += ssum[g][tid]; ts2 += ssq[g][tid]; }
        float mean = ts * (1.0f / D_MODEL);
        float var  = ts2 * (1.0f / D_MODEL) - mean * mean;
        smean[tid] = mean;
        srstd[tid] = rsqrtf(var + 1e-5f);
    }
    __syncthreads();
    float mean = smean[tt], rstd = srstd[tt];
    float* O = out + (long)b * D_MODEL * QLEN;
    bf16* O2 = out2 ? (out2 + (long)b * 2 * D_MODEL * QLEN) : nullptr;
    for (int c = cg * 128; c < cg * 128 + 128; c++) {
        long idx = (long)c * QLEN + t0 + tt;
        float v = Ya[idx] + (Yb ? Yb[idx] : 0.f);
        float r = (v - mean) * rstd;
        O[idx] = r;
        if (O2) {
            bf16 hi, lo; split_bf16(r, hi, lo);
            O2[idx]                          = hi;
            O2[(long)D_MODEL * QLEN + idx]   = lo;
        }
    }
}

// ---------------- launcher ---------------------------------------------------
#define GSMEM44 ((2 * 128 * APADE + 2 * 64 * 136) * 2)    // 71680 (MI=4, NJ=4)

extern "C" void kernel_launch(void* const* d_in, const int* in_sizes, int n_in,
                              void* d_out, int out_size)
{
    const float* z1ss    = (const float*)d_in[0];
    const float* uss     = (const float*)d_in[1];
    const float* z0      = (const float*)d_in[2];
    const float* pos_emb = (const float*)d_in[3];
    const float* qkv_w   = (const float*)d_in[4];
    const float* r_w     = (const float*)d_in[5];
    const float* r_w_bias= (const float*)d_in[6];
    const float* r_r_bias= (const float*)d_in[7];
    const float* o_w     = (const float*)d_in[8];
    const float* o_b     = (const float*)d_in[9];
    const float* ff1_w   = (const float*)d_in[10];
    const float* ff1_b   = (const float*)d_in[11];
    const float* ff2_w   = (const float*)d_in[12];
    const float* ff2_b   = (const float*)d_in[13];
    float* out = (float*)d_out;

    float *wheads, *rkp, *x, *tmp2, *BDg;
    bf16 *qkvw2, *rw2, *ow2, *ff1w2, *ff2w2, *pos2, *cat2, *avec2, *x2, *h2, *rA2, *qr2;
    cudaGetSymbolAddress((void**)&wheads, g_wheads);
    cudaGetSymbolAddress((void**)&rkp,    g_rkp);
    cudaGetSymbolAddress((void**)&x,      g_x);
    cudaGetSymbolAddress((void**)&tmp2,   g_tmp2);
    cudaGetSymbolAddress((void**)&BDg,    g_BD);
    cudaGetSymbolAddress((void**)&qkvw2,  g_qkvw2);
    cudaGetSymbolAddress((void**)&rw2,    g_rw2);
    cudaGetSymbolAddress((void**)&ow2,    g_ow2);
    cudaGetSymbolAddress((void**)&ff1w2,  g_ff1w2);
    cudaGetSymbolAddress((void**)&ff2w2,  g_ff2w2);
    cudaGetSymbolAddress((void**)&pos2,   g_pos2);
    cudaGetSymbolAddress((void**)&cat2,   g_cat2);
    cudaGetSymbolAddress((void**)&avec2,  g_avec2);
    cudaGetSymbolAddress((void**)&x2,     g_x2);
    cudaGetSymbolAddress((void**)&h2,     g_h2);
    cudaGetSymbolAddress((void**)&rA2,    g_rA2);
    cudaGetSymbolAddress((void**)&qr2,    g_qr2);

    cudaFuncSetAttribute(attn_tiled_kernel,
                         cudaFuncAttributeMaxDynamicSharedMemorySize, AT_SMEM);
    cudaFuncSetAttribute(gemm_bf16_kernel<4, 4>,
                         cudaFuncAttributeMaxDynamicSharedMemorySize, GSMEM44);

    const long s3dk = (long)3 * D_MODEL * KLEN;   // wheads batch stride
    const long s2dk = (long)2 * D_MODEL * KLEN;   // cat2 batch stride
    const long s2dq = (long)2 * D_MODEL * QLEN;
    const long s2iq = (long)2 * DINNER * QLEN;
    const long sdq  = (long)D_MODEL * QLEN;
    const long sDK  = (long)D_MODEL * KLEN;
    const int  NB   = BSZ * QLEN;

    // [1] weight expansions (two-plane)
    expand_weights_kernel<<<13312, 128>>>(qkv_w, r_w, o_w, ff1_w, ff2_w,
                                          qkvw2, rw2, ow2, ff1w2, ff2w2);
    // [2] cat expansion (cols [256,1024))
    expand_cat_kernel<<<dim3(3, D_MODEL, BSZ), 256>>>(z0, z1ss, 256);
    // [3] pos expansion (cols [768,1024))
    expandB_kernel<<<dim3(1, D_MODEL, 1), 256>>>(pos_emb, pos2, KLEN, 768, D_MODEL, 0, 0);

    // [4] QKV: tile list, 512 CTAs; Kps=Kp=1024
    gemm_bf16_kernel<4, 4><<<dim3(128, 1, BSZ), 256, GSMEM44>>>(
        qkvw2, cat2 + 256, wheads + 256, nullptr, uss + 256,
        1024, 1024, KLEN, 0, s2dk, s3dk, s3dk, 0, 0, 0, 0, 1);

    // [5] r_head_k: K-split x8 -> 128 CTAs; Kps=128, Kp=1024
    gemm_bf16_kernel<4, 4><<<dim3(2, 8, 8), 256, GSMEM44>>>(
        rw2, pos2 + 768, rkp + 768, nullptr, nullptr,
        128, 1024, KLEN, 0, 0, 0, 0, sDK, 0, 3, 0, 0);

    // [6] reduce rk partials
    reduce_rk_kernel<<<256, 256>>>(rkp);

    // [7] rA2 expansion
    expand_rA_kernel<<<dim3(16, NHEAD), 256>>>(rkp, rA2);
    // [8] qr2 expansion
    expand_qr_kernel<<<dim3(QLEN / 256, DHEAD, BSZ * NHEAD), 256>>>(
        wheads, r_r_bias, qr2);

    // [9] BD GEMM: per head, 256 x 2048, Kps=Kp=64 -> 512 CTAs
    gemm_bf16_kernel<4, 4><<<dim3(16, 2, NHEAD), 256, GSMEM44>>>(
        rA2, qr2, BDg, nullptr, nullptr,
        64, 64, NB, (long)256 * 128, (long)128 * NB, (long)256 * NB,
        0, 0, 0, 0, 0, 0);

    // [10] banded attention -> avec2
    attn_tiled_kernel<<<dim3(QLEN / 32, NHEAD, BSZ), 256, AT_SMEM>>>(
        wheads, BDg, r_w_bias, avec2);

    // [11] O-proj: K-split x2 -> 256 CTAs; Kps=512, Kp=1024
    gemm_bf16_kernel<4, 4><<<dim3(4, 8, 2 * BSZ), 256, GSMEM44>>>(
        ow2, avec2, tmp2, o_b, z1ss,
        512, 1024, QLEN, 0, s2dq, sdq, sdq, (long)BSZ * sdq, 0, 1, 0, 0);

    // [12] x = LN(sum of halves), fused x2
    ln_kernel<<<dim3(QLEN / 32, BSZ), 256>>>(tmp2, tmp2 + (long)BSZ * sdq, x, x2);

    // [13] FF1: 512 CTAs, two-plane relu epilogue; Kps=Kp=1024
    gemm_bf16_kernel<4, 4><<<dim3(4, 32, BSZ), 256, GSMEM44>>>(
        ff1w2, x2, h2, ff1_b, nullptr,
        1024, 1024, QLEN, 0, s2dq, s2iq, 0, 0, (long)DINNER * QLEN, 0, 2, 0);

    // [14] FF2: K-split x2 -> 256 CTAs; Kps=2048, Kp=4096
    gemm_bf16_kernel<4, 4><<<dim3(4, 8, 2 * BSZ), 256, GSMEM44>>>(
        ff2w2, h2, tmp2, ff2_b, x,
        2048, 4096, QLEN, 0, s2iq, sdq, sdq, (long)BSZ * sdq, 0, 1, 0, 0);

    // [15] out = LN(sum of halves)
    ln_kernel<<<dim3(QLEN / 32, BSZ), 256>>>(tmp2, tmp2 + (long)BSZ * sdq, out, nullptr);
}

// round 15
// speedup vs baseline: 1.1847x; 1.0273x over previous
#include <cuda_runtime.h>
#include <cuda_bf16.h>
#include <cstdint>

#define BSZ     4
#define D_MODEL 1024
#define QLEN    512
#define MLEN    512
#define KLEN    1024
#define NHEAD   16
#define DHEAD   64
#define DINNER  4096

typedef __nv_bfloat16 bf16;

// ---------------- fp32 scratch ----------------------------------------------
__device__ float g_wheads[BSZ * 3 * D_MODEL * KLEN];
__device__ float g_rkp[8 * D_MODEL * KLEN];          // 8 K-split partial planes
__device__ float g_x[BSZ * D_MODEL * QLEN];
__device__ float g_tmp2[2 * BSZ * D_MODEL * QLEN];   // K-split halves
__device__ float g_BD[NHEAD * 256 * (BSZ * QLEN)];   // BD[h][t][b*512+i]

// ---------------- two-plane bf16 split scratch ([hi | lo]) -------------------
__device__ bf16 g_qkvw2[3 * D_MODEL * 2 * D_MODEL];
__device__ bf16 g_rw2  [D_MODEL * 2 * D_MODEL];
__device__ bf16 g_ow2  [D_MODEL * 2 * D_MODEL];
__device__ bf16 g_ff1w2[DINNER * 2 * D_MODEL];
__device__ bf16 g_ff2w2[D_MODEL * 2 * DINNER];
__device__ bf16 g_pos2 [2 * D_MODEL * KLEN];
__device__ bf16 g_cat2 [BSZ * 2 * D_MODEL * KLEN];
__device__ bf16 g_avec2[BSZ * 2 * D_MODEL * QLEN];
__device__ bf16 g_x2   [BSZ * 2 * D_MODEL * QLEN];
__device__ bf16 g_h2   [BSZ * 2 * DINNER * QLEN];
__device__ bf16 g_rA2  [NHEAD * 256 * 128];
__device__ bf16 g_qr2  [NHEAD * 128 * (BSZ * QLEN)];

// ---------------- helpers ----------------------------------------------------
__device__ __forceinline__ void split_bf16(float x, bf16& hi, bf16& lo)
{
    hi = __float2bfloat16(x);
    lo = __float2bfloat16(x - __bfloat162float(hi));
}

__device__ __forceinline__ void cp_async16(uint32_t smem_dst, const void* gmem_src)
{
    asm volatile("cp.async.cg.shared.global [%0], [%1], 16;\n"
                 :: "r"(smem_dst), "l"(gmem_src));
}
__device__ __forceinline__ void cp_commit()
{
    asm volatile("cp.async.commit_group;\n");
}
__device__ __forceinline__ void cp_wait_all()
{
    asm volatile("cp.async.wait_group 0;\n");
}
__device__ __forceinline__ void ldsm_x4(uint32_t& r0, uint32_t& r1, uint32_t& r2, uint32_t& r3, uint32_t addr)
{
    asm volatile("ldmatrix.sync.aligned.m8n8.x4.shared.b16 {%0,%1,%2,%3}, [%4];\n"
                 : "=r"(r0), "=r"(r1), "=r"(r2), "=r"(r3) : "r"(addr));
}
__device__ __forceinline__ void ldsm_x4_t(uint32_t& r0, uint32_t& r1, uint32_t& r2, uint32_t& r3, uint32_t addr)
{
    asm volatile("ldmatrix.sync.aligned.m8n8.x4.trans.shared.b16 {%0,%1,%2,%3}, [%4];\n"
                 : "=r"(r0), "=r"(r1), "=r"(r2), "=r"(r3) : "r"(addr));
}
__device__ __forceinline__ void mma16816(float* c, const uint32_t* a, const uint32_t* b)
{
    asm volatile(
        "mma.sync.aligned.m16n8k16.row.col.f32.bf16.bf16.f32 "
        "{%0,%1,%2,%3}, {%4,%5,%6,%7}, {%8,%9}, {%0,%1,%2,%3};\n"
        : "+f"(c[0]), "+f"(c[1]), "+f"(c[2]), "+f"(c[3])
        : "r"(a[0]), "r"(a[1]), "r"(a[2]), "r"(a[3]), "r"(b[0]), "r"(b[1]));
}

// ---------------- expansion kernels (two-plane) -------------------------------
__global__ void expand_weights_kernel(const float* __restrict__ qkv_w,
                                      const float* __restrict__ r_w,
                                      const float* __restrict__ o_w,
                                      const float* __restrict__ ff1_w,
                                      const float* __restrict__ ff2_w,
                                      bf16* qkvw2, bf16* rw2, bf16* ow2,
                                      bf16* ff1w2, bf16* ff2w2)
{
    int cid = blockIdx.x;
    const float* in; bf16* out; int K; int row; int kc;
    if (cid < 3072)       { in = qkv_w; out = qkvw2; K = 1024; row = cid;        kc = 0; }
    else if (cid < 4096)  { in = r_w;   out = rw2;   K = 1024; row = cid - 3072; kc = 0; }
    else if (cid < 5120)  { in = o_w;   out = ow2;   K = 1024; row = cid - 4096; kc = 0; }
    else if (cid < 9216)  { in = ff1_w; out = ff1w2; K = 1024; row = cid - 5120; kc = 0; }
    else { int c = cid - 9216; in = ff2_w; out = ff2w2; K = 4096; row = c >> 2; kc = c & 3; }

    int k0 = (kc * 128 + threadIdx.x) * 8;
    const float4* ip = (const float4*)(in + (long)row * K + k0);
    float4 f0 = ip[0], f1 = ip[1];
    float v[8] = {f0.x, f0.y, f0.z, f0.w, f1.x, f1.y, f1.z, f1.w};
    unsigned short sh[8], sl[8];
#pragma unroll
    for (int j = 0; j < 8; j++) {
        bf16 hi, lo; split_bf16(v[j], hi, lo);
        sh[j] = __bfloat16_as_ushort(hi);
        sl[j] = __bfloat16_as_ushort(lo);
    }
    uint32_t wh[4], wl[4];
#pragma unroll
    for (int i = 0; i < 4; i++) {
        wh[i] = (uint32_t)sh[2 * i] | ((uint32_t)sh[2 * i + 1] << 16);
        wl[i] = (uint32_t)sl[2 * i] | ((uint32_t)sl[2 * i + 1] << 16);
    }
    bf16* orow = out + (long)row * 2 * K;
    *(uint4*)(orow + k0)     = make_uint4(wh[0], wh[1], wh[2], wh[3]);
    *(uint4*)(orow + K + k0) = make_uint4(wl[0], wl[1], wl[2], wl[3]);
}

// B-operand two-plane: hi row k, lo row Kp+k
__global__ void expandB_kernel(const float* __restrict__ in, bf16* __restrict__ out,
                               int ldn, int n0, int Kp, long sIn, long sOut)
{
    int n = n0 + blockIdx.x * 256 + threadIdx.x;
    int k = blockIdx.y;
    float x = in[(long)blockIdx.z * sIn + (long)k * ldn + n];
    bf16 hi, lo; split_bf16(x, hi, lo);
    bf16* o = out + (long)blockIdx.z * sOut + (long)k * ldn + n;
    o[0] = hi;
    o[(long)Kp * ldn] = lo;
}

__global__ void expand_cat_kernel(const float* __restrict__ z0, const float* __restrict__ z1ss,
                                  int t0base)
{
    int t = t0base + blockIdx.x * 256 + threadIdx.x;
    int d = blockIdx.y;
    int b = blockIdx.z;
    float x = (t < MLEN) ? z0[((long)b * D_MODEL + d) * MLEN + t]
                         : z1ss[((long)b * D_MODEL + d) * QLEN + (t - MLEN)];
    bf16 hi, lo; split_bf16(x, hi, lo);
    bf16* o = g_cat2 + (long)b * 2 * D_MODEL * KLEN + (long)d * KLEN + t;
    o[0] = hi;
    o[(long)D_MODEL * KLEN] = lo;
}

__global__ void reduce_rk_kernel(float* __restrict__ rkp)
{
    const long DK = (long)D_MODEL * KLEN;
    int idx = blockIdx.x * 256 + threadIdx.x;
    int row = idx >> 6;
    int t4  = (idx & 63) * 4;
    long base = (long)row * KLEN + 768 + t4;
    float4 a = *(const float4*)(rkp + base);
#pragma unroll
    for (int p = 1; p < 8; p++) {
        float4 q = *(const float4*)(rkp + p * DK + base);
        a.x += q.x; a.y += q.y; a.z += q.z; a.w += q.w;
    }
    *(float4*)(rkp + base) = a;
}

// rA2[h][t][0..64)=hi, [64..128)=lo of rk[h*64+d][768+t]
__global__ void expand_rA_kernel(const float* __restrict__ rkp, bf16* __restrict__ rA2)
{
    int h = blockIdx.y;
    int t = blockIdx.x * 16 + (threadIdx.x >> 4);
    int d0 = (threadIdx.x & 15) * 4;
    bf16* op = rA2 + ((long)h * 256 + t) * 128 + d0;
#pragma unroll
    for (int dd = 0; dd < 4; dd++) {
        int d = d0 + dd;
        float v = rkp[(long)(h * DHEAD + d) * KLEN + 768 + t];
        bf16 hi, lo; split_bf16(v, hi, lo);
        op[dd] = hi; op[64 + dd] = lo;
    }
}

// qr2[h][d][b*512+i]=hi, [64+d]=lo of (Q + rrb)
__global__ void expand_qr_kernel(const float* __restrict__ wheads,
                                 const float* __restrict__ rrb,
                                 bf16* __restrict__ qr2)
{
    int i = blockIdx.x * 256 + threadIdx.x;
    int d = blockIdx.y;
    int b = blockIdx.z & 3, h = blockIdx.z >> 2;
    float v = wheads[(long)b * 3 * D_MODEL * KLEN + (long)(h * DHEAD + d) * KLEN
                     + MLEN + i] + rrb[h * DHEAD + d];
    bf16 hi, lo; split_bf16(v, hi, lo);
    const int NB = BSZ * QLEN;
    bf16* o = qr2 + (long)h * 128 * NB + (long)d * NB + b * QLEN + i;
    o[0] = hi;
    o[64 * NB] = lo;
}

// ---------------- tensor-core GEMM, two-plane 3-term mapping ------------------
// Iteration space: 3 parts x Kps. part0: hiA*hiB, part1: hiA*loB, part2: loA*hiB.
// (part, kk) carried incrementally by the caller loop — NO division in the
// load path (the R14 IDIV regression fix).
#define APADE 72

template<int MI, int NJ>
__global__ __launch_bounds__(256, 2)
void gemm_bf16_kernel(const bf16* __restrict__ A,
                      const bf16* __restrict__ B,
                      void*       __restrict__ Cv,
                      const float* __restrict__ bias,
                      const float* __restrict__ addend,
                      int Kps, int Kp, int ldn,
                      long strideA, long strideB, long strideC,
                      long strideAdd, long strideCk, long planeC,
                      int zshift, int mode, int tilemap)
{
    constexpr int GBMt = 32 * MI;
    constexpr int GBN  = 32 * NJ;
    constexpr int BP   = GBN + 8;
    constexpr int BCH  = GBN / 8;
    constexpr int BSH  = (NJ == 4 ? 4 : 5);

    extern __shared__ bf16 smem_g[];
    bf16* Asm = smem_g;
    bf16* Bsm = smem_g + 2 * GBMt * APADE;

    const int tid  = threadIdx.x;
    const int lane = tid & 31;
    const int warp = tid >> 5;
    const int wm = warp >> 2;
    const int wn = warp & 3;

    int bxi = blockIdx.x, byi = blockIdx.y;
    if (tilemap) {
        int f = blockIdx.x;
        if (f < 96) { byi = 8 + f / 6; bxi = f % 6; }
        else        { int gq = f - 96; byi = gq >> 2; bxi = 2 + (gq & 3); }
    }
    const int bn = bxi * GBN;
    const int bm = byi * GBMt;
    const int b  = blockIdx.z >> zshift;
    const int ks = blockIdx.z & ((1 << zshift) - 1);
    const int ldk = 2 * Kp;

    const bf16* Ag = A + (long)b * strideA + (long)bm * ldk + (long)ks * Kps;
    const bf16* Bg = B + (long)b * strideB + (long)ks * Kps * ldn;

    uint32_t sA = (uint32_t)__cvta_generic_to_shared(Asm);
    uint32_t sB = (uint32_t)__cvta_generic_to_shared(Bsm);
    const uint32_t sAsz = GBMt * APADE * 2;
    const uint32_t sBsz = 64 * BP * 2;

    float acc[MI][NJ][4];
#pragma unroll
    for (int i = 0; i < MI; i++)
#pragma unroll
        for (int j = 0; j < NJ; j++)
#pragma unroll
            for (int r = 0; r < 4; r++) acc[i][j][r] = 0.f;

    // load one 64-K stage; offsets precomputed by caller (no division)
    auto load_tiles = [&](int buf, long aoff, long boff) {
#pragma unroll
        for (int i = 0; i < MI; i++) {
            int c   = tid + 256 * i;
            int row = c >> 3, ch = c & 7;
            cp_async16(sA + buf * sAsz + (row * APADE + ch * 8) * 2,
                       Ag + (long)row * ldk + aoff + ch * 8);
        }
#pragma unroll
        for (int i = 0; i < (64 * BCH) / 256; i++) {
            int c   = tid + 256 * i;
            int row = c >> BSH, ch = c & (BCH - 1);
            cp_async16(sB + buf * sBsz + (row * BP + ch * 8) * 2,
                       Bg + (boff + row) * ldn + bn + ch * 8);
        }
        cp_commit();
    };

    // incremental (part, kk) state for the NEXT stage to load
    // part0: A+0,B+0; part1: A+0,B+Kp; part2: A+Kp,B+0  (relative to ks base)
    int part = 0, kk = 0;
    auto cur_aoff = [&]() -> long { return (part < 2 ? 0L : (long)Kp) + kk; };
    auto cur_boff = [&]() -> long { return (part == 1 ? (long)Kp : 0L) + kk; };
    auto advance  = [&]() { kk += 64; if (kk == Kps) { kk = 0; part++; } };

    load_tiles(0, cur_aoff(), cur_boff());
    advance();

    const int nIter = (3 * Kps) >> 6;
    for (int it = 0; it < nIter; it++) {
        int buf = it & 1;
        cp_wait_all();
        __syncthreads();
        if (it + 1 < nIter) {
            load_tiles(buf ^ 1, cur_aoff(), cur_boff());
            advance();
        }

#pragma unroll
        for (int ks4 = 0; ks4 < 4; ks4++) {
            uint32_t afrag[MI][4];
            uint32_t bfrag[NJ][2];
            int lrow = lane & 15, lcol = (lane >> 4) * 8;
#pragma unroll
            for (int mi = 0; mi < MI; mi++) {
                uint32_t addr = sA + buf * sAsz +
                    ((MI * 16 * wm + 16 * mi + lrow) * APADE + ks4 * 16 + lcol) * 2;
                ldsm_x4(afrag[mi][0], afrag[mi][1], afrag[mi][2], afrag[mi][3], addr);
            }
#pragma unroll
            for (int nj2 = 0; nj2 < NJ / 2; nj2++) {
                uint32_t addr = sB + buf * sBsz +
                    ((ks4 * 16 + lrow) * BP + (8 * NJ) * wn + 16 * nj2 + lcol) * 2;
                uint32_t r0, r1, r2, r3;
                ldsm_x4_t(r0, r1, r2, r3, addr);
                bfrag[2 * nj2][0] = r0;     bfrag[2 * nj2][1] = r1;
                bfrag[2 * nj2 + 1][0] = r2; bfrag[2 * nj2 + 1][1] = r3;
            }
#pragma unroll
            for (int mi = 0; mi < MI; mi++)
#pragma unroll
                for (int nj = 0; nj < NJ; nj++)
                    mma16816(acc[mi][nj], afrag[mi], bfrag[nj]);
        }
        __syncthreads();
    }

    const float* Ad = (addend && ks == 0) ? (addend + (long)b * strideAdd) : nullptr;
    const float* bz = (ks == 0) ? bias : nullptr;
    int g = lane >> 2, tg = lane & 3;

    if (mode == 2) {
        bf16* C2 = (bf16*)Cv + (long)b * strideC;
#pragma unroll
        for (int mi = 0; mi < MI; mi++) {
            int row0 = bm + MI * 16 * wm + 16 * mi + g;
            int row1 = row0 + 8;
            float bv0 = bz ? bz[row0] : 0.f;
            float bv1 = bz ? bz[row1] : 0.f;
#pragma unroll
            for (int nj = 0; nj < NJ; nj++) {
                int col = bn + (8 * NJ) * wn + 8 * nj + 2 * tg;
#pragma unroll
                for (int half = 0; half < 2; half++) {
                    int row = half ? row1 : row0;
                    float bv = half ? bv1 : bv0;
                    float v0 = fmaxf(acc[mi][nj][2 * half]     + bv, 0.f);
                    float v1 = fmaxf(acc[mi][nj][2 * half + 1] + bv, 0.f);
                    bf16 h0, l0, h1, l1;
                    split_bf16(v0, h0, l0);
                    split_bf16(v1, h1, l1);
                    long base = (long)row * ldn + col;
                    C2[base]              = h0; C2[base + 1]              = h1;
                    C2[planeC + base]     = l0; C2[planeC + base + 1]     = l1;
                }
            }
        }
        return;
    }

    float* Cb = (float*)Cv + (long)b * strideC + (long)ks * strideCk;
#pragma unroll
    for (int mi = 0; mi < MI; mi++) {
        int row0 = bm + MI * 16 * wm + 16 * mi + g;
        int row1 = row0 + 8;
        float bv0 = bz ? bz[row0] : 0.f;
        float bv1 = bz ? bz[row1] : 0.f;
#pragma unroll
        for (int nj = 0; nj < NJ; nj++) {
            int col = bn + (8 * NJ) * wn + 8 * nj + 2 * tg;
            float v00 = acc[mi][nj][0] + bv0;
            float v01 = acc[mi][nj][1] + bv0;
            float v10 = acc[mi][nj][2] + bv1;
            float v11 = acc[mi][nj][3] + bv1;
            if (Ad) {
                v00 += Ad[(long)row0 * ldn + col];
                v01 += Ad[(long)row0 * ldn + col + 1];
                v10 += Ad[(long)row1 * ldn + col];
                v11 += Ad[(long)row1 * ldn + col + 1];
            }
            if (mode == 1) {
                v00 = fmaxf(v00, 0.f); v01 = fmaxf(v01, 0.f);
                v10 = fmaxf(v10, 0.f); v11 = fmaxf(v11, 0.f);
            }
            Cb[(long)row0 * ldn + col]     = v00;
            Cb[(long)row0 * ldn + col + 1] = v01;
            Cb[(long)row1 * ldn + col]     = v10;
            Cb[(long)row1 * ldn + col + 1] = v11;
        }
    }
}

// ---------------- tiled banded attention: 32-query blocks --------------------
// K [jj][d]; V staged [d][jj] via cp.async16; Ps stride 68, float4 AV.
// Chunk base jb = i0 + 256 + 64c (16B aligned); t = 64c + jj - qi - 1.
#define AT_SMEM ((32*68 + 32*258 + 64*68*2 + 32*68 + 256 + 32) * 4)

__global__ __launch_bounds__(256)
void attn_tiled_kernel(const float* __restrict__ wheads,
                       const float* __restrict__ BDg,
                       const float* __restrict__ rwb,
                       bf16*        __restrict__ avec2)
{
    extern __shared__ float sm[];
    float* qw   = sm;                        // [q][d]   stride 68
    float* BDs  = qw + 32 * 68;              // [q][t]   stride 258
    float* Ks   = BDs + 32 * 258;            // [jj][d]  stride 68
    float* Vs   = Ks + 64 * 68;              // [d][jj]  stride 68
    float* Ps   = Vs + 64 * 68;              // [q][jj]  stride 68
    float* red  = Ps + 32 * 68;              // [8][32]
    float* sinv = red + 256;                 // [32]

    const int i0 = blockIdx.x * 32;
    const int h  = blockIdx.y;
    const int b  = blockIdx.z;
    const int tid = threadIdx.x;

    const float* W  = wheads + (long)b * (3 * D_MODEL) * KLEN;
    const float* Qg = W + (long)(h * DHEAD) * KLEN;
    const float* Kg = W + (long)(D_MODEL + h * DHEAD) * KLEN;
    const float* Vg = W + (long)(2 * D_MODEL + h * DHEAD) * KLEN;

    for (int idx = tid; idx < 32 * 64; idx += 256) {
        int d = idx >> 5, q = idx & 31;
        qw[q * 68 + d] = Qg[(long)d * KLEN + MLEN + i0 + q] + rwb[h * DHEAD + d];
    }
    {
        const float* BDh = BDg + (long)h * 256 * (BSZ * QLEN) + b * QLEN + i0;
        for (int idx = tid; idx < 32 * 256; idx += 256) {
            int q = idx & 31, t = idx >> 5;
            BDs[q * 258 + t] = BDh[(long)t * (BSZ * QLEN) + q];
        }
    }
    __syncthreads();

    const int qi = tid & 31;
    const int jg = tid >> 5;
    uint32_t VsAddr = (uint32_t)__cvta_generic_to_shared(Vs);
    float O[8];
#pragma unroll
    for (int u = 0; u < 8; u++) O[u] = 0.f;
    float sume = 0.f;

    for (int c = 0; c < 5; c++) {
        int jbase = i0 + 256 + 64 * c;
        if (c > 0) __syncthreads();
        for (int idx = tid; idx < 64 * 16; idx += 256) {
            int d = idx >> 4, jj0 = (idx & 15) * 4;
            int jg0 = jbase + jj0;
            uint32_t dst = VsAddr + (d * 68 + jj0) * 4;
            if (jg0 + 3 < KLEN) {
                cp_async16(dst, Vg + (long)d * KLEN + jg0);
            } else {
                float4 z = make_float4(0.f, 0.f, 0.f, 0.f);
                if (jg0 + 0 < KLEN) z.x = Vg[(long)d * KLEN + jg0];
                if (jg0 + 1 < KLEN) z.y = Vg[(long)d * KLEN + jg0 + 1];
                if (jg0 + 2 < KLEN) z.z = Vg[(long)d * KLEN + jg0 + 2];
                if (jg0 + 3 < KLEN) z.w = Vg[(long)d * KLEN + jg0 + 3];
                *(float4*)(Vs + d * 68 + jj0) = z;
            }
        }
        cp_commit();
        for (int idx = tid; idx < 64 * 64; idx += 256) {
            int d = idx >> 6, jj = idx & 63;
            int jglob = jbase + jj;
            Ks[jj * 68 + d] = (jglob < KLEN) ? Kg[(long)d * KLEN + jglob] : 0.f;
        }
        cp_wait_all();
        __syncthreads();

        {
            float acc[8];
#pragma unroll
            for (int u = 0; u < 8; u++) acc[u] = 0.f;
            for (int d4 = 0; d4 < 16; d4++) {
                float4 qv4 = *(const float4*)(qw + qi * 68 + d4 * 4);
#pragma unroll
                for (int u = 0; u < 8; u++) {
                    float4 k4 = *(const float4*)(Ks + (jg * 8 + u) * 68 + d4 * 4);
                    acc[u] = fmaf(qv4.x, k4.x, acc[u]);
                    acc[u] = fmaf(qv4.y, k4.y, acc[u]);
                    acc[u] = fmaf(qv4.z, k4.z, acc[u]);
                    acc[u] = fmaf(qv4.w, k4.w, acc[u]);
                }
            }
#pragma unroll
            for (int u = 0; u < 8; u++) {
                int jj = jg * 8 + u;
                int t  = 64 * c + jj - qi - 1;
                float pv = 0.f;
                if (t >= 0 && t < 256)
                    pv = __expf((acc[u] + BDs[qi * 258 + t]) * 0.125f);
                sume += pv;
                Ps[qi * 68 + jj] = pv;
            }
        }
        __syncthreads();

        for (int js = 0; js < 16; js++) {
            int jj0 = js * 4;
            float4 p4 = *(const float4*)(Ps + qi * 68 + jj0);
#pragma unroll
            for (int u = 0; u < 8; u++) {
                float4 v4 = *(const float4*)(Vs + (jg * 8 + u) * 68 + jj0);
                O[u] = fmaf(p4.x, v4.x, O[u]);
                O[u] = fmaf(p4.y, v4.y, O[u]);
                O[u] = fmaf(p4.z, v4.z, O[u]);
                O[u] = fmaf(p4.w, v4.w, O[u]);
            }
        }
    }

    red[jg * 32 + qi] = sume;
    __syncthreads();
    if (tid < 32) {
        float s = 0.f;
#pragma unroll
        for (int g8 = 0; g8 < 8; g8++) s += red[g8 * 32 + tid];
        sinv[tid] = 1.f / s;
    }
    __syncthreads();
    float inv = sinv[qi];
    bf16* outp = avec2 + (long)b * 2 * D_MODEL * QLEN;
#pragma unroll
    for (int u = 0; u < 8; u++) {
        int dp = h * DHEAD + jg * 8 + u;
        float v = O[u] * inv;
        bf16 hi, lo; split_bf16(v, hi, lo);
        long base = (long)dp * QLEN + i0 + qi;
        outp[base]                          = hi;
        outp[(long)D_MODEL * QLEN + base]   = lo;
    }
}

// ---------------- channel LayerNorm (optional 2nd input, 2-plane split) ------
__global__ __launch_bounds__(256)
void ln_kernel(const float* __restrict__ ya, const float* __restrict__ yb,
               float* __restrict__ out, bf16* __restrict__ out2)
{
    int b  = blockIdx.y;
    int t0 = blockIdx.x * 32;
    int tid = threadIdx.x;
    int tt = tid & 31, cg = tid >> 5;
    const float* Ya = ya + (long)b * D_MODEL * QLEN;
    const float* Yb = yb ? (yb + (long)b * D_MODEL * QLEN) : nullptr;

    float s = 0.f, s2 = 0.f;
    for (int c = cg * 128; c < cg * 128 + 128; c++) {
        long idx = (long)c * QLEN + t0 + tt;
        float v = Ya[idx] + (Yb ? Yb[idx] : 0.f);
        s += v; s2 += v * v;
    }
    __shared__ float ssum[8][32], ssq[8][32];
    __shared__ float smean[32], srstd[32];
    ssum[cg][tt] = s; ssq[cg][tt] = s2;
    __syncthreads();
    if (tid < 32) {
        float ts = 0.f, ts2 = 0.f;
#pragma unroll
        for (int g = 0; g < 8; g++) { ts += ssum[g][tid]; ts2 += ssq[g][tid]; }
        float mean = ts * (1.0f / D_MODEL);
        float var  = ts2 * (1.0f / D_MODEL) - mean * mean;
        smean[tid] = mean;
        srstd[tid] = rsqrtf(var + 1e-5f);
    }
    __syncthreads();
    float mean = smean[tt], rstd = srstd[tt];
    float* O = out + (long)b * D_MODEL * QLEN;
    bf16* O2 = out2 ? (out2 + (long)b * 2 * D_MODEL * QLEN) : nullptr;
    for (int c = cg * 128; c < cg * 128 + 128; c++) {
        long idx = (long)c * QLEN + t0 + tt;
        float v = Ya[idx] + (Yb ? Yb[idx] : 0.f);
        float r = (v - mean) * rstd;
        O[idx] = r;
        if (O2) {
            bf16 hi, lo; split_bf16(r, hi, lo);
            O2[idx]                          = hi;
            O2[(long)D_MODEL * QLEN + idx]   = lo;
        }
    }
}

// ---------------- launcher ---------------------------------------------------
#define GSMEM44 ((2 * 128 * APADE + 2 * 64 * 136) * 2)    // 71680 (MI=4, NJ=4)

extern "C" void kernel_launch(void* const* d_in, const int* in_sizes, int n_in,
                              void* d_out, int out_size)
{
    const float* z1ss    = (const float*)d_in[0];
    const float* uss     = (const float*)d_in[1];
    const float* z0      = (const float*)d_in[2];
    const float* pos_emb = (const float*)d_in[3];
    const float* qkv_w   = (const float*)d_in[4];
    const float* r_w     = (const float*)d_in[5];
    const float* r_w_bias= (const float*)d_in[6];
    const float* r_r_bias= (const float*)d_in[7];
    const float* o_w     = (const float*)d_in[8];
    const float* o_b     = (const float*)d_in[9];
    const float* ff1_w   = (const float*)d_in[10];
    const float* ff1_b   = (const float*)d_in[11];
    const float* ff2_w   = (const float*)d_in[12];
    const float* ff2_b   = (const float*)d_in[13];
    float* out = (float*)d_out;

    float *wheads, *rkp, *x, *tmp2, *BDg;
    bf16 *qkvw2, *rw2, *ow2, *ff1w2, *ff2w2, *pos2, *cat2, *avec2, *x2, *h2, *rA2, *qr2;
    cudaGetSymbolAddress((void**)&wheads, g_wheads);
    cudaGetSymbolAddress((void**)&rkp,    g_rkp);
    cudaGetSymbolAddress((void**)&x,      g_x);
    cudaGetSymbolAddress((void**)&tmp2,   g_tmp2);
    cudaGetSymbolAddress((void**)&BDg,    g_BD);
    cudaGetSymbolAddress((void**)&qkvw2,  g_qkvw2);
    cudaGetSymbolAddress((void**)&rw2,    g_rw2);
    cudaGetSymbolAddress((void**)&ow2,    g_ow2);
    cudaGetSymbolAddress((void**)&ff1w2,  g_ff1w2);
    cudaGetSymbolAddress((void**)&ff2w2,  g_ff2w2);
    cudaGetSymbolAddress((void**)&pos2,   g_pos2);
    cudaGetSymbolAddress((void**)&cat2,   g_cat2);
    cudaGetSymbolAddress((void**)&avec2,  g_avec2);
    cudaGetSymbolAddress((void**)&x2,     g_x2);
    cudaGetSymbolAddress((void**)&h2,     g_h2);
    cudaGetSymbolAddress((void**)&rA2,    g_rA2);
    cudaGetSymbolAddress((void**)&qr2,    g_qr2);

    cudaFuncSetAttribute(attn_tiled_kernel,
                         cudaFuncAttributeMaxDynamicSharedMemorySize, AT_SMEM);
    cudaFuncSetAttribute(gemm_bf16_kernel<4, 4>,
                         cudaFuncAttributeMaxDynamicSharedMemorySize, GSMEM44);

    const long s3dk = (long)3 * D_MODEL * KLEN;   // wheads batch stride
    const long s2dk = (long)2 * D_MODEL * KLEN;   // cat2 batch stride
    const long s2dq = (long)2 * D_MODEL * QLEN;
    const long s2iq = (long)2 * DINNER * QLEN;
    const long sdq  = (long)D_MODEL * QLEN;
    const long sDK  = (long)D_MODEL * KLEN;
    const int  NB   = BSZ * QLEN;

    // [1] weight expansions (two-plane)
    expand_weights_kernel<<<13312, 128>>>(qkv_w, r_w, o_w, ff1_w, ff2_w,
                                          qkvw2, rw2, ow2, ff1w2, ff2w2);
    // [2] cat expansion (cols [256,1024))
    expand_cat_kernel<<<dim3(3, D_MODEL, BSZ), 256>>>(z0, z1ss, 256);
    // [3] pos expansion (cols [768,1024))
    expandB_kernel<<<dim3(1, D_MODEL, 1), 256>>>(pos_emb, pos2, KLEN, 768, D_MODEL, 0, 0);

    // [4] QKV: tile list, 512 CTAs; Kps=Kp=1024
    gemm_bf16_kernel<4, 4><<<dim3(128, 1, BSZ), 256, GSMEM44>>>(
        qkvw2, cat2 + 256, wheads + 256, nullptr, uss + 256,
        1024, 1024, KLEN, 0, s2dk, s3dk, s3dk, 0, 0, 0, 0, 1);

    // [5] r_head_k: K-split x8 -> 128 CTAs; Kps=128, Kp=1024
    gemm_bf16_kernel<4, 4><<<dim3(2, 8, 8), 256, GSMEM44>>>(
        rw2, pos2 + 768, rkp + 768, nullptr, nullptr,
        128, 1024, KLEN, 0, 0, 0, 0, sDK, 0, 3, 0, 0);

    // [6] reduce rk partials
    reduce_rk_kernel<<<256, 256>>>(rkp);

    // [7] rA2 expansion
    expand_rA_kernel<<<dim3(16, NHEAD), 256>>>(rkp, rA2);
    // [8] qr2 expansion
    expand_qr_kernel<<<dim3(QLEN / 256, DHEAD, BSZ * NHEAD), 256>>>(
        wheads, r_r_bias, qr2);

    // [9] BD GEMM: per head, 256 x 2048, Kps=Kp=64 -> 512 CTAs
    gemm_bf16_kernel<4, 4><<<dim3(16, 2, NHEAD), 256, GSMEM44>>>(
        rA2, qr2, BDg, nullptr, nullptr,
        64, 64, NB, (long)256 * 128, (long)128 * NB, (long)256 * NB,
        0, 0, 0, 0, 0, 0);

    // [10] banded attention -> avec2
    attn_tiled_kernel<<<dim3(QLEN / 32, NHEAD, BSZ), 256, AT_SMEM>>>(
        wheads, BDg, r_w_bias, avec2);

    // [11] O-proj: K-split x2 -> 256 CTAs; Kps=512, Kp=1024
    gemm_bf16_kernel<4, 4><<<dim3(4, 8, 2 * BSZ), 256, GSMEM44>>>(
        ow2, avec2, tmp2, o_b, z1ss,
        512, 1024, QLEN, 0, s2dq, sdq, sdq, (long)BSZ * sdq, 0, 1, 0, 0);

    // [12] x = LN(sum of halves), fused x2
    ln_kernel<<<dim3(QLEN / 32, BSZ), 256>>>(tmp2, tmp2 + (long)BSZ * sdq, x, x2);

    // [13] FF1: 512 CTAs, two-plane relu epilogue; Kps=Kp=1024
    gemm_bf16_kernel<4, 4><<<dim3(4, 32, BSZ), 256, GSMEM44>>>(
        ff1w2, x2, h2, ff1_b, nullptr,
        1024, 1024, QLEN, 0, s2dq, s2iq, 0, 0, (long)DINNER * QLEN, 0, 2, 0);

    // [14] FF2: K-split x2 -> 256 CTAs; Kps=2048, Kp=4096
    gemm_bf16_kernel<4, 4><<<dim3(4, 8, 2 * BSZ), 256, GSMEM44>>>(
        ff2w2, h2, tmp2, ff2_b, x,
        2048, 4096, QLEN, 0, s2iq, sdq, sdq, (long)BSZ * sdq, 0, 1, 0, 0);

    // [15] out = LN(sum of halves)
    ln_kernel<<<dim3(QLEN / 32, BSZ), 256>>>(tmp2, tmp2 + (long)BSZ * sdq, out, nullptr);
}

// round 16
// speedup vs baseline: 1.1919x; 1.0061x over previous
#include <cuda_runtime.h>
#include <cuda_bf16.h>
#include <cstdint>

#define BSZ     4
#define D_MODEL 1024
#define QLEN    512
#define MLEN    512
#define KLEN    1024
#define NHEAD   16
#define DHEAD   64
#define DINNER  4096

typedef __nv_bfloat16 bf16;

// ---------------- fp32 scratch ----------------------------------------------
__device__ float g_wheads[BSZ * 3 * D_MODEL * KLEN];
__device__ float g_rkp[8 * D_MODEL * KLEN];          // 8 K-split partial planes
__device__ float g_x[BSZ * D_MODEL * QLEN];
__device__ float g_tmp2[2 * BSZ * D_MODEL * QLEN];   // K-split halves
__device__ float g_BD[NHEAD * 256 * (BSZ * QLEN)];   // BD[h][t][b*512+i]

// ---------------- two-plane bf16 split scratch ([hi | lo]) -------------------
__device__ bf16 g_qkvw2[3 * D_MODEL * 2 * D_MODEL];
__device__ bf16 g_rw2  [D_MODEL * 2 * D_MODEL];
__device__ bf16 g_ow2  [D_MODEL * 2 * D_MODEL];
__device__ bf16 g_ff1w2[DINNER * 2 * D_MODEL];
__device__ bf16 g_ff2w2[D_MODEL * 2 * DINNER];
__device__ bf16 g_pos2 [2 * D_MODEL * KLEN];
__device__ bf16 g_cat2 [BSZ * 2 * D_MODEL * KLEN];
__device__ bf16 g_avec2[BSZ * 2 * D_MODEL * QLEN];
__device__ bf16 g_x2   [BSZ * 2 * D_MODEL * QLEN];
__device__ bf16 g_h2   [BSZ * 2 * DINNER * QLEN];
__device__ bf16 g_rA2  [NHEAD * 256 * 128];
__device__ bf16 g_qr2  [NHEAD * 128 * (BSZ * QLEN)];

// ---------------- helpers ----------------------------------------------------
__device__ __forceinline__ void split_bf16(float x, bf16& hi, bf16& lo)
{
    hi = __float2bfloat16(x);
    lo = __float2bfloat16(x - __bfloat162float(hi));
}

__device__ __forceinline__ void cp_async16(uint32_t smem_dst, const void* gmem_src)
{
    asm volatile("cp.async.cg.shared.global [%0], [%1], 16;\n"
                 :: "r"(smem_dst), "l"(gmem_src));
}
__device__ __forceinline__ void cp_commit()
{
    asm volatile("cp.async.commit_group;\n");
}
__device__ __forceinline__ void cp_wait_all()
{
    asm volatile("cp.async.wait_group 0;\n");
}
__device__ __forceinline__ void ldsm_x4(uint32_t& r0, uint32_t& r1, uint32_t& r2, uint32_t& r3, uint32_t addr)
{
    asm volatile("ldmatrix.sync.aligned.m8n8.x4.shared.b16 {%0,%1,%2,%3}, [%4];\n"
                 : "=r"(r0), "=r"(r1), "=r"(r2), "=r"(r3) : "r"(addr));
}
__device__ __forceinline__ void ldsm_x4_t(uint32_t& r0, uint32_t& r1, uint32_t& r2, uint32_t& r3, uint32_t addr)
{
    asm volatile("ldmatrix.sync.aligned.m8n8.x4.trans.shared.b16 {%0,%1,%2,%3}, [%4];\n"
                 : "=r"(r0), "=r"(r1), "=r"(r2), "=r"(r3) : "r"(addr));
}
__device__ __forceinline__ void mma16816(float* c, const uint32_t* a, const uint32_t* b)
{
    asm volatile(
        "mma.sync.aligned.m16n8k16.row.col.f32.bf16.bf16.f32 "
        "{%0,%1,%2,%3}, {%4,%5,%6,%7}, {%8,%9}, {%0,%1,%2,%3};\n"
        : "+f"(c[0]), "+f"(c[1]), "+f"(c[2]), "+f"(c[3])
        : "r"(a[0]), "r"(a[1]), "r"(a[2]), "r"(a[3]), "r"(b[0]), "r"(b[1]));
}

// ---------------- expansion kernels (two-plane) -------------------------------
__global__ void expand_weights_kernel(const float* __restrict__ qkv_w,
                                      const float* __restrict__ r_w,
                                      const float* __restrict__ o_w,
                                      const float* __restrict__ ff1_w,
                                      const float* __restrict__ ff2_w,
                                      bf16* qkvw2, bf16* rw2, bf16* ow2,
                                      bf16* ff1w2, bf16* ff2w2)
{
    int cid = blockIdx.x;
    const float* in; bf16* out; int K; int row; int kc;
    if (cid < 3072)       { in = qkv_w; out = qkvw2; K = 1024; row = cid;        kc = 0; }
    else if (cid < 4096)  { in = r_w;   out = rw2;   K = 1024; row = cid - 3072; kc = 0; }
    else if (cid < 5120)  { in = o_w;   out = ow2;   K = 1024; row = cid - 4096; kc = 0; }
    else if (cid < 9216)  { in = ff1_w; out = ff1w2; K = 1024; row = cid - 5120; kc = 0; }
    else { int c = cid - 9216; in = ff2_w; out = ff2w2; K = 4096; row = c >> 2; kc = c & 3; }

    int k0 = (kc * 128 + threadIdx.x) * 8;
    const float4* ip = (const float4*)(in + (long)row * K + k0);
    float4 f0 = ip[0], f1 = ip[1];
    float v[8] = {f0.x, f0.y, f0.z, f0.w, f1.x, f1.y, f1.z, f1.w};
    unsigned short sh[8], sl[8];
#pragma unroll
    for (int j = 0; j < 8; j++) {
        bf16 hi, lo; split_bf16(v[j], hi, lo);
        sh[j] = __bfloat16_as_ushort(hi);
        sl[j] = __bfloat16_as_ushort(lo);
    }
    uint32_t wh[4], wl[4];
#pragma unroll
    for (int i = 0; i < 4; i++) {
        wh[i] = (uint32_t)sh[2 * i] | ((uint32_t)sh[2 * i + 1] << 16);
        wl[i] = (uint32_t)sl[2 * i] | ((uint32_t)sl[2 * i + 1] << 16);
    }
    bf16* orow = out + (long)row * 2 * K;
    *(uint4*)(orow + k0)     = make_uint4(wh[0], wh[1], wh[2], wh[3]);
    *(uint4*)(orow + K + k0) = make_uint4(wl[0], wl[1], wl[2], wl[3]);
}

// B-operand two-plane: hi row k, lo row Kp+k
__global__ void expandB_kernel(const float* __restrict__ in, bf16* __restrict__ out,
                               int ldn, int n0, int Kp, long sIn, long sOut)
{
    int n = n0 + blockIdx.x * 256 + threadIdx.x;
    int k = blockIdx.y;
    float x = in[(long)blockIdx.z * sIn + (long)k * ldn + n];
    bf16 hi, lo; split_bf16(x, hi, lo);
    bf16* o = out + (long)blockIdx.z * sOut + (long)k * ldn + n;
    o[0] = hi;
    o[(long)Kp * ldn] = lo;
}

__global__ void expand_cat_kernel(const float* __restrict__ z0, const float* __restrict__ z1ss,
                                  int t0base)
{
    int t = t0base + blockIdx.x * 256 + threadIdx.x;
    int d = blockIdx.y;
    int b = blockIdx.z;
    float x = (t < MLEN) ? z0[((long)b * D_MODEL + d) * MLEN + t]
                         : z1ss[((long)b * D_MODEL + d) * QLEN + (t - MLEN)];
    bf16 hi, lo; split_bf16(x, hi, lo);
    bf16* o = g_cat2 + (long)b * 2 * D_MODEL * KLEN + (long)d * KLEN + t;
    o[0] = hi;
    o[(long)D_MODEL * KLEN] = lo;
}

// fused: reduce 8 rkp partial planes AND write split rA2[h][t][hi|lo] directly
__global__ void reduce_rk_rA_kernel(const float* __restrict__ rkp,
                                    bf16* __restrict__ rA2)
{
    const long DK = (long)D_MODEL * KLEN;
    int idx = blockIdx.x * 256 + threadIdx.x;     // 65536 threads
    int row = idx >> 6;                           // global d in [0,1024)
    int t4  = (idx & 63) * 4;                     // t in [0,256)
    long base = (long)row * KLEN + 768 + t4;
    float4 a = *(const float4*)(rkp + base);
#pragma unroll
    for (int p = 1; p < 8; p++) {
        float4 q = *(const float4*)(rkp + p * DK + base);
        a.x += q.x; a.y += q.y; a.z += q.z; a.w += q.w;
    }
    int h = row >> 6, dl = row & 63;
    float v[4] = {a.x, a.y, a.z, a.w};
#pragma unroll
    for (int i = 0; i < 4; i++) {
        bf16 hi, lo; split_bf16(v[i], hi, lo);
        bf16* op = rA2 + ((long)h * 256 + t4 + i) * 128 + dl;
        op[0]  = hi;
        op[64] = lo;
    }
}

// qr2[h][d][b*512+i]=hi, [64+d]=lo of (Q + rrb)
__global__ void expand_qr_kernel(const float* __restrict__ wheads,
                                 const float* __restrict__ rrb,
                                 bf16* __restrict__ qr2)
{
    int i = blockIdx.x * 256 + threadIdx.x;
    int d = blockIdx.y;
    int b = blockIdx.z & 3, h = blockIdx.z >> 2;
    float v = wheads[(long)b * 3 * D_MODEL * KLEN + (long)(h * DHEAD + d) * KLEN
                     + MLEN + i] + rrb[h * DHEAD + d];
    bf16 hi, lo; split_bf16(v, hi, lo);
    const int NB = BSZ * QLEN;
    bf16* o = qr2 + (long)h * 128 * NB + (long)d * NB + b * QLEN + i;
    o[0] = hi;
    o[64 * NB] = lo;
}

// ---------------- tensor-core GEMM, two-plane 3-term, 3-stage pipeline -------
// Iteration space: 3 parts x Kps. part0: hiA*hiB, part1: hiA*loB, part2: loA*hiB.
// (part, kk) carried incrementally. 3-stage cp.async ring, wait_group 1,
// single __syncthreads per iteration.
#define APADE 72
#define NSTG  3

template<int MI, int NJ>
__global__ __launch_bounds__(256, 2)
void gemm_bf16_kernel(const bf16* __restrict__ A,
                      const bf16* __restrict__ B,
                      void*       __restrict__ Cv,
                      const float* __restrict__ bias,
                      const float* __restrict__ addend,
                      int Kps, int Kp, int ldn,
                      long strideA, long strideB, long strideC,
                      long strideAdd, long strideCk, long planeC,
                      int zshift, int mode, int tilemap)
{
    constexpr int GBMt = 32 * MI;
    constexpr int GBN  = 32 * NJ;
    constexpr int BP   = GBN + 8;
    constexpr int BCH  = GBN / 8;
    constexpr int BSH  = (NJ == 4 ? 4 : 5);

    extern __shared__ bf16 smem_g[];
    bf16* Asm = smem_g;
    bf16* Bsm = smem_g + NSTG * GBMt * APADE;

    const int tid  = threadIdx.x;
    const int lane = tid & 31;
    const int warp = tid >> 5;
    const int wm = warp >> 2;
    const int wn = warp & 3;

    int bxi = blockIdx.x, byi = blockIdx.y;
    if (tilemap) {
        int f = blockIdx.x;
        if (f < 96) { byi = 8 + f / 6; bxi = f % 6; }
        else        { int gq = f - 96; byi = gq >> 2; bxi = 2 + (gq & 3); }
    }
    const int bn = bxi * GBN;
    const int bm = byi * GBMt;
    const int b  = blockIdx.z >> zshift;
    const int ks = blockIdx.z & ((1 << zshift) - 1);
    const int ldk = 2 * Kp;

    const bf16* Ag = A + (long)b * strideA + (long)bm * ldk + (long)ks * Kps;
    const bf16* Bg = B + (long)b * strideB + (long)ks * Kps * ldn;

    uint32_t sA = (uint32_t)__cvta_generic_to_shared(Asm);
    uint32_t sB = (uint32_t)__cvta_generic_to_shared(Bsm);
    const uint32_t sAsz = GBMt * APADE * 2;
    const uint32_t sBsz = 64 * BP * 2;

    float acc[MI][NJ][4];
#pragma unroll
    for (int i = 0; i < MI; i++)
#pragma unroll
        for (int j = 0; j < NJ; j++)
#pragma unroll
            for (int r = 0; r < 4; r++) acc[i][j][r] = 0.f;

    auto load_tiles = [&](int buf, long aoff, long boff) {
#pragma unroll
        for (int i = 0; i < MI; i++) {
            int c   = tid + 256 * i;
            int row = c >> 3, ch = c & 7;
            cp_async16(sA + buf * sAsz + (row * APADE + ch * 8) * 2,
                       Ag + (long)row * ldk + aoff + ch * 8);
        }
#pragma unroll
        for (int i = 0; i < (64 * BCH) / 256; i++) {
            int c   = tid + 256 * i;
            int row = c >> BSH, ch = c & (BCH - 1);
            cp_async16(sB + buf * sBsz + (row * BP + ch * 8) * 2,
                       Bg + (boff + row) * ldn + bn + ch * 8);
        }
        cp_commit();
    };

    // incremental (part, kk) state for the NEXT stage to load
    int part = 0, kk = 0;
    auto cur_aoff = [&]() -> long { return (part < 2 ? 0L : (long)Kp) + kk; };
    auto cur_boff = [&]() -> long { return (part == 1 ? (long)Kp : 0L) + kk; };
    auto advance  = [&]() { kk += 64; if (kk == Kps) { kk = 0; part++; } };

    load_tiles(0, cur_aoff(), cur_boff());
    advance();
    load_tiles(1, cur_aoff(), cur_boff());
    advance();

    const int nIter = (3 * Kps) >> 6;
    int buf = 0;
    for (int it = 0; it < nIter; it++) {
        if (it + 1 < nIter) asm volatile("cp.async.wait_group 1;\n");
        else                asm volatile("cp.async.wait_group 0;\n");
        __syncthreads();
        if (it + 2 < nIter) {
            int lb = buf + 2; if (lb >= NSTG) lb -= NSTG;
            load_tiles(lb, cur_aoff(), cur_boff());
            advance();
        }

#pragma unroll
        for (int ks4 = 0; ks4 < 4; ks4++) {
            uint32_t afrag[MI][4];
            uint32_t bfrag[NJ][2];
            int lrow = lane & 15, lcol = (lane >> 4) * 8;
#pragma unroll
            for (int mi = 0; mi < MI; mi++) {
                uint32_t addr = sA + buf * sAsz +
                    ((MI * 16 * wm + 16 * mi + lrow) * APADE + ks4 * 16 + lcol) * 2;
                ldsm_x4(afrag[mi][0], afrag[mi][1], afrag[mi][2], afrag[mi][3], addr);
            }
#pragma unroll
            for (int nj2 = 0; nj2 < NJ / 2; nj2++) {
                uint32_t addr = sB + buf * sBsz +
                    ((ks4 * 16 + lrow) * BP + (8 * NJ) * wn + 16 * nj2 + lcol) * 2;
                uint32_t r0, r1, r2, r3;
                ldsm_x4_t(r0, r1, r2, r3, addr);
                bfrag[2 * nj2][0] = r0;     bfrag[2 * nj2][1] = r1;
                bfrag[2 * nj2 + 1][0] = r2; bfrag[2 * nj2 + 1][1] = r3;
            }
#pragma unroll
            for (int mi = 0; mi < MI; mi++)
#pragma unroll
                for (int nj = 0; nj < NJ; nj++)
                    mma16816(acc[mi][nj], afrag[mi], bfrag[nj]);
        }
        buf++; if (buf == NSTG) buf = 0;
    }

    const float* Ad = (addend && ks == 0) ? (addend + (long)b * strideAdd) : nullptr;
    const float* bz = (ks == 0) ? bias : nullptr;
    int g = lane >> 2, tg = lane & 3;

    if (mode == 2) {
        bf16* C2 = (bf16*)Cv + (long)b * strideC;
#pragma unroll
        for (int mi = 0; mi < MI; mi++) {
            int row0 = bm + MI * 16 * wm + 16 * mi + g;
            int row1 = row0 + 8;
            float bv0 = bz ? bz[row0] : 0.f;
            float bv1 = bz ? bz[row1] : 0.f;
#pragma unroll
            for (int nj = 0; nj < NJ; nj++) {
                int col = bn + (8 * NJ) * wn + 8 * nj + 2 * tg;
#pragma unroll
                for (int half = 0; half < 2; half++) {
                    int row = half ? row1 : row0;
                    float bv = half ? bv1 : bv0;
                    float v0 = fmaxf(acc[mi][nj][2 * half]     + bv, 0.f);
                    float v1 = fmaxf(acc[mi][nj][2 * half + 1] + bv, 0.f);
                    bf16 h0, l0, h1, l1;
                    split_bf16(v0, h0, l0);
                    split_bf16(v1, h1, l1);
                    long base = (long)row * ldn + col;
                    C2[base]              = h0; C2[base + 1]              = h1;
                    C2[planeC + base]     = l0; C2[planeC + base + 1]     = l1;
                }
            }
        }
        return;
    }

    float* Cb = (float*)Cv + (long)b * strideC + (long)ks * strideCk;
#pragma unroll
    for (int mi = 0; mi < MI; mi++) {
        int row0 = bm + MI * 16 * wm + 16 * mi + g;
        int row1 = row0 + 8;
        float bv0 = bz ? bz[row0] : 0.f;
        float bv1 = bz ? bz[row1] : 0.f;
#pragma unroll
        for (int nj = 0; nj < NJ; nj++) {
            int col = bn + (8 * NJ) * wn + 8 * nj + 2 * tg;
            float v00 = acc[mi][nj][0] + bv0;
            float v01 = acc[mi][nj][1] + bv0;
            float v10 = acc[mi][nj][2] + bv1;
            float v11 = acc[mi][nj][3] + bv1;
            if (Ad) {
                v00 += Ad[(long)row0 * ldn + col];
                v01 += Ad[(long)row0 * ldn + col + 1];
                v10 += Ad[(long)row1 * ldn + col];
                v11 += Ad[(long)row1 * ldn + col + 1];
            }
            if (mode == 1) {
                v00 = fmaxf(v00, 0.f); v01 = fmaxf(v01, 0.f);
                v10 = fmaxf(v10, 0.f); v11 = fmaxf(v11, 0.f);
            }
            Cb[(long)row0 * ldn + col]     = v00;
            Cb[(long)row0 * ldn + col + 1] = v01;
            Cb[(long)row1 * ldn + col]     = v10;
            Cb[(long)row1 * ldn + col + 1] = v11;
        }
    }
}

// ---------------- tiled banded attention: 32-query blocks --------------------
#define AT_SMEM ((32*68 + 32*258 + 64*68*2 + 32*68 + 256 + 32) * 4)

__global__ __launch_bounds__(256)
void attn_tiled_kernel(const float* __restrict__ wheads,
                       const float* __restrict__ BDg,
                       const float* __restrict__ rwb,
                       bf16*        __restrict__ avec2)
{
    extern __shared__ float sm[];
    float* qw   = sm;                        // [q][d]   stride 68
    float* BDs  = qw + 32 * 68;              // [q][t]   stride 258
    float* Ks   = BDs + 32 * 258;            // [jj][d]  stride 68
    float* Vs   = Ks + 64 * 68;              // [d][jj]  stride 68
    float* Ps   = Vs + 64 * 68;              // [q][jj]  stride 68
    float* red  = Ps + 32 * 68;              // [8][32]
    float* sinv = red + 256;                 // [32]

    const int i0 = blockIdx.x * 32;
    const int h  = blockIdx.y;
    const int b  = blockIdx.z;
    const int tid = threadIdx.x;

    const float* W  = wheads + (long)b * (3 * D_MODEL) * KLEN;
    const float* Qg = W + (long)(h * DHEAD) * KLEN;
    const float* Kg = W + (long)(D_MODEL + h * DHEAD) * KLEN;
    const float* Vg = W + (long)(2 * D_MODEL + h * DHEAD) * KLEN;

    for (int idx = tid; idx < 32 * 64; idx += 256) {
        int d = idx >> 5, q = idx & 31;
        qw[q * 68 + d] = Qg[(long)d * KLEN + MLEN + i0 + q] + rwb[h * DHEAD + d];
    }
    {
        const float* BDh = BDg + (long)h * 256 * (BSZ * QLEN) + b * QLEN + i0;
        for (int idx = tid; idx < 32 * 256; idx += 256) {
            int q = idx & 31, t = idx >> 5;
            BDs[q * 258 + t] = BDh[(long)t * (BSZ * QLEN) + q];
        }
    }
    __syncthreads();

    const int qi = tid & 31;
    const int jg = tid >> 5;
    uint32_t VsAddr = (uint32_t)__cvta_generic_to_shared(Vs);
    float O[8];
#pragma unroll
    for (int u = 0; u < 8; u++) O[u] = 0.f;
    float sume = 0.f;

    for (int c = 0; c < 5; c++) {
        int jbase = i0 + 256 + 64 * c;
        if (c > 0) __syncthreads();
        for (int idx = tid; idx < 64 * 16; idx += 256) {
            int d = idx >> 4, jj0 = (idx & 15) * 4;
            int jg0 = jbase + jj0;
            uint32_t dst = VsAddr + (d * 68 + jj0) * 4;
            if (jg0 + 3 < KLEN) {
                cp_async16(dst, Vg + (long)d * KLEN + jg0);
            } else {
                float4 z = make_float4(0.f, 0.f, 0.f, 0.f);
                if (jg0 + 0 < KLEN) z.x = Vg[(long)d * KLEN + jg0];
                if (jg0 + 1 < KLEN) z.y = Vg[(long)d * KLEN + jg0 + 1];
                if (jg0 + 2 < KLEN) z.z = Vg[(long)d * KLEN + jg0 + 2];
                if (jg0 + 3 < KLEN) z.w = Vg[(long)d * KLEN + jg0 + 3];
                *(float4*)(Vs + d * 68 + jj0) = z;
            }
        }
        cp_commit();
        for (int idx = tid; idx < 64 * 64; idx += 256) {
            int d = idx >> 6, jj = idx & 63;
            int jglob = jbase + jj;
            Ks[jj * 68 + d] = (jglob < KLEN) ? Kg[(long)d * KLEN + jglob] : 0.f;
        }
        cp_wait_all();
        __syncthreads();

        {
            float acc[8];
#pragma unroll
            for (int u = 0; u < 8; u++) acc[u] = 0.f;
            for (int d4 = 0; d4 < 16; d4++) {
                float4 qv4 = *(const float4*)(qw + qi * 68 + d4 * 4);
#pragma unroll
                for (int u = 0; u < 8; u++) {
                    float4 k4 = *(const float4*)(Ks + (jg * 8 + u) * 68 + d4 * 4);
                    acc[u] = fmaf(qv4.x, k4.x, acc[u]);
                    acc[u] = fmaf(qv4.y, k4.y, acc[u]);
                    acc[u] = fmaf(qv4.z, k4.z, acc[u]);
                    acc[u] = fmaf(qv4.w, k4.w, acc[u]);
                }
            }
            float pvv[8];
#pragma unroll
            for (int u = 0; u < 8; u++) {
                int jj = jg * 8 + u;
                int t  = 64 * c + jj - qi - 1;
                float pv = 0.f;
                if (t >= 0 && t < 256)
                    pv = __expf((acc[u] + BDs[qi * 258 + t]) * 0.125f);
                sume += pv;
                pvv[u] = pv;
            }
            // conflict-free float4 stores (68/4 = 17, odd)
            *(float4*)(Ps + qi * 68 + jg * 8)     = make_float4(pvv[0], pvv[1], pvv[2], pvv[3]);
            *(float4*)(Ps + qi * 68 + jg * 8 + 4) = make_float4(pvv[4], pvv[5], pvv[6], pvv[7]);
        }
        __syncthreads();

        for (int js = 0; js < 16; js++) {
            int jj0 = js * 4;
            float4 p4 = *(const float4*)(Ps + qi * 68 + jj0);
#pragma unroll
            for (int u = 0; u < 8; u++) {
                float4 v4 = *(const float4*)(Vs + (jg * 8 + u) * 68 + jj0);
                O[u] = fmaf(p4.x, v4.x, O[u]);
                O[u] = fmaf(p4.y, v4.y, O[u]);
                O[u] = fmaf(p4.z, v4.z, O[u]);
                O[u] = fmaf(p4.w, v4.w, O[u]);
            }
        }
    }

    red[jg * 32 + qi] = sume;
    __syncthreads();
    if (tid < 32) {
        float s = 0.f;
#pragma unroll
        for (int g8 = 0; g8 < 8; g8++) s += red[g8 * 32 + tid];
        sinv[tid] = 1.f / s;
    }
    __syncthreads();
    float inv = sinv[qi];
    bf16* outp = avec2 + (long)b * 2 * D_MODEL * QLEN;
#pragma unroll
    for (int u = 0; u < 8; u++) {
        int dp = h * DHEAD + jg * 8 + u;
        float v = O[u] * inv;
        bf16 hi, lo; split_bf16(v, hi, lo);
        long base = (long)dp * QLEN + i0 + qi;
        outp[base]                          = hi;
        outp[(long)D_MODEL * QLEN + base]   = lo;
    }
}

// ---------------- channel LayerNorm (optional 2nd input, 2-plane split) ------
__global__ __launch_bounds__(256)
void ln_kernel(const float* __restrict__ ya, const float* __restrict__ yb,
               float* __restrict__ out, bf16* __restrict__ out2)
{
    int b  = blockIdx.y;
    int t0 = blockIdx.x * 32;
    int tid = threadIdx.x;
    int tt = tid & 31, cg = tid >> 5;
    const float* Ya = ya + (long)b * D_MODEL * QLEN;
    const float* Yb = yb ? (yb + (long)b * D_MODEL * QLEN) : nullptr;

    float s = 0.f, s2 = 0.f;
    for (int c = cg * 128; c < cg * 128 + 128; c++) {
        long idx = (long)c * QLEN + t0 + tt;
        float v = Ya[idx] + (Yb ? Yb[idx] : 0.f);
        s += v; s2 += v * v;
    }
    __shared__ float ssum[8][32], ssq[8][32];
    __shared__ float smean[32], srstd[32];
    ssum[cg][tt] = s; ssq[cg][tt] = s2;
    __syncthreads();
    if (tid < 32) {
        float ts = 0.f, ts2 = 0.f;
#pragma unroll
        for (int g = 0; g < 8; g++) { ts += ssum[g][tid]; ts2 += ssq[g][tid]; }
        float mean = ts * (1.0f / D_MODEL);
        float var  = ts2 * (1.0f / D_MODEL) - mean * mean;
        smean[tid] = mean;
        srstd[tid] = rsqrtf(var + 1e-5f);
    }
    __syncthreads();
    float mean = smean[tt], rstd = srstd[tt];
    float* O = out + (long)b * D_MODEL * QLEN;
    bf16* O2 = out2 ? (out2 + (long)b * 2 * D_MODEL * QLEN) : nullptr;
    for (int c = cg * 128; c < cg * 128 + 128; c++) {
        long idx = (long)c * QLEN + t0 + tt;
        float v = Ya[idx] + (Yb ? Yb[idx] : 0.f);
        float r = (v - mean) * rstd;
        O[idx] = r;
        if (O2) {
            bf16 hi, lo; split_bf16(r, hi, lo);
            O2[idx]                          = hi;
            O2[(long)D_MODEL * QLEN + idx]   = lo;
        }
    }
}

// ---------------- launcher ---------------------------------------------------
#define GSMEM44 ((NSTG * 128 * APADE + NSTG * 64 * 136) * 2)   // 107520

extern "C" void kernel_launch(void* const* d_in, const int* in_sizes, int n_in,
                              void* d_out, int out_size)
{
    const float* z1ss    = (const float*)d_in[0];
    const float* uss     = (const float*)d_in[1];
    const float* z0      = (const float*)d_in[2];
    const float* pos_emb = (const float*)d_in[3];
    const float* qkv_w   = (const float*)d_in[4];
    const float* r_w     = (const float*)d_in[5];
    const float* r_w_bias= (const float*)d_in[6];
    const float* r_r_bias= (const float*)d_in[7];
    const float* o_w     = (const float*)d_in[8];
    const float* o_b     = (const float*)d_in[9];
    const float* ff1_w   = (const float*)d_in[10];
    const float* ff1_b   = (const float*)d_in[11];
    const float* ff2_w   = (const float*)d_in[12];
    const float* ff2_b   = (const float*)d_in[13];
    float* out = (float*)d_out;

    float *wheads, *rkp, *x, *tmp2, *BDg;
    bf16 *qkvw2, *rw2, *ow2, *ff1w2, *ff2w2, *pos2, *cat2, *avec2, *x2, *h2, *rA2, *qr2;
    cudaGetSymbolAddress((void**)&wheads, g_wheads);
    cudaGetSymbolAddress((void**)&rkp,    g_rkp);
    cudaGetSymbolAddress((void**)&x,      g_x);
    cudaGetSymbolAddress((void**)&tmp2,   g_tmp2);
    cudaGetSymbolAddress((void**)&BDg,    g_BD);
    cudaGetSymbolAddress((void**)&qkvw2,  g_qkvw2);
    cudaGetSymbolAddress((void**)&rw2,    g_rw2);
    cudaGetSymbolAddress((void**)&ow2,    g_ow2);
    cudaGetSymbolAddress((void**)&ff1w2,  g_ff1w2);
    cudaGetSymbolAddress((void**)&ff2w2,  g_ff2w2);
    cudaGetSymbolAddress((void**)&pos2,   g_pos2);
    cudaGetSymbolAddress((void**)&cat2,   g_cat2);
    cudaGetSymbolAddress((void**)&avec2,  g_avec2);
    cudaGetSymbolAddress((void**)&x2,     g_x2);
    cudaGetSymbolAddress((void**)&h2,     g_h2);
    cudaGetSymbolAddress((void**)&rA2,    g_rA2);
    cudaGetSymbolAddress((void**)&qr2,    g_qr2);

    cudaFuncSetAttribute(attn_tiled_kernel,
                         cudaFuncAttributeMaxDynamicSharedMemorySize, AT_SMEM);
    cudaFuncSetAttribute(gemm_bf16_kernel<4, 4>,
                         cudaFuncAttributeMaxDynamicSharedMemorySize, GSMEM44);

    const long s3dk = (long)3 * D_MODEL * KLEN;   // wheads batch stride
    const long s2dk = (long)2 * D_MODEL * KLEN;   // cat2 batch stride
    const long s2dq = (long)2 * D_MODEL * QLEN;
    const long s2iq = (long)2 * DINNER * QLEN;
    const long sdq  = (long)D_MODEL * QLEN;
    const long sDK  = (long)D_MODEL * KLEN;
    const int  NB   = BSZ * QLEN;

    // [1] weight expansions (two-plane)
    expand_weights_kernel<<<13312, 128>>>(qkv_w, r_w, o_w, ff1_w, ff2_w,
                                          qkvw2, rw2, ow2, ff1w2, ff2w2);
    // [2] cat expansion (cols [256,1024))
    expand_cat_kernel<<<dim3(3, D_MODEL, BSZ), 256>>>(z0, z1ss, 256);
    // [3] pos expansion (cols [768,1024))
    expandB_kernel<<<dim3(1, D_MODEL, 1), 256>>>(pos_emb, pos2, KLEN, 768, D_MODEL, 0, 0);

    // [4] QKV: tile list, 512 CTAs; Kps=Kp=1024
    gemm_bf16_kernel<4, 4><<<dim3(128, 1, BSZ), 256, GSMEM44>>>(
        qkvw2, cat2 + 256, wheads + 256, nullptr, uss + 256,
        1024, 1024, KLEN, 0, s2dk, s3dk, s3dk, 0, 0, 0, 0, 1);

    // [5] r_head_k: K-split x8 -> 128 CTAs; Kps=128, Kp=1024
    gemm_bf16_kernel<4, 4><<<dim3(2, 8, 8), 256, GSMEM44>>>(
        rw2, pos2 + 768, rkp + 768, nullptr, nullptr,
        128, 1024, KLEN, 0, 0, 0, 0, sDK, 0, 3, 0, 0);

    // [6] fused reduce rk partials + rA2 split expansion
    reduce_rk_rA_kernel<<<256, 256>>>(rkp, rA2);

    // [7] qr2 expansion
    expand_qr_kernel<<<dim3(QLEN / 256, DHEAD, BSZ * NHEAD), 256>>>(
        wheads, r_r_bias, qr2);

    // [8] BD GEMM: per head, 256 x 2048, Kps=Kp=64 -> 512 CTAs
    gemm_bf16_kernel<4, 4><<<dim3(16, 2, NHEAD), 256, GSMEM44>>>(
        rA2, qr2, BDg, nullptr, nullptr,
        64, 64, NB, (long)256 * 128, (long)128 * NB, (long)256 * NB,
        0, 0, 0, 0, 0, 0);

    // [9] banded attention -> avec2
    attn_tiled_kernel<<<dim3(QLEN / 32, NHEAD, BSZ), 256, AT_SMEM>>>(
        wheads, BDg, r_w_bias, avec2);

    // [10] O-proj: K-split x2 -> 256 CTAs; Kps=512, Kp=1024
    gemm_bf16_kernel<4, 4><<<dim3(4, 8, 2 * BSZ), 256, GSMEM44>>>(
        ow2, avec2, tmp2, o_b, z1ss,
        512, 1024, QLEN, 0, s2dq, sdq, sdq, (long)BSZ * sdq, 0, 1, 0, 0);

    // [11] x = LN(sum of halves), fused x2
    ln_kernel<<<dim3(QLEN / 32, BSZ), 256>>>(tmp2, tmp2 + (long)BSZ * sdq, x, x2);

    // [12] FF1: 512 CTAs, two-plane relu epilogue; Kps=Kp=1024
    gemm_bf16_kernel<4, 4><<<dim3(4, 32, BSZ), 256, GSMEM44>>>(
        ff1w2, x2, h2, ff1_b, nullptr,
        1024, 1024, QLEN, 0, s2dq, s2iq, 0, 0, (long)DINNER * QLEN, 0, 2, 0);

    // [13] FF2: K-split x2 -> 256 CTAs; Kps=2048, Kp=4096
    gemm_bf16_kernel<4, 4><<<dim3(4, 8, 2 * BSZ), 256, GSMEM44>>>(
        ff2w2, h2, tmp2, ff2_b, x,
        2048, 4096, QLEN, 0, s2iq, sdq, sdq, (long)BSZ * sdq, 0, 1, 0, 0);

    // [14] out = LN(sum of halves)
    ln_kernel<<<dim3(QLEN / 32, BSZ), 256>>>(tmp2, tmp2 + (long)BSZ * sdq, out, nullptr);
}

// round 17
// speedup vs baseline: 1.2324x; 1.0340x over previous
#include <cuda_runtime.h>
#include <cuda_bf16.h>
#include <cstdint>

#define BSZ     4
#define D_MODEL 1024
#define QLEN    512
#define MLEN    512
#define KLEN    1024
#define NHEAD   16
#define DHEAD   64
#define DINNER  4096

typedef __nv_bfloat16 bf16;

// ---------------- fp32 scratch ----------------------------------------------
__device__ float g_wheads[BSZ * 3 * D_MODEL * KLEN];
__device__ float g_rkp[8 * D_MODEL * KLEN];          // 8 K-split partial planes
__device__ float g_x[BSZ * D_MODEL * QLEN];
__device__ float g_tmp2[2 * BSZ * D_MODEL * QLEN];   // K-split halves
__device__ float g_BD[NHEAD * 288 * (BSZ * QLEN)];   // diagonal BDd[h][s][b*512+i]

// ---------------- two-plane bf16 split scratch ([hi | lo]) -------------------
__device__ bf16 g_qkvw2[3 * D_MODEL * 2 * D_MODEL];
__device__ bf16 g_rw2  [D_MODEL * 2 * D_MODEL];
__device__ bf16 g_ow2  [D_MODEL * 2 * D_MODEL];
__device__ bf16 g_ff1w2[DINNER * 2 * D_MODEL];
__device__ bf16 g_ff2w2[D_MODEL * 2 * DINNER];
__device__ bf16 g_pos2 [2 * D_MODEL * KLEN];
__device__ bf16 g_cat2 [BSZ * 2 * D_MODEL * KLEN];
__device__ bf16 g_avec2[BSZ * 2 * D_MODEL * QLEN];
__device__ bf16 g_x2   [BSZ * 2 * D_MODEL * QLEN];
__device__ bf16 g_h2   [BSZ * 2 * DINNER * QLEN];
__device__ bf16 g_rA2  [NHEAD * 256 * 128];
__device__ bf16 g_qr2  [NHEAD * 128 * (BSZ * QLEN)];

// ---------------- helpers ----------------------------------------------------
__device__ __forceinline__ void split_bf16(float x, bf16& hi, bf16& lo)
{
    hi = __float2bfloat16(x);
    lo = __float2bfloat16(x - __bfloat162float(hi));
}

__device__ __forceinline__ void cp_async16(uint32_t smem_dst, const void* gmem_src)
{
    asm volatile("cp.async.cg.shared.global [%0], [%1], 16;\n"
                 :: "r"(smem_dst), "l"(gmem_src));
}
__device__ __forceinline__ void cp_commit()
{
    asm volatile("cp.async.commit_group;\n");
}
__device__ __forceinline__ void cp_wait_all()
{
    asm volatile("cp.async.wait_group 0;\n");
}
__device__ __forceinline__ void ldsm_x4(uint32_t& r0, uint32_t& r1, uint32_t& r2, uint32_t& r3, uint32_t addr)
{
    asm volatile("ldmatrix.sync.aligned.m8n8.x4.shared.b16 {%0,%1,%2,%3}, [%4];\n"
                 : "=r"(r0), "=r"(r1), "=r"(r2), "=r"(r3) : "r"(addr));
}
__device__ __forceinline__ void ldsm_x4_t(uint32_t& r0, uint32_t& r1, uint32_t& r2, uint32_t& r3, uint32_t addr)
{
    asm volatile("ldmatrix.sync.aligned.m8n8.x4.trans.shared.b16 {%0,%1,%2,%3}, [%4];\n"
                 : "=r"(r0), "=r"(r1), "=r"(r2), "=r"(r3) : "r"(addr));
}
__device__ __forceinline__ void mma16816(float* c, const uint32_t* a, const uint32_t* b)
{
    asm volatile(
        "mma.sync.aligned.m16n8k16.row.col.f32.bf16.bf16.f32 "
        "{%0,%1,%2,%3}, {%4,%5,%6,%7}, {%8,%9}, {%0,%1,%2,%3};\n"
        : "+f"(c[0]), "+f"(c[1]), "+f"(c[2]), "+f"(c[3])
        : "r"(a[0]), "r"(a[1]), "r"(a[2]), "r"(a[3]), "r"(b[0]), "r"(b[1]));
}

// ---------------- expansion kernels (two-plane) -------------------------------
__global__ void expand_weights_kernel(const float* __restrict__ qkv_w,
                                      const float* __restrict__ r_w,
                                      const float* __restrict__ o_w,
                                      const float* __restrict__ ff1_w,
                                      const float* __restrict__ ff2_w,
                                      bf16* qkvw2, bf16* rw2, bf16* ow2,
                                      bf16* ff1w2, bf16* ff2w2)
{
    int cid = blockIdx.x;
    const float* in; bf16* out; int K; int row; int kc;
    if (cid < 3072)       { in = qkv_w; out = qkvw2; K = 1024; row = cid;        kc = 0; }
    else if (cid < 4096)  { in = r_w;   out = rw2;   K = 1024; row = cid - 3072; kc = 0; }
    else if (cid < 5120)  { in = o_w;   out = ow2;   K = 1024; row = cid - 4096; kc = 0; }
    else if (cid < 9216)  { in = ff1_w; out = ff1w2; K = 1024; row = cid - 5120; kc = 0; }
    else { int c = cid - 9216; in = ff2_w; out = ff2w2; K = 4096; row = c >> 2; kc = c & 3; }

    int k0 = (kc * 128 + threadIdx.x) * 8;
    const float4* ip = (const float4*)(in + (long)row * K + k0);
    float4 f0 = ip[0], f1 = ip[1];
    float v[8] = {f0.x, f0.y, f0.z, f0.w, f1.x, f1.y, f1.z, f1.w};
    unsigned short sh[8], sl[8];
#pragma unroll
    for (int j = 0; j < 8; j++) {
        bf16 hi, lo; split_bf16(v[j], hi, lo);
        sh[j] = __bfloat16_as_ushort(hi);
        sl[j] = __bfloat16_as_ushort(lo);
    }
    uint32_t wh[4], wl[4];
#pragma unroll
    for (int i = 0; i < 4; i++) {
        wh[i] = (uint32_t)sh[2 * i] | ((uint32_t)sh[2 * i + 1] << 16);
        wl[i] = (uint32_t)sl[2 * i] | ((uint32_t)sl[2 * i + 1] << 16);
    }
    bf16* orow = out + (long)row * 2 * K;
    *(uint4*)(orow + k0)     = make_uint4(wh[0], wh[1], wh[2], wh[3]);
    *(uint4*)(orow + K + k0) = make_uint4(wl[0], wl[1], wl[2], wl[3]);
}

// merged cat (z<BSZ) + pos (z==BSZ) expansion
__global__ void expand_catpos_kernel(const float* __restrict__ z0,
                                     const float* __restrict__ z1ss,
                                     const float* __restrict__ pos_emb,
                                     bf16* __restrict__ cat2,
                                     bf16* __restrict__ pos2)
{
    int d = blockIdx.y;
    int z = blockIdx.z;
    if (z < BSZ) {
        int t = 256 + blockIdx.x * 256 + threadIdx.x;
        float x = (t < MLEN) ? z0[((long)z * D_MODEL + d) * MLEN + t]
                             : z1ss[((long)z * D_MODEL + d) * QLEN + (t - MLEN)];
        bf16 hi, lo; split_bf16(x, hi, lo);
        bf16* o = cat2 + (long)z * 2 * D_MODEL * KLEN + (long)d * KLEN + t;
        o[0] = hi;
        o[(long)D_MODEL * KLEN] = lo;
    } else {
        if (blockIdx.x > 0) return;
        int t = 768 + threadIdx.x;
        float x = pos_emb[(long)d * KLEN + t];
        bf16 hi, lo; split_bf16(x, hi, lo);
        bf16* o = pos2 + (long)d * KLEN + t;
        o[0] = hi;
        o[(long)D_MODEL * KLEN] = lo;
    }
}

// fused: reduce 8 rkp partial planes AND write split rA2[h][t][hi|lo] directly
__global__ void reduce_rk_rA_kernel(const float* __restrict__ rkp,
                                    bf16* __restrict__ rA2)
{
    const long DK = (long)D_MODEL * KLEN;
    int idx = blockIdx.x * 256 + threadIdx.x;
    int row = idx >> 6;
    int t4  = (idx & 63) * 4;
    long base = (long)row * KLEN + 768 + t4;
    float4 a = *(const float4*)(rkp + base);
#pragma unroll
    for (int p = 1; p < 8; p++) {
        float4 q = *(const float4*)(rkp + p * DK + base);
        a.x += q.x; a.y += q.y; a.z += q.z; a.w += q.w;
    }
    int h = row >> 6, dl = row & 63;
    float v[4] = {a.x, a.y, a.z, a.w};
#pragma unroll
    for (int i = 0; i < 4; i++) {
        bf16 hi, lo; split_bf16(v[i], hi, lo);
        bf16* op = rA2 + ((long)h * 256 + t4 + i) * 128 + dl;
        op[0]  = hi;
        op[64] = lo;
    }
}

// qr2[h][d][b*512+i]=hi, [64+d]=lo of (Q + rrb)
__global__ void expand_qr_kernel(const float* __restrict__ wheads,
                                 const float* __restrict__ rrb,
                                 bf16* __restrict__ qr2)
{
    int i = blockIdx.x * 256 + threadIdx.x;
    int d = blockIdx.y;
    int b = blockIdx.z & 3, h = blockIdx.z >> 2;
    float v = wheads[(long)b * 3 * D_MODEL * KLEN + (long)(h * DHEAD + d) * KLEN
                     + MLEN + i] + rrb[h * DHEAD + d];
    bf16 hi, lo; split_bf16(v, hi, lo);
    const int NB = BSZ * QLEN;
    bf16* o = qr2 + (long)h * 128 * NB + (long)d * NB + b * QLEN + i;
    o[0] = hi;
    o[64 * NB] = lo;
}

// ---------------- tensor-core GEMM, two-plane 3-term, 3-stage pipeline -------
// mode: 0 fp32, 1 fp32 relu, 2 two-plane bf16 relu, 3 fp32 diagonal scatter
// (row + (col&31)) for the BD table.
#define APADE 72
#define NSTG  3

template<int MI, int NJ>
__global__ __launch_bounds__(256, 2)
void gemm_bf16_kernel(const bf16* __restrict__ A,
                      const bf16* __restrict__ B,
                      void*       __restrict__ Cv,
                      const float* __restrict__ bias,
                      const float* __restrict__ addend,
                      int Kps, int Kp, int ldn,
                      long strideA, long strideB, long strideC,
                      long strideAdd, long strideCk, long planeC,
                      int zshift, int mode, int tilemap)
{
    constexpr int GBMt = 32 * MI;
    constexpr int GBN  = 32 * NJ;
    constexpr int BP   = GBN + 8;
    constexpr int BCH  = GBN / 8;
    constexpr int BSH  = (NJ == 4 ? 4 : 5);

    extern __shared__ bf16 smem_g[];
    bf16* Asm = smem_g;
    bf16* Bsm = smem_g + NSTG * GBMt * APADE;

    const int tid  = threadIdx.x;
    const int lane = tid & 31;
    const int warp = tid >> 5;
    const int wm = warp >> 2;
    const int wn = warp & 3;

    int bxi = blockIdx.x, byi = blockIdx.y;
    if (tilemap) {
        int f = blockIdx.x;
        if (f < 96) { byi = 8 + f / 6; bxi = f % 6; }
        else        { int gq = f - 96; byi = gq >> 2; bxi = 2 + (gq & 3); }
    }
    const int bn = bxi * GBN;
    const int bm = byi * GBMt;
    const int b  = blockIdx.z >> zshift;
    const int ks = blockIdx.z & ((1 << zshift) - 1);
    const int ldk = 2 * Kp;

    const bf16* Ag = A + (long)b * strideA + (long)bm * ldk + (long)ks * Kps;
    const bf16* Bg = B + (long)b * strideB + (long)ks * Kps * ldn;

    uint32_t sA = (uint32_t)__cvta_generic_to_shared(Asm);
    uint32_t sB = (uint32_t)__cvta_generic_to_shared(Bsm);
    const uint32_t sAsz = GBMt * APADE * 2;
    const uint32_t sBsz = 64 * BP * 2;

    float acc[MI][NJ][4];
#pragma unroll
    for (int i = 0; i < MI; i++)
#pragma unroll
        for (int j = 0; j < NJ; j++)
#pragma unroll
            for (int r = 0; r < 4; r++) acc[i][j][r] = 0.f;

    auto load_tiles = [&](int buf, long aoff, long boff) {
#pragma unroll
        for (int i = 0; i < MI; i++) {
            int c   = tid + 256 * i;
            int row = c >> 3, ch = c & 7;
            cp_async16(sA + buf * sAsz + (row * APADE + ch * 8) * 2,
                       Ag + (long)row * ldk + aoff + ch * 8);
        }
#pragma unroll
        for (int i = 0; i < (64 * BCH) / 256; i++) {
            int c   = tid + 256 * i;
            int row = c >> BSH, ch = c & (BCH - 1);
            cp_async16(sB + buf * sBsz + (row * BP + ch * 8) * 2,
                       Bg + (boff + row) * ldn + bn + ch * 8);
        }
        cp_commit();
    };

    int part = 0, kk = 0;
    auto cur_aoff = [&]() -> long { return (part < 2 ? 0L : (long)Kp) + kk; };
    auto cur_boff = [&]() -> long { return (part == 1 ? (long)Kp : 0L) + kk; };
    auto advance  = [&]() { kk += 64; if (kk == Kps) { kk = 0; part++; } };

    load_tiles(0, cur_aoff(), cur_boff());
    advance();
    load_tiles(1, cur_aoff(), cur_boff());
    advance();

    const int nIter = (3 * Kps) >> 6;
    int buf = 0;
    for (int it = 0; it < nIter; it++) {
        if (it + 1 < nIter) asm volatile("cp.async.wait_group 1;\n");
        else                asm volatile("cp.async.wait_group 0;\n");
        __syncthreads();
        if (it + 2 < nIter) {
            int lb = buf + 2; if (lb >= NSTG) lb -= NSTG;
            load_tiles(lb, cur_aoff(), cur_boff());
            advance();
        }

#pragma unroll
        for (int ks4 = 0; ks4 < 4; ks4++) {
            uint32_t afrag[MI][4];
            uint32_t bfrag[NJ][2];
            int lrow = lane & 15, lcol = (lane >> 4) * 8;
#pragma unroll
            for (int mi = 0; mi < MI; mi++) {
                uint32_t addr = sA + buf * sAsz +
                    ((MI * 16 * wm + 16 * mi + lrow) * APADE + ks4 * 16 + lcol) * 2;
                ldsm_x4(afrag[mi][0], afrag[mi][1], afrag[mi][2], afrag[mi][3], addr);
            }
#pragma unroll
            for (int nj2 = 0; nj2 < NJ / 2; nj2++) {
                uint32_t addr = sB + buf * sBsz +
                    ((ks4 * 16 + lrow) * BP + (8 * NJ) * wn + 16 * nj2 + lcol) * 2;
                uint32_t r0, r1, r2, r3;
                ldsm_x4_t(r0, r1, r2, r3, addr);
                bfrag[2 * nj2][0] = r0;     bfrag[2 * nj2][1] = r1;
                bfrag[2 * nj2 + 1][0] = r2; bfrag[2 * nj2 + 1][1] = r3;
            }
#pragma unroll
            for (int mi = 0; mi < MI; mi++)
#pragma unroll
                for (int nj = 0; nj < NJ; nj++)
                    mma16816(acc[mi][nj], afrag[mi], bfrag[nj]);
        }
        buf++; if (buf == NSTG) buf = 0;
    }

    const float* Ad = (addend && ks == 0) ? (addend + (long)b * strideAdd) : nullptr;
    const float* bz = (ks == 0) ? bias : nullptr;
    int g = lane >> 2, tg = lane & 3;

    if (mode == 3) {
        // diagonal scatter: element (row, col) -> row' = row + (col & 31)
        float* Cb = (float*)Cv + (long)b * strideC;
#pragma unroll
        for (int mi = 0; mi < MI; mi++) {
            int row0 = bm + MI * 16 * wm + 16 * mi + g;
            int row1 = row0 + 8;
#pragma unroll
            for (int nj = 0; nj < NJ; nj++) {
                int col = bn + (8 * NJ) * wn + 8 * nj + 2 * tg;
                int c0 = col & 31, c1 = (col + 1) & 31;
                Cb[(long)(row0 + c0) * ldn + col]     = acc[mi][nj][0];
                Cb[(long)(row0 + c1) * ldn + col + 1] = acc[mi][nj][1];
                Cb[(long)(row1 + c0) * ldn + col]     = acc[mi][nj][2];
                Cb[(long)(row1 + c1) * ldn + col + 1] = acc[mi][nj][3];
            }
        }
        return;
    }

    if (mode == 2) {
        bf16* C2 = (bf16*)Cv + (long)b * strideC;
#pragma unroll
        for (int mi = 0; mi < MI; mi++) {
            int row0 = bm + MI * 16 * wm + 16 * mi + g;
            int row1 = row0 + 8;
            float bv0 = bz ? bz[row0] : 0.f;
            float bv1 = bz ? bz[row1] : 0.f;
#pragma unroll
            for (int nj = 0; nj < NJ; nj++) {
                int col = bn + (8 * NJ) * wn + 8 * nj + 2 * tg;
#pragma unroll
                for (int half = 0; half < 2; half++) {
                    int row = half ? row1 : row0;
                    float bv = half ? bv1 : bv0;
                    float v0 = fmaxf(acc[mi][nj][2 * half]     + bv, 0.f);
                    float v1 = fmaxf(acc[mi][nj][2 * half + 1] + bv, 0.f);
                    bf16 h0, l0, h1, l1;
                    split_bf16(v0, h0, l0);
                    split_bf16(v1, h1, l1);
                    long base = (long)row * ldn + col;
                    C2[base]              = h0; C2[base + 1]              = h1;
                    C2[planeC + base]     = l0; C2[planeC + base + 1]     = l1;
                }
            }
        }
        return;
    }

    float* Cb = (float*)Cv + (long)b * strideC + (long)ks * strideCk;
#pragma unroll
    for (int mi = 0; mi < MI; mi++) {
        int row0 = bm + MI * 16 * wm + 16 * mi + g;
        int row1 = row0 + 8;
        float bv0 = bz ? bz[row0] : 0.f;
        float bv1 = bz ? bz[row1] : 0.f;
#pragma unroll
        for (int nj = 0; nj < NJ; nj++) {
            int col = bn + (8 * NJ) * wn + 8 * nj + 2 * tg;
            float v00 = acc[mi][nj][0] + bv0;
            float v01 = acc[mi][nj][1] + bv0;
            float v10 = acc[mi][nj][2] + bv1;
            float v11 = acc[mi][nj][3] + bv1;
            if (Ad) {
                v00 += Ad[(long)row0 * ldn + col];
                v01 += Ad[(long)row0 * ldn + col + 1];
                v10 += Ad[(long)row1 * ldn + col];
                v11 += Ad[(long)row1 * ldn + col + 1];
            }
            if (mode == 1) {
                v00 = fmaxf(v00, 0.f); v01 = fmaxf(v01, 0.f);
                v10 = fmaxf(v10, 0.f); v11 = fmaxf(v11, 0.f);
            }
            Cb[(long)row0 * ldn + col]     = v00;
            Cb[(long)row0 * ldn + col + 1] = v01;
            Cb[(long)row1 * ldn + col]     = v10;
            Cb[(long)row1 * ldn + col + 1] = v11;
        }
    }
}

// ---------------- tiled banded attention: 32-query blocks, 4 CTAs/SM ---------
// BD read directly from diagonal gmem layout (coalesced; no smem staging).
#define AT_SMEM ((32*68 + 64*68*2 + 32*68 + 256 + 32) * 4)   // 53376 B

__global__ __launch_bounds__(256)
void attn_tiled_kernel(const float* __restrict__ wheads,
                       const float* __restrict__ BDg,
                       const float* __restrict__ rwb,
                       bf16*        __restrict__ avec2)
{
    extern __shared__ float sm[];
    float* qw   = sm;                        // [q][d]   stride 68
    float* Ks   = qw + 32 * 68;              // [jj][d]  stride 68
    float* Vs   = Ks + 64 * 68;              // [d][jj]  stride 68
    float* Ps   = Vs + 64 * 68;              // [q][jj]  stride 68
    float* red  = Ps + 32 * 68;              // [8][32]
    float* sinv = red + 256;                 // [32]

    const int i0 = blockIdx.x * 32;
    const int h  = blockIdx.y;
    const int b  = blockIdx.z;
    const int tid = threadIdx.x;
    const int NB = BSZ * QLEN;

    const float* W  = wheads + (long)b * (3 * D_MODEL) * KLEN;
    const float* Qg = W + (long)(h * DHEAD) * KLEN;
    const float* Kg = W + (long)(D_MODEL + h * DHEAD) * KLEN;
    const float* Vg = W + (long)(2 * D_MODEL + h * DHEAD) * KLEN;
    const float* BDh = BDg + (long)h * 288 * NB + b * QLEN + i0;

    for (int idx = tid; idx < 32 * 64; idx += 256) {
        int d = idx >> 5, q = idx & 31;
        qw[q * 68 + d] = Qg[(long)d * KLEN + MLEN + i0 + q] + rwb[h * DHEAD + d];
    }
    __syncthreads();

    const int qi = tid & 31;
    const int jg = tid >> 5;
    uint32_t VsAddr = (uint32_t)__cvta_generic_to_shared(Vs);
    float O[8];
#pragma unroll
    for (int u = 0; u < 8; u++) O[u] = 0.f;
    float sume = 0.f;

    for (int c = 0; c < 5; c++) {
        int jbase = i0 + 256 + 64 * c;
        if (c > 0) __syncthreads();
        for (int idx = tid; idx < 64 * 16; idx += 256) {
            int d = idx >> 4, jj0 = (idx & 15) * 4;
            int jg0 = jbase + jj0;
            uint32_t dst = VsAddr + (d * 68 + jj0) * 4;
            if (jg0 + 3 < KLEN) {
                cp_async16(dst, Vg + (long)d * KLEN + jg0);
            } else {
                float4 z = make_float4(0.f, 0.f, 0.f, 0.f);
                if (jg0 + 0 < KLEN) z.x = Vg[(long)d * KLEN + jg0];
                if (jg0 + 1 < KLEN) z.y = Vg[(long)d * KLEN + jg0 + 1];
                if (jg0 + 2 < KLEN) z.z = Vg[(long)d * KLEN + jg0 + 2];
                if (jg0 + 3 < KLEN) z.w = Vg[(long)d * KLEN + jg0 + 3];
                *(float4*)(Vs + d * 68 + jj0) = z;
            }
        }
        cp_commit();
        for (int idx = tid; idx < 64 * 64; idx += 256) {
            int d = idx >> 6, jj = idx & 63;
            int jglob = jbase + jj;
            Ks[jj * 68 + d] = (jglob < KLEN) ? Kg[(long)d * KLEN + jglob] : 0.f;
        }
        // prefetch BD diagonal rows for this chunk (coalesced over qi)
        float bdv[8];
#pragma unroll
        for (int u = 0; u < 8; u++) {
            int s = 64 * c + jg * 8 + u - 1;
            if (s < 0) s = 0;
            bdv[u] = BDh[(long)s * NB + qi];
        }
        cp_wait_all();
        __syncthreads();

        {
            float acc[8];
#pragma unroll
            for (int u = 0; u < 8; u++) acc[u] = 0.f;
            for (int d4 = 0; d4 < 16; d4++) {
                float4 qv4 = *(const float4*)(qw + qi * 68 + d4 * 4);
#pragma unroll
                for (int u = 0; u < 8; u++) {
                    float4 k4 = *(const float4*)(Ks + (jg * 8 + u) * 68 + d4 * 4);
                    acc[u] = fmaf(qv4.x, k4.x, acc[u]);
                    acc[u] = fmaf(qv4.y, k4.y, acc[u]);
                    acc[u] = fmaf(qv4.z, k4.z, acc[u]);
                    acc[u] = fmaf(qv4.w, k4.w, acc[u]);
                }
            }
            float pvv[8];
#pragma unroll
            for (int u = 0; u < 8; u++) {
                int jj = jg * 8 + u;
                int t  = 64 * c + jj - qi - 1;
                float pv = 0.f;
                if (t >= 0 && t < 256)
                    pv = __expf((acc[u] + bdv[u]) * 0.125f);
                sume += pv;
                pvv[u] = pv;
            }
            *(float4*)(Ps + qi * 68 + jg * 8)     = make_float4(pvv[0], pvv[1], pvv[2], pvv[3]);
            *(float4*)(Ps + qi * 68 + jg * 8 + 4) = make_float4(pvv[4], pvv[5], pvv[6], pvv[7]);
        }
        __syncthreads();

        for (int js = 0; js < 16; js++) {
            int jj0 = js * 4;
            float4 p4 = *(const float4*)(Ps + qi * 68 + jj0);
#pragma unroll
            for (int u = 0; u < 8; u++) {
                float4 v4 = *(const float4*)(Vs + (jg * 8 + u) * 68 + jj0);
                O[u] = fmaf(p4.x, v4.x, O[u]);
                O[u] = fmaf(p4.y, v4.y, O[u]);
                O[u] = fmaf(p4.z, v4.z, O[u]);
                O[u] = fmaf(p4.w, v4.w, O[u]);
            }
        }
    }

    red[jg * 32 + qi] = sume;
    __syncthreads();
    if (tid < 32) {
        float s = 0.f;
#pragma unroll
        for (int g8 = 0; g8 < 8; g8++) s += red[g8 * 32 + tid];
        sinv[tid] = 1.f / s;
    }
    __syncthreads();
    float inv = sinv[qi];
    bf16* outp = avec2 + (long)b * 2 * D_MODEL * QLEN;
#pragma unroll
    for (int u = 0; u < 8; u++) {
        int dp = h * DHEAD + jg * 8 + u;
        float v = O[u] * inv;
        bf16 hi, lo; split_bf16(v, hi, lo);
        long base = (long)dp * QLEN + i0 + qi;
        outp[base]                          = hi;
        outp[(long)D_MODEL * QLEN + base]   = lo;
    }
}

// ---------------- channel LayerNorm (optional 2nd input, 2-plane split) ------
__global__ __launch_bounds__(256)
void ln_kernel(const float* __restrict__ ya, const float* __restrict__ yb,
               float* __restrict__ out, bf16* __restrict__ out2)
{
    int b  = blockIdx.y;
    int t0 = blockIdx.x * 32;
    int tid = threadIdx.x;
    int tt = tid & 31, cg = tid >> 5;
    const float* Ya = ya + (long)b * D_MODEL * QLEN;
    const float* Yb = yb ? (yb + (long)b * D_MODEL * QLEN) : nullptr;

    float s = 0.f, s2 = 0.f;
    for (int c = cg * 128; c < cg * 128 + 128; c++) {
        long idx = (long)c * QLEN + t0 + tt;
        float v = Ya[idx] + (Yb ? Yb[idx] : 0.f);
        s += v; s2 += v * v;
    }
    __shared__ float ssum[8][32], ssq[8][32];
    __shared__ float smean[32], srstd[32];
    ssum[cg][tt] = s; ssq[cg][tt] = s2;
    __syncthreads();
    if (tid < 32) {
        float ts = 0.f, ts2 = 0.f;
#pragma unroll
        for (int g = 0; g < 8; g++) { ts += ssum[g][tid]; ts2 += ssq[g][tid]; }
        float mean = ts * (1.0f / D_MODEL);
        float var  = ts2 * (1.0f / D_MODEL) - mean * mean;
        smean[tid] = mean;
        srstd[tid] = rsqrtf(var + 1e-5f);
    }
    __syncthreads();
    float mean = smean[tt], rstd = srstd[tt];
    float* O = out + (long)b * D_MODEL * QLEN;
    bf16* O2 = out2 ? (out2 + (long)b * 2 * D_MODEL * QLEN) : nullptr;
    for (int c = cg * 128; c < cg * 128 + 128; c++) {
        long idx = (long)c * QLEN + t0 + tt;
        float v = Ya[idx] + (Yb ? Yb[idx] : 0.f);
        float r = (v - mean) * rstd;
        O[idx] = r;
        if (O2) {
            bf16 hi, lo; split_bf16(r, hi, lo);
            O2[idx]                          = hi;
            O2[(long)D_MODEL * QLEN + idx]   = lo;
        }
    }
}

// ---------------- launcher ---------------------------------------------------
#define GSMEM44 ((NSTG * 128 * APADE + NSTG * 64 * 136) * 2)   // 107520

extern "C" void kernel_launch(void* const* d_in, const int* in_sizes, int n_in,
                              void* d_out, int out_size)
{
    const float* z1ss    = (const float*)d_in[0];
    const float* uss     = (const float*)d_in[1];
    const float* z0      = (const float*)d_in[2];
    const float* pos_emb = (const float*)d_in[3];
    const float* qkv_w   = (const float*)d_in[4];
    const float* r_w     = (const float*)d_in[5];
    const float* r_w_bias= (const float*)d_in[6];
    const float* r_r_bias= (const float*)d_in[7];
    const float* o_w     = (const float*)d_in[8];
    const float* o_b     = (const float*)d_in[9];
    const float* ff1_w   = (const float*)d_in[10];
    const float* ff1_b   = (const float*)d_in[11];
    const float* ff2_w   = (const float*)d_in[12];
    const float* ff2_b   = (const float*)d_in[13];
    float* out = (float*)d_out;

    float *wheads, *rkp, *x, *tmp2, *BDg;
    bf16 *qkvw2, *rw2, *ow2, *ff1w2, *ff2w2, *pos2, *cat2, *avec2, *x2, *h2, *rA2, *qr2;
    cudaGetSymbolAddress((void**)&wheads, g_wheads);
    cudaGetSymbolAddress((void**)&rkp,    g_rkp);
    cudaGetSymbolAddress((void**)&x,      g_x);
    cudaGetSymbolAddress((void**)&tmp2,   g_tmp2);
    cudaGetSymbolAddress((void**)&BDg,    g_BD);
    cudaGetSymbolAddress((void**)&qkvw2,  g_qkvw2);
    cudaGetSymbolAddress((void**)&rw2,    g_rw2);
    cudaGetSymbolAddress((void**)&ow2,    g_ow2);
    cudaGetSymbolAddress((void**)&ff1w2,  g_ff1w2);
    cudaGetSymbolAddress((void**)&ff2w2,  g_ff2w2);
    cudaGetSymbolAddress((void**)&pos2,   g_pos2);
    cudaGetSymbolAddress((void**)&cat2,   g_cat2);
    cudaGetSymbolAddress((void**)&avec2,  g_avec2);
    cudaGetSymbolAddress((void**)&x2,     g_x2);
    cudaGetSymbolAddress((void**)&h2,     g_h2);
    cudaGetSymbolAddress((void**)&rA2,    g_rA2);
    cudaGetSymbolAddress((void**)&qr2,    g_qr2);

    cudaFuncSetAttribute(attn_tiled_kernel,
                         cudaFuncAttributeMaxDynamicSharedMemorySize, AT_SMEM);
    cudaFuncSetAttribute(gemm_bf16_kernel<4, 4>,
                         cudaFuncAttributeMaxDynamicSharedMemorySize, GSMEM44);

    const long s3dk = (long)3 * D_MODEL * KLEN;
    const long s2dk = (long)2 * D_MODEL * KLEN;
    const long s2dq = (long)2 * D_MODEL * QLEN;
    const long s2iq = (long)2 * DINNER * QLEN;
    const long sdq  = (long)D_MODEL * QLEN;
    const long sDK  = (long)D_MODEL * KLEN;
    const int  NB   = BSZ * QLEN;

    // [1] weight expansions (two-plane)
    expand_weights_kernel<<<13312, 128>>>(qkv_w, r_w, o_w, ff1_w, ff2_w,
                                          qkvw2, rw2, ow2, ff1w2, ff2w2);
    // [2] merged cat (cols [256,1024)) + pos (cols [768,1024)) expansion
    expand_catpos_kernel<<<dim3(3, D_MODEL, BSZ + 1), 256>>>(
        z0, z1ss, pos_emb, cat2, pos2);

    // [3] QKV: tile list, 512 CTAs; Kps=Kp=1024
    gemm_bf16_kernel<4, 4><<<dim3(128, 1, BSZ), 256, GSMEM44>>>(
        qkvw2, cat2 + 256, wheads + 256, nullptr, uss + 256,
        1024, 1024, KLEN, 0, s2dk, s3dk, s3dk, 0, 0, 0, 0, 1);

    // [4] r_head_k: K-split x8 -> 128 CTAs; Kps=128, Kp=1024
    gemm_bf16_kernel<4, 4><<<dim3(2, 8, 8), 256, GSMEM44>>>(
        rw2, pos2 + 768, rkp + 768, nullptr, nullptr,
        128, 1024, KLEN, 0, 0, 0, 0, sDK, 0, 3, 0, 0);

    // [5] fused reduce rk partials + rA2 split expansion
    reduce_rk_rA_kernel<<<256, 256>>>(rkp, rA2);

    // [6] qr2 expansion
    expand_qr_kernel<<<dim3(QLEN / 256, DHEAD, BSZ * NHEAD), 256>>>(
        wheads, r_r_bias, qr2);

    // [7] BD GEMM: per head, 256 x 2048, Kps=Kp=64; diagonal scatter epilogue
    gemm_bf16_kernel<4, 4><<<dim3(16, 2, NHEAD), 256, GSMEM44>>>(
        rA2, qr2, BDg, nullptr, nullptr,
        64, 64, NB, (long)256 * 128, (long)128 * NB, (long)288 * NB,
        0, 0, 0, 0, 3, 0);

    // [8] banded attention (BD direct from gmem, 4 CTAs/SM) -> avec2
    attn_tiled_kernel<<<dim3(QLEN / 32, NHEAD, BSZ), 256, AT_SMEM>>>(
        wheads, BDg, r_w_bias, avec2);

    // [9] O-proj: K-split x2 -> 256 CTAs; Kps=512, Kp=1024
    gemm_bf16_kernel<4, 4><<<dim3(4, 8, 2 * BSZ), 256, GSMEM44>>>(
        ow2, avec2, tmp2, o_b, z1ss,
        512, 1024, QLEN, 0, s2dq, sdq, sdq, (long)BSZ * sdq, 0, 1, 0, 0);

    // [10] x = LN(sum of halves), fused x2
    ln_kernel<<<dim3(QLEN / 32, BSZ), 256>>>(tmp2, tmp2 + (long)BSZ * sdq, x, x2);

    // [11] FF1: 512 CTAs, two-plane relu epilogue; Kps=Kp=1024
    gemm_bf16_kernel<4, 4><<<dim3(4, 32, BSZ), 256, GSMEM44>>>(
        ff1w2, x2, h2, ff1_b, nullptr,
        1024, 1024, QLEN, 0, s2dq, s2iq, 0, 0, (long)DINNER * QLEN, 0, 2, 0);

    // [12] FF2: K-split x2 -> 256 CTAs; Kps=2048, Kp=4096
    gemm_bf16_kernel<4, 4><<<dim3(4, 8, 2 * BSZ), 256, GSMEM44>>>(
        ff2w2, h2, tmp2, ff2_b, x,
        2048, 4096, QLEN, 0, s2iq, sdq, sdq, (long)BSZ * sdq, 0, 1, 0, 0);

    // [13] out = LN(sum of halves)
    ln_kernel<<<dim3(QLEN / 32, BSZ), 256>>>(tmp2, tmp2 + (long)BSZ * sdq, out, nullptr);
}